// round 1
// baseline (speedup 1.0000x reference)
#include <cuda_runtime.h>

#define Bb 2
#define Ss 2048
#define Dd 1024
#define Hh 16
#define HD 64
#define Mtot (Bb*Ss)   // 4096

// Scratch (static device arrays; allocation APIs are forbidden)
__device__ float g_q[Bb*Hh*Ss*HD];    // (B,H,S,hd)
__device__ float g_k[Bb*Hh*Ss*HD];
__device__ float g_v[Bb*Hh*Ss*HD];
__device__ float g_ctx[Mtot*Dd];      // (B,S,D)

// ---------------------------------------------------------------------------
// C = A(M,K) @ W(N,K)^T + bias
// IN_SEL:  0 -> A param, 1 -> g_ctx
// OUT_SEL: 0 -> C param (plain [M,N]), 1/2/3 -> g_q/g_k/g_v with head permute
// ---------------------------------------------------------------------------
template<int IN_SEL, int OUT_SEL>
__global__ __launch_bounds__(256)
void sgemm_nt(const float* __restrict__ A, const float* __restrict__ W,
              const float* __restrict__ bias, float* __restrict__ C,
              int M, int N, int K)
{
    __shared__ float As[16][132];   // [k][m], stride 132: 16B-aligned rows, 2-way STS max
    __shared__ float Bs[16][132];   // [k][n]

    const float* Ap = (IN_SEL == 1) ? (const float*)g_ctx : A;

    const int m0 = blockIdx.y * 128;
    const int n0 = blockIdx.x * 128;
    const int tid = threadIdx.x;
    const int ty = tid >> 4, tx = tid & 15;

    float acc[8][8];
#pragma unroll
    for (int i = 0; i < 8; i++)
#pragma unroll
        for (int j = 0; j < 8; j++) acc[i][j] = 0.f;

    for (int kt = 0; kt < K; kt += 16) {
#pragma unroll
        for (int p = 0; p < 2; p++) {
            int idx = tid + p * 256;
            int r = idx >> 2, c4 = (idx & 3) << 2;
            float4 va = *(const float4*)(Ap + (size_t)(m0 + r) * K + kt + c4);
            As[c4 + 0][r] = va.x; As[c4 + 1][r] = va.y;
            As[c4 + 2][r] = va.z; As[c4 + 3][r] = va.w;
            float4 vb = *(const float4*)(W + (size_t)(n0 + r) * K + kt + c4);
            Bs[c4 + 0][r] = vb.x; Bs[c4 + 1][r] = vb.y;
            Bs[c4 + 2][r] = vb.z; Bs[c4 + 3][r] = vb.w;
        }
        __syncthreads();
#pragma unroll 4
        for (int kk = 0; kk < 16; kk++) {
            float a[8], b[8];
#pragma unroll
            for (int i = 0; i < 8; i++) a[i] = As[kk][ty * 8 + i];
#pragma unroll
            for (int j = 0; j < 8; j++) b[j] = Bs[kk][tx * 8 + j];
#pragma unroll
            for (int i = 0; i < 8; i++)
#pragma unroll
                for (int j = 0; j < 8; j++) acc[i][j] += a[i] * b[j];
        }
        __syncthreads();
    }

    float* qkv = (OUT_SEL == 1) ? g_q : (OUT_SEL == 2) ? g_k : g_v;
#pragma unroll
    for (int i = 0; i < 8; i++) {
        int m = m0 + ty * 8 + i;
#pragma unroll
        for (int j = 0; j < 8; j++) {
            int n = n0 + tx * 8 + j;
            float v = acc[i][j] + bias[n];
            if (OUT_SEL == 0) {
                C[(size_t)m * N + n] = v;
            } else {
                int bi = m >> 11, s = m & (Ss - 1);
                int h = n >> 6,  d = n & (HD - 1);
                qkv[(((size_t)(bi * Hh + h)) * Ss + s) * HD + d] = v;
            }
        }
    }
}

// ---------------------------------------------------------------------------
// Causal flash attention, fp32. Block = one (b,h, 64-row q tile). 256 threads,
// 4x4 microtiles, online softmax via 16-lane shfl reductions.
// P tile reuses the K smem buffer -> exactly 48KB static smem.
// ---------------------------------------------------------------------------
__global__ __launch_bounds__(256)
void attn_kernel()
{
    __shared__ float Qs[64][64];   // [d][r], Q * 1/sqrt(hd)
    __shared__ float KPs[64][64];  // phase 1: K^T [d][c]; phase 2: P [r][c]
    __shared__ float Vs[64][64];   // [c][d]

    const int qt = blockIdx.x;     // q tile 0..31
    const int bh = blockIdx.y;     // b*H + h, 0..31
    const int b = bh >> 4, h = bh & 15;
    const int tid = threadIdx.x;
    const int ty = tid >> 4, tx = tid & 15;

    const float* qbase = g_q + ((size_t)bh * Ss + qt * 64) * HD;
    const float* kbase = g_k + (size_t)bh * Ss * HD;
    const float* vbase = g_v + (size_t)bh * Ss * HD;
    const float scale = 0.125f;    // 1/sqrt(64)

    // Load Q transposed + pre-scaled (r-fastest mapping -> conflict-free STS)
#pragma unroll
    for (int p = 0; p < 4; p++) {
        int idx = tid + p * 256;
        int r = idx & 63, c4 = (idx >> 6) << 2;
        float4 v4 = *(const float4*)(qbase + (size_t)r * HD + c4);
        Qs[c4 + 0][r] = v4.x * scale; Qs[c4 + 1][r] = v4.y * scale;
        Qs[c4 + 2][r] = v4.z * scale; Qs[c4 + 3][r] = v4.w * scale;
    }

    float acc[4][4];
#pragma unroll
    for (int i = 0; i < 4; i++)
#pragma unroll
        for (int j = 0; j < 4; j++) acc[i][j] = 0.f;
    float mrow[4], lrow[4];
#pragma unroll
    for (int i = 0; i < 4; i++) { mrow[i] = -1e30f; lrow[i] = 0.f; }

    for (int kt = 0; kt <= qt; kt++) {
        __syncthreads();           // prior PV reads of KPs/Vs done
#pragma unroll
        for (int p = 0; p < 4; p++) {
            int idx = tid + p * 256;
            int r = idx & 63, c4 = (idx >> 6) << 2;      // K transposed
            float4 kv = *(const float4*)(kbase + (size_t)(kt * 64 + r) * HD + c4);
            KPs[c4 + 0][r] = kv.x; KPs[c4 + 1][r] = kv.y;
            KPs[c4 + 2][r] = kv.z; KPs[c4 + 3][r] = kv.w;
            int rv = idx >> 4, cv = (idx & 15) << 2;     // V natural (coalesced)
            *(float4*)&Vs[rv][cv] =
                *(const float4*)(vbase + (size_t)(kt * 64 + rv) * HD + cv);
        }
        __syncthreads();

        // S = Q K^T
        float s[4][4];
#pragma unroll
        for (int i = 0; i < 4; i++)
#pragma unroll
            for (int j = 0; j < 4; j++) s[i][j] = 0.f;
#pragma unroll 8
        for (int d = 0; d < 64; d++) {
            float a[4], bb[4];
#pragma unroll
            for (int i = 0; i < 4; i++) a[i] = Qs[d][ty * 4 + i];
#pragma unroll
            for (int j = 0; j < 4; j++) bb[j] = KPs[d][tx * 4 + j];
#pragma unroll
            for (int i = 0; i < 4; i++)
#pragma unroll
                for (int j = 0; j < 4; j++) s[i][j] += a[i] * bb[j];
        }

        if (kt == qt) {            // diagonal tile: causal mask
#pragma unroll
            for (int i = 0; i < 4; i++)
#pragma unroll
                for (int j = 0; j < 4; j++)
                    if (tx * 4 + j > ty * 4 + i) s[i][j] = -1e30f;
        }

        // Online softmax (row group = 16 lanes sharing ty = half-warp)
#pragma unroll
        for (int i = 0; i < 4; i++) {
            float mx = fmaxf(fmaxf(s[i][0], s[i][1]), fmaxf(s[i][2], s[i][3]));
#pragma unroll
            for (int off = 8; off >= 1; off >>= 1)
                mx = fmaxf(mx, __shfl_xor_sync(0xffffffffu, mx, off, 16));
            float mnew = fmaxf(mrow[i], mx);
            float al = __expf(mrow[i] - mnew);
            float sum = 0.f;
#pragma unroll
            for (int j = 0; j < 4; j++) { s[i][j] = __expf(s[i][j] - mnew); sum += s[i][j]; }
#pragma unroll
            for (int off = 8; off >= 1; off >>= 1)
                sum += __shfl_xor_sync(0xffffffffu, sum, off, 16);
            lrow[i] = lrow[i] * al + sum;
            mrow[i] = mnew;
#pragma unroll
            for (int j = 0; j < 4; j++) acc[i][j] *= al;
        }

        __syncthreads();           // all score reads of KPs done before overwrite
#pragma unroll
        for (int i = 0; i < 4; i++)
            *(float4*)&KPs[ty * 4 + i][tx * 4] =
                make_float4(s[i][0], s[i][1], s[i][2], s[i][3]);
        __syncthreads();

        // O += P V
#pragma unroll 8
        for (int c = 0; c < 64; c++) {
            float a[4], bb[4];
#pragma unroll
            for (int i = 0; i < 4; i++) a[i] = KPs[ty * 4 + i][c];
#pragma unroll
            for (int j = 0; j < 4; j++) bb[j] = Vs[c][tx * 4 + j];
#pragma unroll
            for (int i = 0; i < 4; i++)
#pragma unroll
                for (int j = 0; j < 4; j++) acc[i][j] += a[i] * bb[j];
        }
    }

    // ctx (B,S,D) epilogue
#pragma unroll
    for (int i = 0; i < 4; i++) {
        float inv = 1.f / lrow[i];
        int sg = qt * 64 + ty * 4 + i;
        float* dst = g_ctx + ((size_t)b * Ss + sg) * Dd + h * HD + tx * 4;
        *(float4*)dst = make_float4(acc[i][0] * inv, acc[i][1] * inv,
                                    acc[i][2] * inv, acc[i][3] * inv);
    }
}

// ---------------------------------------------------------------------------
extern "C" void kernel_launch(void* const* d_in, const int* in_sizes, int n_in,
                              void* d_out, int out_size)
{
    const float* x  = (const float*)d_in[0];
    const float* Wq = (const float*)d_in[1];
    const float* bq = (const float*)d_in[2];
    const float* Wk = (const float*)d_in[3];
    const float* bk = (const float*)d_in[4];
    const float* Wv = (const float*)d_in[5];
    const float* bv = (const float*)d_in[6];
    const float* Wo = (const float*)d_in[7];
    const float* bo = (const float*)d_in[8];
    float* out = (float*)d_out;

    dim3 gblk(Dd / 128, Mtot / 128);   // (8, 32)
    sgemm_nt<0, 1><<<gblk, 256>>>(x, Wq, bq, nullptr, Mtot, Dd, Dd);
    sgemm_nt<0, 2><<<gblk, 256>>>(x, Wk, bk, nullptr, Mtot, Dd, Dd);
    sgemm_nt<0, 3><<<gblk, 256>>>(x, Wv, bv, nullptr, Mtot, Dd, Dd);

    attn_kernel<<<dim3(Ss / 64, Bb * Hh), 256>>>();

    sgemm_nt<1, 0><<<gblk, 256>>>(nullptr, Wo, bo, out, Mtot, Dd, Dd);
}

// round 3
// speedup vs baseline: 1.6029x; 1.6029x over previous
#include <cuda_runtime.h>
#include <cuda_bf16.h>
#include <cstdint>

#define Bb 2
#define Ss 2048
#define Dd 1024
#define Hh 16
#define HD 64
#define Mtot (Bb*Ss)   // 4096

// ---------------- scratch (static device arrays; alloc APIs forbidden) -----
__device__ float g_q[Bb*Hh*Ss*HD];                      // (B,H,S,hd) fp32
__device__ float g_k[Bb*Hh*Ss*HD];
__device__ float g_v[Bb*Hh*Ss*HD];
__device__ __align__(16) __nv_bfloat16 g_xh[Mtot*Dd];   // x split hi/lo
__device__ __align__(16) __nv_bfloat16 g_xl[Mtot*Dd];
__device__ __align__(16) __nv_bfloat16 g_wh[4u*Dd*Dd];  // Wq,Wk,Wv,Wo hi
__device__ __align__(16) __nv_bfloat16 g_wl[4u*Dd*Dd];  // lo
__device__ __align__(16) __nv_bfloat16 g_ch[Mtot*Dd];   // ctx hi/lo (B,S,D)
__device__ __align__(16) __nv_bfloat16 g_cl[Mtot*Dd];

// ---------------- PTX helpers (all sm_80/75-era, no 'a'-feature ops) -------
__device__ __forceinline__ uint32_t smem_to_u32(const void* p) {
    uint32_t a;
    asm("{ .reg .u64 t; cvta.to.shared.u64 t, %1; cvt.u32.u64 %0, t; }"
        : "=r"(a) : "l"(p));
    return a;
}
__device__ __forceinline__ void cp_async16(uint32_t dst, const void* src) {
    asm volatile("cp.async.cg.shared.global [%0], [%1], 16;"
                 :: "r"(dst), "l"(src) : "memory");
}
__device__ __forceinline__ void cp_commit() {
    asm volatile("cp.async.commit_group;" ::: "memory");
}
template<int N> __device__ __forceinline__ void cp_wait() {
    asm volatile("cp.async.wait_group %0;" :: "n"(N) : "memory");
}
__device__ __forceinline__ void ldsm_x4(uint32_t* r, uint32_t addr) {
    asm volatile("ldmatrix.sync.aligned.m8n8.x4.shared.b16 {%0,%1,%2,%3}, [%4];"
                 : "=r"(r[0]), "=r"(r[1]), "=r"(r[2]), "=r"(r[3]) : "r"(addr));
}
__device__ __forceinline__ void mma16816(float* c, const uint32_t* a, const uint32_t* b) {
    asm volatile("mma.sync.aligned.m16n8k16.row.col.f32.bf16.bf16.f32 "
                 "{%0,%1,%2,%3}, {%4,%5,%6,%7}, {%8,%9}, {%0,%1,%2,%3};"
                 : "+f"(c[0]), "+f"(c[1]), "+f"(c[2]), "+f"(c[3])
                 : "r"(a[0]), "r"(a[1]), "r"(a[2]), "r"(a[3]), "r"(b[0]), "r"(b[1]));
}

// ---------------- fp32 -> bf16 hi/lo split ---------------------------------
__device__ __forceinline__ void split2(float v, __nv_bfloat16& h, __nv_bfloat16& l) {
    h = __float2bfloat16(v);
    l = __float2bfloat16(v - __bfloat162float(h));
}

__global__ __launch_bounds__(256) void split_x(const float* __restrict__ src) {
    int i = (blockIdx.x * 256 + threadIdx.x) * 4;
    float4 v = *(const float4*)(src + i);
    __nv_bfloat16 h0, h1, h2, h3, l0, l1, l2, l3;
    split2(v.x, h0, l0); split2(v.y, h1, l1); split2(v.z, h2, l2); split2(v.w, h3, l3);
    *(__nv_bfloat162*)(g_xh + i)     = __nv_bfloat162(h0, h1);
    *(__nv_bfloat162*)(g_xh + i + 2) = __nv_bfloat162(h2, h3);
    *(__nv_bfloat162*)(g_xl + i)     = __nv_bfloat162(l0, l1);
    *(__nv_bfloat162*)(g_xl + i + 2) = __nv_bfloat162(l2, l3);
}

__global__ __launch_bounds__(256) void split_w(const float* __restrict__ src, int widx) {
    int i = (blockIdx.x * 256 + threadIdx.x) * 4;
    size_t o = (size_t)widx * Dd * Dd + i;
    float4 v = *(const float4*)(src + i);
    __nv_bfloat16 h0, h1, h2, h3, l0, l1, l2, l3;
    split2(v.x, h0, l0); split2(v.y, h1, l1); split2(v.z, h2, l2); split2(v.w, h3, l3);
    *(__nv_bfloat162*)(g_wh + o)     = __nv_bfloat162(h0, h1);
    *(__nv_bfloat162*)(g_wh + o + 2) = __nv_bfloat162(h2, h3);
    *(__nv_bfloat162*)(g_wl + o)     = __nv_bfloat162(l0, l1);
    *(__nv_bfloat162*)(g_wl + o + 2) = __nv_bfloat162(l2, l3);
}

// ---------------------------------------------------------------------------
// mma.sync GEMM: C[M,N] = A[M,K] @ W[N,K]^T + bias via 3-term bf16 split.
// Block 128x128, 8 warps (2x4), warp tile 64x32, K-chunk 32, double-buffered
// cp.async. Smem tiles: 128 rows x 80B (64B data + 16B pad -> conflict-free
// ldmatrix: slot = 5r mod 8 is a permutation).
// ASEL: 0 -> g_xh/g_xl, 1 -> g_ch/g_cl
// OSEL: 0 -> Cout [M,N]; 1/2/3 -> g_q/g_k/g_v with (B,H,S,hd) permute
// ---------------------------------------------------------------------------
#define TILE_B   10240                 // 128 * 80
#define BUF_B    (4 * TILE_B)          // Ah, Al, Bh, Bl
#define GEMM_SMEM (2 * BUF_B + 512)    // 82432

template<int ASEL, int OSEL>
__global__ __launch_bounds__(256)
void gemm_mma(int widx, const float* __restrict__ bias, float* __restrict__ Cout)
{
    extern __shared__ char smem[];
    const uint32_t sb = smem_to_u32(smem);
    float* biasS = (float*)(smem + 2 * BUF_B);

    const int tid = threadIdx.x, wid = tid >> 5, lid = tid & 31;
    const int wm = wid >> 2, wn = wid & 3;
    const int m0 = blockIdx.y * 128, n0 = blockIdx.x * 128;

    const __nv_bfloat16* Ah = (ASEL == 0) ? g_xh : g_ch;
    const __nv_bfloat16* Al = (ASEL == 0) ? g_xl : g_cl;
    const __nv_bfloat16* Wh = g_wh + (size_t)widx * Dd * Dd;
    const __nv_bfloat16* Wl = g_wl + (size_t)widx * Dd * Dd;

    if (tid < 128) biasS[tid] = bias[n0 + tid];

    float acc[4][4][4];
#pragma unroll
    for (int i = 0; i < 4; i++)
#pragma unroll
        for (int j = 0; j < 4; j++)
#pragma unroll
            for (int k = 0; k < 4; k++) acc[i][j][k] = 0.f;

    // async-load one 32-wide K chunk (4 tiles) into buffer `buf`
    auto issue = [&](int kt, int buf) {
        const int kc = kt * 32;
#pragma unroll
        for (int i = 0; i < 8; i++) {
            int idx = tid + i * 256;
            int tile = idx >> 9, w = idx & 511;
            int r = w >> 2, seg = (w & 3) * 16;
            uint32_t dst = sb + buf * BUF_B + tile * TILE_B + r * 80 + seg;
            const char* src;
            if (tile == 0)      src = (const char*)(Ah + (size_t)(m0 + r) * Dd + kc) + seg;
            else if (tile == 1) src = (const char*)(Al + (size_t)(m0 + r) * Dd + kc) + seg;
            else if (tile == 2) src = (const char*)(Wh + (size_t)(n0 + r) * Dd + kc) + seg;
            else                src = (const char*)(Wl + (size_t)(n0 + r) * Dd + kc) + seg;
            cp_async16(dst, src);
        }
        cp_commit();
    };

    issue(0, 0);
    int buf = 0;
    const int arow0 = wm * 64 + (lid & 15);
    const int abyte0 = (lid >> 4) * 16;
    const int brow0 = wn * 32 + ((lid >> 4) << 3) + (lid & 7);
    const int bbyte0 = ((lid >> 3) & 1) * 16;

    for (int kt = 0; kt < 32; kt++) {
        if (kt + 1 < 32) { issue(kt + 1, buf ^ 1); cp_wait<1>(); }
        else             { cp_wait<0>(); }
        __syncthreads();

        const uint32_t tAh = sb + buf * BUF_B;
        const uint32_t tAl = tAh + TILE_B;
        const uint32_t tBh = tAh + 2 * TILE_B;
        const uint32_t tBl = tAh + 3 * TILE_B;

#pragma unroll
        for (int kk = 0; kk < 2; kk++) {
            uint32_t aH[4][4], aL[4][4], bH[4][2], bL[4][2];
            const int ab = kk * 32 + abyte0;
            const int bb = kk * 32 + bbyte0;
#pragma unroll
            for (int mf = 0; mf < 4; mf++) {
                uint32_t ro = (arow0 + mf * 16) * 80;
                ldsm_x4(aH[mf], tAh + ro + ab);
                ldsm_x4(aL[mf], tAl + ro + ab);
            }
#pragma unroll
            for (int nf2 = 0; nf2 < 2; nf2++) {
                uint32_t ro = (brow0 + nf2 * 16) * 80;
                uint32_t r4[4];
                ldsm_x4(r4, tBh + ro + bb);
                bH[nf2 * 2][0] = r4[0]; bH[nf2 * 2][1] = r4[1];
                bH[nf2 * 2 + 1][0] = r4[2]; bH[nf2 * 2 + 1][1] = r4[3];
                ldsm_x4(r4, tBl + ro + bb);
                bL[nf2 * 2][0] = r4[0]; bL[nf2 * 2][1] = r4[1];
                bL[nf2 * 2 + 1][0] = r4[2]; bL[nf2 * 2 + 1][1] = r4[3];
            }
#pragma unroll
            for (int mf = 0; mf < 4; mf++)
#pragma unroll
                for (int nf = 0; nf < 4; nf++) {
                    mma16816(acc[mf][nf], aH[mf], bH[nf]);
                    mma16816(acc[mf][nf], aH[mf], bL[nf]);
                    mma16816(acc[mf][nf], aL[mf], bH[nf]);
                }
        }
        __syncthreads();
        buf ^= 1;
    }

    // epilogue: mma C layout -> gmem
#pragma unroll
    for (int mf = 0; mf < 4; mf++) {
#pragma unroll
        for (int nf = 0; nf < 4; nf++) {
            int nl = wn * 32 + nf * 8 + (lid & 3) * 2;
            int n = n0 + nl;
            float b0 = biasS[nl], b1 = biasS[nl + 1];
#pragma unroll
            for (int half = 0; half < 2; half++) {
                int m = m0 + wm * 64 + mf * 16 + (lid >> 2) + half * 8;
                float2 v = make_float2(acc[mf][nf][half * 2 + 0] + b0,
                                       acc[mf][nf][half * 2 + 1] + b1);
                if (OSEL == 0) {
                    *(float2*)(Cout + (size_t)m * Dd + n) = v;
                } else {
                    float* qkv = (OSEL == 1) ? g_q : (OSEL == 2) ? g_k : g_v;
                    int b = m >> 11, s = m & (Ss - 1);
                    int h = n >> 6, d = n & (HD - 1);
                    *(float2*)(qkv + (((size_t)(b * Hh + h)) * Ss + s) * HD + d) = v;
                }
            }
        }
    }
}

// ---------------------------------------------------------------------------
// Causal flash attention, fp32 SIMT; epilogue emits ctx as bf16 hi/lo.
// ---------------------------------------------------------------------------
__global__ __launch_bounds__(256)
void attn_kernel()
{
    __shared__ float Qs[64][64];
    __shared__ float KPs[64][64];
    __shared__ float Vs[64][64];

    const int qt = blockIdx.x;
    const int bh = blockIdx.y;
    const int b = bh >> 4, h = bh & 15;
    const int tid = threadIdx.x;
    const int ty = tid >> 4, tx = tid & 15;

    const float* qbase = g_q + ((size_t)bh * Ss + qt * 64) * HD;
    const float* kbase = g_k + (size_t)bh * Ss * HD;
    const float* vbase = g_v + (size_t)bh * Ss * HD;
    const float scale = 0.125f;

#pragma unroll
    for (int p = 0; p < 4; p++) {
        int idx = tid + p * 256;
        int r = idx & 63, c4 = (idx >> 6) << 2;
        float4 v4 = *(const float4*)(qbase + (size_t)r * HD + c4);
        Qs[c4 + 0][r] = v4.x * scale; Qs[c4 + 1][r] = v4.y * scale;
        Qs[c4 + 2][r] = v4.z * scale; Qs[c4 + 3][r] = v4.w * scale;
    }

    float acc[4][4];
#pragma unroll
    for (int i = 0; i < 4; i++)
#pragma unroll
        for (int j = 0; j < 4; j++) acc[i][j] = 0.f;
    float mrow[4], lrow[4];
#pragma unroll
    for (int i = 0; i < 4; i++) { mrow[i] = -1e30f; lrow[i] = 0.f; }

    for (int kt = 0; kt <= qt; kt++) {
        __syncthreads();
#pragma unroll
        for (int p = 0; p < 4; p++) {
            int idx = tid + p * 256;
            int r = idx & 63, c4 = (idx >> 6) << 2;
            float4 kv = *(const float4*)(kbase + (size_t)(kt * 64 + r) * HD + c4);
            KPs[c4 + 0][r] = kv.x; KPs[c4 + 1][r] = kv.y;
            KPs[c4 + 2][r] = kv.z; KPs[c4 + 3][r] = kv.w;
            int rv = idx >> 4, cv = (idx & 15) << 2;
            *(float4*)&Vs[rv][cv] =
                *(const float4*)(vbase + (size_t)(kt * 64 + rv) * HD + cv);
        }
        __syncthreads();

        float s[4][4];
#pragma unroll
        for (int i = 0; i < 4; i++)
#pragma unroll
            for (int j = 0; j < 4; j++) s[i][j] = 0.f;
#pragma unroll 8
        for (int d = 0; d < 64; d++) {
            float a[4], bb[4];
#pragma unroll
            for (int i = 0; i < 4; i++) a[i] = Qs[d][ty * 4 + i];
#pragma unroll
            for (int j = 0; j < 4; j++) bb[j] = KPs[d][tx * 4 + j];
#pragma unroll
            for (int i = 0; i < 4; i++)
#pragma unroll
                for (int j = 0; j < 4; j++) s[i][j] += a[i] * bb[j];
        }

        if (kt == qt) {
#pragma unroll
            for (int i = 0; i < 4; i++)
#pragma unroll
                for (int j = 0; j < 4; j++)
                    if (tx * 4 + j > ty * 4 + i) s[i][j] = -1e30f;
        }

#pragma unroll
        for (int i = 0; i < 4; i++) {
            float mx = fmaxf(fmaxf(s[i][0], s[i][1]), fmaxf(s[i][2], s[i][3]));
#pragma unroll
            for (int off = 8; off >= 1; off >>= 1)
                mx = fmaxf(mx, __shfl_xor_sync(0xffffffffu, mx, off, 16));
            float mnew = fmaxf(mrow[i], mx);
            float al = __expf(mrow[i] - mnew);
            float sum = 0.f;
#pragma unroll
            for (int j = 0; j < 4; j++) { s[i][j] = __expf(s[i][j] - mnew); sum += s[i][j]; }
#pragma unroll
            for (int off = 8; off >= 1; off >>= 1)
                sum += __shfl_xor_sync(0xffffffffu, sum, off, 16);
            lrow[i] = lrow[i] * al + sum;
            mrow[i] = mnew;
#pragma unroll
            for (int j = 0; j < 4; j++) acc[i][j] *= al;
        }

        __syncthreads();
#pragma unroll
        for (int i = 0; i < 4; i++)
            *(float4*)&KPs[ty * 4 + i][tx * 4] =
                make_float4(s[i][0], s[i][1], s[i][2], s[i][3]);
        __syncthreads();

#pragma unroll 8
        for (int c = 0; c < 64; c++) {
            float a[4], bb[4];
#pragma unroll
            for (int i = 0; i < 4; i++) a[i] = KPs[ty * 4 + i][c];
#pragma unroll
            for (int j = 0; j < 4; j++) bb[j] = Vs[c][tx * 4 + j];
#pragma unroll
            for (int i = 0; i < 4; i++)
#pragma unroll
                for (int j = 0; j < 4; j++) acc[i][j] += a[i] * bb[j];
        }
    }

    // ctx epilogue -> bf16 hi/lo split, (B,S,D) layout
#pragma unroll
    for (int i = 0; i < 4; i++) {
        float inv = 1.f / lrow[i];
        int sg = qt * 64 + ty * 4 + i;
        size_t base = ((size_t)b * Ss + sg) * Dd + h * HD + tx * 4;
        float v0 = acc[i][0] * inv, v1 = acc[i][1] * inv;
        float v2 = acc[i][2] * inv, v3 = acc[i][3] * inv;
        __nv_bfloat16 h0, h1, h2, h3, l0, l1, l2, l3;
        split2(v0, h0, l0); split2(v1, h1, l1); split2(v2, h2, l2); split2(v3, h3, l3);
        *(__nv_bfloat162*)(g_ch + base)     = __nv_bfloat162(h0, h1);
        *(__nv_bfloat162*)(g_ch + base + 2) = __nv_bfloat162(h2, h3);
        *(__nv_bfloat162*)(g_cl + base)     = __nv_bfloat162(l0, l1);
        *(__nv_bfloat162*)(g_cl + base + 2) = __nv_bfloat162(l2, l3);
    }
}

// ---------------------------------------------------------------------------
extern "C" void kernel_launch(void* const* d_in, const int* in_sizes, int n_in,
                              void* d_out, int out_size)
{
    const float* x  = (const float*)d_in[0];
    const float* Wq = (const float*)d_in[1];
    const float* bq = (const float*)d_in[2];
    const float* Wk = (const float*)d_in[3];
    const float* bk = (const float*)d_in[4];
    const float* Wv = (const float*)d_in[5];
    const float* bv = (const float*)d_in[6];
    const float* Wo = (const float*)d_in[7];
    const float* bo = (const float*)d_in[8];
    float* out = (float*)d_out;

    // idempotent, deterministic (>48KB dynamic smem)
    cudaFuncSetAttribute(gemm_mma<0, 1>, cudaFuncAttributeMaxDynamicSharedMemorySize, GEMM_SMEM);
    cudaFuncSetAttribute(gemm_mma<0, 2>, cudaFuncAttributeMaxDynamicSharedMemorySize, GEMM_SMEM);
    cudaFuncSetAttribute(gemm_mma<0, 3>, cudaFuncAttributeMaxDynamicSharedMemorySize, GEMM_SMEM);
    cudaFuncSetAttribute(gemm_mma<1, 0>, cudaFuncAttributeMaxDynamicSharedMemorySize, GEMM_SMEM);

    split_x<<<Mtot * Dd / 1024, 256>>>(x);
    split_w<<<Dd * Dd / 1024, 256>>>(Wq, 0);
    split_w<<<Dd * Dd / 1024, 256>>>(Wk, 1);
    split_w<<<Dd * Dd / 1024, 256>>>(Wv, 2);
    split_w<<<Dd * Dd / 1024, 256>>>(Wo, 3);

    dim3 gblk(Dd / 128, Mtot / 128);   // (8, 32)
    gemm_mma<0, 1><<<gblk, 256, GEMM_SMEM>>>(0, bq, nullptr);
    gemm_mma<0, 2><<<gblk, 256, GEMM_SMEM>>>(1, bk, nullptr);
    gemm_mma<0, 3><<<gblk, 256, GEMM_SMEM>>>(2, bv, nullptr);

    attn_kernel<<<dim3(Ss / 64, Bb * Hh), 256>>>();

    gemm_mma<1, 0><<<gblk, 256, GEMM_SMEM>>>(3, bo, out);
}

// round 4
// speedup vs baseline: 2.8875x; 1.8014x over previous
#include <cuda_runtime.h>
#include <cuda_bf16.h>
#include <cstdint>

#define Bb 2
#define Ss 2048
#define Dd 1024
#define Hh 16
#define HD 64
#define Mtot (Bb*Ss)   // 4096

// ---------------- scratch (static device arrays; alloc APIs forbidden) -----
__device__ __align__(16) __nv_bfloat16 g_qh[Bb*Hh*Ss*HD];  // (B,H,S,hd) bf16 hi/lo
__device__ __align__(16) __nv_bfloat16 g_ql[Bb*Hh*Ss*HD];
__device__ __align__(16) __nv_bfloat16 g_kh[Bb*Hh*Ss*HD];
__device__ __align__(16) __nv_bfloat16 g_kl[Bb*Hh*Ss*HD];
__device__ __align__(16) __nv_bfloat16 g_vh[Bb*Hh*Ss*HD];
__device__ __align__(16) __nv_bfloat16 g_vl[Bb*Hh*Ss*HD];
__device__ __align__(16) __nv_bfloat16 g_xh[Mtot*Dd];      // x split hi/lo
__device__ __align__(16) __nv_bfloat16 g_xl[Mtot*Dd];
__device__ __align__(16) __nv_bfloat16 g_wh[4u*Dd*Dd];     // Wq,Wk,Wv,Wo hi
__device__ __align__(16) __nv_bfloat16 g_wl[4u*Dd*Dd];     // lo
__device__ __align__(16) __nv_bfloat16 g_ch[Mtot*Dd];      // ctx hi/lo (B,S,D)
__device__ __align__(16) __nv_bfloat16 g_cl[Mtot*Dd];

// ---------------- PTX helpers (sm_80/75-era only) --------------------------
__device__ __forceinline__ uint32_t smem_to_u32(const void* p) {
    uint32_t a;
    asm("{ .reg .u64 t; cvta.to.shared.u64 t, %1; cvt.u32.u64 %0, t; }"
        : "=r"(a) : "l"(p));
    return a;
}
__device__ __forceinline__ void cp_async16(uint32_t dst, const void* src) {
    asm volatile("cp.async.cg.shared.global [%0], [%1], 16;"
                 :: "r"(dst), "l"(src) : "memory");
}
__device__ __forceinline__ void cp_commit() {
    asm volatile("cp.async.commit_group;" ::: "memory");
}
template<int N> __device__ __forceinline__ void cp_wait() {
    asm volatile("cp.async.wait_group %0;" :: "n"(N) : "memory");
}
__device__ __forceinline__ void ldsm_x4(uint32_t* r, uint32_t addr) {
    asm volatile("ldmatrix.sync.aligned.m8n8.x4.shared.b16 {%0,%1,%2,%3}, [%4];"
                 : "=r"(r[0]), "=r"(r[1]), "=r"(r[2]), "=r"(r[3]) : "r"(addr));
}
__device__ __forceinline__ void ldsm_x4_t(uint32_t* r, uint32_t addr) {
    asm volatile("ldmatrix.sync.aligned.m8n8.x4.trans.shared.b16 {%0,%1,%2,%3}, [%4];"
                 : "=r"(r[0]), "=r"(r[1]), "=r"(r[2]), "=r"(r[3]) : "r"(addr));
}
__device__ __forceinline__ void mma16816(float* c, const uint32_t* a, const uint32_t* b) {
    asm volatile("mma.sync.aligned.m16n8k16.row.col.f32.bf16.bf16.f32 "
                 "{%0,%1,%2,%3}, {%4,%5,%6,%7}, {%8,%9}, {%0,%1,%2,%3};"
                 : "+f"(c[0]), "+f"(c[1]), "+f"(c[2]), "+f"(c[3])
                 : "r"(a[0]), "r"(a[1]), "r"(a[2]), "r"(a[3]), "r"(b[0]), "r"(b[1]));
}

// ---------------- fp32 -> bf16 hi/lo split ---------------------------------
__device__ __forceinline__ void split2(float v, __nv_bfloat16& h, __nv_bfloat16& l) {
    h = __float2bfloat16(v);
    l = __float2bfloat16(v - __bfloat162float(h));
}
__device__ __forceinline__ uint32_t packbf(float a, float b) {
    __nv_bfloat162 t(__float2bfloat16(a), __float2bfloat16(b));
    return *(uint32_t*)&t;
}

__global__ __launch_bounds__(256) void split_x(const float* __restrict__ src) {
    int i = (blockIdx.x * 256 + threadIdx.x) * 4;
    float4 v = *(const float4*)(src + i);
    __nv_bfloat16 h0, h1, h2, h3, l0, l1, l2, l3;
    split2(v.x, h0, l0); split2(v.y, h1, l1); split2(v.z, h2, l2); split2(v.w, h3, l3);
    *(__nv_bfloat162*)(g_xh + i)     = __nv_bfloat162(h0, h1);
    *(__nv_bfloat162*)(g_xh + i + 2) = __nv_bfloat162(h2, h3);
    *(__nv_bfloat162*)(g_xl + i)     = __nv_bfloat162(l0, l1);
    *(__nv_bfloat162*)(g_xl + i + 2) = __nv_bfloat162(l2, l3);
}

__global__ __launch_bounds__(256) void split_w(const float* __restrict__ src, int widx) {
    int i = (blockIdx.x * 256 + threadIdx.x) * 4;
    size_t o = (size_t)widx * Dd * Dd + i;
    float4 v = *(const float4*)(src + i);
    __nv_bfloat16 h0, h1, h2, h3, l0, l1, l2, l3;
    split2(v.x, h0, l0); split2(v.y, h1, l1); split2(v.z, h2, l2); split2(v.w, h3, l3);
    *(__nv_bfloat162*)(g_wh + o)     = __nv_bfloat162(h0, h1);
    *(__nv_bfloat162*)(g_wh + o + 2) = __nv_bfloat162(h2, h3);
    *(__nv_bfloat162*)(g_wl + o)     = __nv_bfloat162(l0, l1);
    *(__nv_bfloat162*)(g_wl + o + 2) = __nv_bfloat162(l2, l3);
}

// ---------------------------------------------------------------------------
// mma.sync GEMM (3-term bf16 split). Block 128x128, 8 warps, double-buffered
// cp.async. OSEL: 0 -> Cout fp32 [M,N]; 1/2/3 -> Q/K/V bf16 hi/lo with head
// permute (Q pre-scaled by 1/8).
// ---------------------------------------------------------------------------
#define TILE_B   10240                 // 128 * 80
#define BUF_B    (4 * TILE_B)
#define GEMM_SMEM (2 * BUF_B + 512)

template<int ASEL, int OSEL>
__global__ __launch_bounds__(256)
void gemm_mma(int widx, const float* __restrict__ bias, float* __restrict__ Cout)
{
    extern __shared__ char smem[];
    const uint32_t sb = smem_to_u32(smem);
    float* biasS = (float*)(smem + 2 * BUF_B);

    const int tid = threadIdx.x, wid = tid >> 5, lid = tid & 31;
    const int wm = wid >> 2, wn = wid & 3;
    const int m0 = blockIdx.y * 128, n0 = blockIdx.x * 128;

    const __nv_bfloat16* Ah = (ASEL == 0) ? g_xh : g_ch;
    const __nv_bfloat16* Al = (ASEL == 0) ? g_xl : g_cl;
    const __nv_bfloat16* Wh = g_wh + (size_t)widx * Dd * Dd;
    const __nv_bfloat16* Wl = g_wl + (size_t)widx * Dd * Dd;

    if (tid < 128) biasS[tid] = bias[n0 + tid];

    float acc[4][4][4];
#pragma unroll
    for (int i = 0; i < 4; i++)
#pragma unroll
        for (int j = 0; j < 4; j++)
#pragma unroll
            for (int k = 0; k < 4; k++) acc[i][j][k] = 0.f;

    auto issue = [&](int kt, int buf) {
        const int kc = kt * 32;
#pragma unroll
        for (int i = 0; i < 8; i++) {
            int idx = tid + i * 256;
            int tile = idx >> 9, w = idx & 511;
            int r = w >> 2, seg = (w & 3) * 16;
            uint32_t dst = sb + buf * BUF_B + tile * TILE_B + r * 80 + seg;
            const char* src;
            if (tile == 0)      src = (const char*)(Ah + (size_t)(m0 + r) * Dd + kc) + seg;
            else if (tile == 1) src = (const char*)(Al + (size_t)(m0 + r) * Dd + kc) + seg;
            else if (tile == 2) src = (const char*)(Wh + (size_t)(n0 + r) * Dd + kc) + seg;
            else                src = (const char*)(Wl + (size_t)(n0 + r) * Dd + kc) + seg;
            cp_async16(dst, src);
        }
        cp_commit();
    };

    issue(0, 0);
    int buf = 0;
    const int arow0 = wm * 64 + (lid & 15);
    const int abyte0 = (lid >> 4) * 16;
    const int brow0 = wn * 32 + ((lid >> 4) << 3) + (lid & 7);
    const int bbyte0 = ((lid >> 3) & 1) * 16;

    for (int kt = 0; kt < 32; kt++) {
        if (kt + 1 < 32) { issue(kt + 1, buf ^ 1); cp_wait<1>(); }
        else             { cp_wait<0>(); }
        __syncthreads();

        const uint32_t tAh = sb + buf * BUF_B;
        const uint32_t tAl = tAh + TILE_B;
        const uint32_t tBh = tAh + 2 * TILE_B;
        const uint32_t tBl = tAh + 3 * TILE_B;

#pragma unroll
        for (int kk = 0; kk < 2; kk++) {
            uint32_t aH[4][4], aL[4][4], bH[4][2], bL[4][2];
            const int ab = kk * 32 + abyte0;
            const int bb = kk * 32 + bbyte0;
#pragma unroll
            for (int mf = 0; mf < 4; mf++) {
                uint32_t ro = (arow0 + mf * 16) * 80;
                ldsm_x4(aH[mf], tAh + ro + ab);
                ldsm_x4(aL[mf], tAl + ro + ab);
            }
#pragma unroll
            for (int nf2 = 0; nf2 < 2; nf2++) {
                uint32_t ro = (brow0 + nf2 * 16) * 80;
                uint32_t r4[4];
                ldsm_x4(r4, tBh + ro + bb);
                bH[nf2 * 2][0] = r4[0]; bH[nf2 * 2][1] = r4[1];
                bH[nf2 * 2 + 1][0] = r4[2]; bH[nf2 * 2 + 1][1] = r4[3];
                ldsm_x4(r4, tBl + ro + bb);
                bL[nf2 * 2][0] = r4[0]; bL[nf2 * 2][1] = r4[1];
                bL[nf2 * 2 + 1][0] = r4[2]; bL[nf2 * 2 + 1][1] = r4[3];
            }
#pragma unroll
            for (int mf = 0; mf < 4; mf++)
#pragma unroll
                for (int nf = 0; nf < 4; nf++) {
                    mma16816(acc[mf][nf], aH[mf], bH[nf]);
                    mma16816(acc[mf][nf], aH[mf], bL[nf]);
                    mma16816(acc[mf][nf], aL[mf], bH[nf]);
                }
        }
        __syncthreads();
        buf ^= 1;
    }

#pragma unroll
    for (int mf = 0; mf < 4; mf++) {
#pragma unroll
        for (int nf = 0; nf < 4; nf++) {
            int nl = wn * 32 + nf * 8 + (lid & 3) * 2;
            int n = n0 + nl;
            float b0 = biasS[nl], b1 = biasS[nl + 1];
#pragma unroll
            for (int half = 0; half < 2; half++) {
                int m = m0 + wm * 64 + mf * 16 + (lid >> 2) + half * 8;
                float v0 = acc[mf][nf][half * 2 + 0] + b0;
                float v1 = acc[mf][nf][half * 2 + 1] + b1;
                if (OSEL == 0) {
                    *(float2*)(Cout + (size_t)m * Dd + n) = make_float2(v0, v1);
                } else {
                    if (OSEL == 1) { v0 *= 0.125f; v1 *= 0.125f; }  // 1/sqrt(hd)
                    __nv_bfloat16 h0, l0, h1, l1;
                    split2(v0, h0, l0); split2(v1, h1, l1);
                    __nv_bfloat16* dh = (OSEL == 1) ? g_qh : (OSEL == 2) ? g_kh : g_vh;
                    __nv_bfloat16* dl = (OSEL == 1) ? g_ql : (OSEL == 2) ? g_kl : g_vl;
                    int b = m >> 11, s = m & (Ss - 1);
                    int hh = n >> 6, d = n & (HD - 1);
                    size_t o = (((size_t)(b * Hh + hh)) * Ss + s) * HD + d;
                    *(__nv_bfloat162*)(dh + o) = __nv_bfloat162(h0, h1);
                    *(__nv_bfloat162*)(dl + o) = __nv_bfloat162(l0, l1);
                }
            }
        }
    }
}

// ---------------------------------------------------------------------------
// Tensor-core causal flash attention, bf16 3-term split.
// CTA = 128 threads (4 warps), 64-row q tile; warp w owns rows w*16..w*16+15
// of the tile, all 64 k-cols. K/V tiles double-buffered via cp.async.
// Smem row stride 144B (9 slots, 9r mod 8 = permutation => conflict-free).
// ---------------------------------------------------------------------------
#define AT_STRIDE 144
#define AT_TILE   (64 * AT_STRIDE)           // 9216
#define AT_KV0    (2 * AT_TILE)
#define ATTN_SMEM (2 * AT_TILE + 2 * 4 * AT_TILE)   // 92160

__global__ __launch_bounds__(128)
void attn_mma()
{
    extern __shared__ char smem[];
    const uint32_t sb = smem_to_u32(smem);
    const int qt = blockIdx.x;                 // q tile (64 rows)
    const int bh = blockIdx.y;
    const int b = bh >> 4, h = bh & 15;
    const int tid = threadIdx.x, wid = tid >> 5, lid = tid & 31;

    const __nv_bfloat16* QH = g_qh + ((size_t)bh * Ss + qt * 64) * HD;
    const __nv_bfloat16* QL = g_ql + ((size_t)bh * Ss + qt * 64) * HD;
    const __nv_bfloat16* bases[4] = {
        g_kh + (size_t)bh * Ss * HD, g_kl + (size_t)bh * Ss * HD,
        g_vh + (size_t)bh * Ss * HD, g_vl + (size_t)bh * Ss * HD };

    // Q tile (Qh, Ql): 64 rows x 128B
#pragma unroll
    for (int i = 0; i < 8; i++) {
        int idx = tid + i * 128;
        int s = idx >> 9, w = idx & 511;
        int r = w >> 3, c = w & 7;
        cp_async16(sb + s * AT_TILE + r * AT_STRIDE + c * 16,
                   (s ? QL : QH) + r * HD + c * 8);
    }
    cp_commit();

    auto issue = [&](int kt, int buf) {
#pragma unroll
        for (int i = 0; i < 16; i++) {
            int idx = tid + i * 128;
            int t = idx >> 9, w = idx & 511;
            int r = w >> 3, c = w & 7;
            cp_async16(sb + AT_KV0 + buf * (4 * AT_TILE) + t * AT_TILE + r * AT_STRIDE + c * 16,
                       bases[t] + (size_t)(kt * 64 + r) * HD + c * 8);
        }
        cp_commit();
    };
    issue(0, 0);

    float acc[8][4];
#pragma unroll
    for (int i = 0; i < 8; i++)
#pragma unroll
        for (int j = 0; j < 4; j++) acc[i][j] = 0.f;
    float mrow[2] = { -1e30f, -1e30f }, lrow[2] = { 0.f, 0.f };

    const uint32_t qrowb = (wid * 16 + (lid & 15)) * AT_STRIDE + (lid >> 4) * 16;
    const uint32_t krowb = (((lid >> 4) << 3) + (lid & 7)) * AT_STRIDE + ((lid >> 3) & 1) * 16;
    const uint32_t vrowb = (lid & 15) * AT_STRIDE + ((lid >> 4) & 1) * 16;
    int buf = 0;

    for (int kt = 0; kt <= qt; kt++) {
        if (kt < qt) { issue(kt + 1, buf ^ 1); cp_wait<1>(); }
        else         { cp_wait<0>(); }
        __syncthreads();

        const uint32_t kbh = sb + AT_KV0 + buf * (4 * AT_TILE);
        const uint32_t kbl = kbh + AT_TILE;
        const uint32_t vbh = kbh + 2 * AT_TILE;
        const uint32_t vbl = kbh + 3 * AT_TILE;

        // ---- S = Qh Kh^T + Qh Kl^T + Ql Kh^T ----
        float sf[8][4];
#pragma unroll
        for (int i = 0; i < 8; i++)
#pragma unroll
            for (int j = 0; j < 4; j++) sf[i][j] = 0.f;

#pragma unroll
        for (int kk = 0; kk < 4; kk++) {
            uint32_t aH[4], aL[4];
            ldsm_x4(aH, sb + qrowb + kk * 32);
            ldsm_x4(aL, sb + AT_TILE + qrowb + kk * 32);
#pragma unroll
            for (int nf2 = 0; nf2 < 4; nf2++) {
                uint32_t ba = nf2 * 16 * AT_STRIDE + krowb + kk * 32;
                uint32_t rH[4], rL[4];
                ldsm_x4(rH, kbh + ba);
                ldsm_x4(rL, kbl + ba);
                mma16816(sf[nf2 * 2],     aH, rH);
                mma16816(sf[nf2 * 2 + 1], aH, rH + 2);
                mma16816(sf[nf2 * 2],     aH, rL);
                mma16816(sf[nf2 * 2 + 1], aH, rL + 2);
                mma16816(sf[nf2 * 2],     aL, rH);
                mma16816(sf[nf2 * 2 + 1], aL, rH + 2);
            }
        }

        if (kt == qt) {       // causal mask on diagonal tile
            int r0 = wid * 16 + (lid >> 2);
#pragma unroll
            for (int nf = 0; nf < 8; nf++) {
                int c0 = nf * 8 + (lid & 3) * 2;
                if (c0     > r0)     sf[nf][0] = -1e30f;
                if (c0 + 1 > r0)     sf[nf][1] = -1e30f;
                if (c0     > r0 + 8) sf[nf][2] = -1e30f;
                if (c0 + 1 > r0 + 8) sf[nf][3] = -1e30f;
            }
        }

        // ---- online softmax (row lives in 4 lanes: xor 1,2) ----
#pragma unroll
        for (int hf = 0; hf < 2; hf++) {
            float mx = -1e30f;
#pragma unroll
            for (int nf = 0; nf < 8; nf++)
                mx = fmaxf(mx, fmaxf(sf[nf][hf * 2], sf[nf][hf * 2 + 1]));
            mx = fmaxf(mx, __shfl_xor_sync(0xffffffffu, mx, 1));
            mx = fmaxf(mx, __shfl_xor_sync(0xffffffffu, mx, 2));
            float mnew = fmaxf(mrow[hf], mx);
            float alpha = __expf(mrow[hf] - mnew);
            mrow[hf] = mnew;
            float sum = 0.f;
#pragma unroll
            for (int nf = 0; nf < 8; nf++) {
                sf[nf][hf * 2]     = __expf(sf[nf][hf * 2] - mnew);
                sf[nf][hf * 2 + 1] = __expf(sf[nf][hf * 2 + 1] - mnew);
                sum += sf[nf][hf * 2] + sf[nf][hf * 2 + 1];
            }
            sum += __shfl_xor_sync(0xffffffffu, sum, 1);
            sum += __shfl_xor_sync(0xffffffffu, sum, 2);
            lrow[hf] = lrow[hf] * alpha + sum;
#pragma unroll
            for (int nf = 0; nf < 8; nf++) {
                acc[nf][hf * 2]     *= alpha;
                acc[nf][hf * 2 + 1] *= alpha;
            }
        }

        // ---- O += Ph Vh + Ph Vl + Pl Vh ----
#pragma unroll
        for (int kk2 = 0; kk2 < 4; kk2++) {
            uint32_t aPh[4], aPl[4];
#pragma unroll
            for (int q = 0; q < 2; q++) {
                const float* c = sf[kk2 * 2 + q];
                float h0f = __bfloat162float(__float2bfloat16(c[0]));
                float h1f = __bfloat162float(__float2bfloat16(c[1]));
                float h2f = __bfloat162float(__float2bfloat16(c[2]));
                float h3f = __bfloat162float(__float2bfloat16(c[3]));
                aPh[q * 2]     = packbf(c[0], c[1]);
                aPh[q * 2 + 1] = packbf(c[2], c[3]);
                aPl[q * 2]     = packbf(c[0] - h0f, c[1] - h1f);
                aPl[q * 2 + 1] = packbf(c[2] - h2f, c[3] - h3f);
            }
#pragma unroll
            for (int nf2 = 0; nf2 < 4; nf2++) {
                uint32_t va = (kk2 * 16) * AT_STRIDE + vrowb + nf2 * 32;
                uint32_t vH[4], vL[4];
                ldsm_x4_t(vH, vbh + va);
                ldsm_x4_t(vL, vbl + va);
                mma16816(acc[nf2 * 2],     aPh, vH);
                mma16816(acc[nf2 * 2 + 1], aPh, vH + 2);
                mma16816(acc[nf2 * 2],     aPh, vL);
                mma16816(acc[nf2 * 2 + 1], aPh, vL + 2);
                mma16816(acc[nf2 * 2],     aPl, vH);
                mma16816(acc[nf2 * 2 + 1], aPl, vH + 2);
            }
        }
        __syncthreads();    // all reads of buf done before next issue overwrites
        buf ^= 1;
    }

    // ---- epilogue: ctx -> bf16 hi/lo (B,S,D) ----
    float inv0 = 1.f / lrow[0], inv1 = 1.f / lrow[1];
    int r0 = qt * 64 + wid * 16 + (lid >> 2);
#pragma unroll
    for (int nf = 0; nf < 8; nf++) {
        int d0 = h * HD + nf * 8 + (lid & 3) * 2;
        size_t o0 = ((size_t)b * Ss + r0) * Dd + d0;
        size_t o1 = ((size_t)b * Ss + r0 + 8) * Dd + d0;
        float v0 = acc[nf][0] * inv0, v1 = acc[nf][1] * inv0;
        float v2 = acc[nf][2] * inv1, v3 = acc[nf][3] * inv1;
        __nv_bfloat16 h0, l0, h1, l1, h2, l2, h3, l3;
        split2(v0, h0, l0); split2(v1, h1, l1);
        split2(v2, h2, l2); split2(v3, h3, l3);
        *(__nv_bfloat162*)(g_ch + o0) = __nv_bfloat162(h0, h1);
        *(__nv_bfloat162*)(g_cl + o0) = __nv_bfloat162(l0, l1);
        *(__nv_bfloat162*)(g_ch + o1) = __nv_bfloat162(h2, h3);
        *(__nv_bfloat162*)(g_cl + o1) = __nv_bfloat162(l2, l3);
    }
}

// ---------------------------------------------------------------------------
extern "C" void kernel_launch(void* const* d_in, const int* in_sizes, int n_in,
                              void* d_out, int out_size)
{
    const float* x  = (const float*)d_in[0];
    const float* Wq = (const float*)d_in[1];
    const float* bq = (const float*)d_in[2];
    const float* Wk = (const float*)d_in[3];
    const float* bk = (const float*)d_in[4];
    const float* Wv = (const float*)d_in[5];
    const float* bv = (const float*)d_in[6];
    const float* Wo = (const float*)d_in[7];
    const float* bo = (const float*)d_in[8];
    float* out = (float*)d_out;

    cudaFuncSetAttribute(gemm_mma<0, 1>, cudaFuncAttributeMaxDynamicSharedMemorySize, GEMM_SMEM);
    cudaFuncSetAttribute(gemm_mma<0, 2>, cudaFuncAttributeMaxDynamicSharedMemorySize, GEMM_SMEM);
    cudaFuncSetAttribute(gemm_mma<0, 3>, cudaFuncAttributeMaxDynamicSharedMemorySize, GEMM_SMEM);
    cudaFuncSetAttribute(gemm_mma<1, 0>, cudaFuncAttributeMaxDynamicSharedMemorySize, GEMM_SMEM);
    cudaFuncSetAttribute(attn_mma, cudaFuncAttributeMaxDynamicSharedMemorySize, ATTN_SMEM);

    split_x<<<Mtot * Dd / 1024, 256>>>(x);
    split_w<<<Dd * Dd / 1024, 256>>>(Wq, 0);
    split_w<<<Dd * Dd / 1024, 256>>>(Wk, 1);
    split_w<<<Dd * Dd / 1024, 256>>>(Wv, 2);
    split_w<<<Dd * Dd / 1024, 256>>>(Wo, 3);

    dim3 gblk(Dd / 128, Mtot / 128);   // (8, 32)
    gemm_mma<0, 1><<<gblk, 256, GEMM_SMEM>>>(0, bq, nullptr);
    gemm_mma<0, 2><<<gblk, 256, GEMM_SMEM>>>(1, bk, nullptr);
    gemm_mma<0, 3><<<gblk, 256, GEMM_SMEM>>>(2, bv, nullptr);

    attn_mma<<<dim3(Ss / 64, Bb * Hh), 128, ATTN_SMEM>>>();

    gemm_mma<1, 0><<<gblk, 256, GEMM_SMEM>>>(3, bo, out);
}

// round 5
// speedup vs baseline: 2.8996x; 1.0042x over previous
#include <cuda_runtime.h>
#include <cuda_bf16.h>
#include <cstdint>

#define Bb 2
#define Ss 2048
#define Dd 1024
#define Hh 16
#define HD 64
#define Mtot (Bb*Ss)   // 4096
#define QSCALE 0.1803368801111244f   // 0.125 * log2(e): softmax in exp2 domain

// ---------------- scratch (static device arrays; alloc APIs forbidden) -----
__device__ __align__(16) __nv_bfloat16 g_qh[Bb*Hh*Ss*HD];  // (B,H,S,hd) bf16 hi/lo
__device__ __align__(16) __nv_bfloat16 g_ql[Bb*Hh*Ss*HD];
__device__ __align__(16) __nv_bfloat16 g_kh[Bb*Hh*Ss*HD];
__device__ __align__(16) __nv_bfloat16 g_kl[Bb*Hh*Ss*HD];
__device__ __align__(16) __nv_bfloat16 g_vh[Bb*Hh*Ss*HD];
__device__ __align__(16) __nv_bfloat16 g_vl[Bb*Hh*Ss*HD];
__device__ __align__(16) __nv_bfloat16 g_xh[Mtot*Dd];      // x split hi/lo
__device__ __align__(16) __nv_bfloat16 g_xl[Mtot*Dd];
__device__ __align__(16) __nv_bfloat16 g_wh[4u*Dd*Dd];     // Wq,Wk,Wv,Wo hi
__device__ __align__(16) __nv_bfloat16 g_wl[4u*Dd*Dd];     // lo
__device__ __align__(16) __nv_bfloat16 g_ch[Mtot*Dd];      // ctx hi/lo (B,S,D)
__device__ __align__(16) __nv_bfloat16 g_cl[Mtot*Dd];

// ---------------- PTX helpers (sm_80/75-era only) --------------------------
__device__ __forceinline__ uint32_t smem_to_u32(const void* p) {
    uint32_t a;
    asm("{ .reg .u64 t; cvta.to.shared.u64 t, %1; cvt.u32.u64 %0, t; }"
        : "=r"(a) : "l"(p));
    return a;
}
__device__ __forceinline__ void cp_async16(uint32_t dst, const void* src) {
    asm volatile("cp.async.cg.shared.global [%0], [%1], 16;"
                 :: "r"(dst), "l"(src) : "memory");
}
__device__ __forceinline__ void cp_commit() {
    asm volatile("cp.async.commit_group;" ::: "memory");
}
template<int N> __device__ __forceinline__ void cp_wait() {
    asm volatile("cp.async.wait_group %0;" :: "n"(N) : "memory");
}
__device__ __forceinline__ void ldsm_x4(uint32_t* r, uint32_t addr) {
    asm volatile("ldmatrix.sync.aligned.m8n8.x4.shared.b16 {%0,%1,%2,%3}, [%4];"
                 : "=r"(r[0]), "=r"(r[1]), "=r"(r[2]), "=r"(r[3]) : "r"(addr));
}
__device__ __forceinline__ void ldsm_x4_t(uint32_t* r, uint32_t addr) {
    asm volatile("ldmatrix.sync.aligned.m8n8.x4.trans.shared.b16 {%0,%1,%2,%3}, [%4];"
                 : "=r"(r[0]), "=r"(r[1]), "=r"(r[2]), "=r"(r[3]) : "r"(addr));
}
__device__ __forceinline__ void mma16816(float* c, const uint32_t* a, const uint32_t* b) {
    asm volatile("mma.sync.aligned.m16n8k16.row.col.f32.bf16.bf16.f32 "
                 "{%0,%1,%2,%3}, {%4,%5,%6,%7}, {%8,%9}, {%0,%1,%2,%3};"
                 : "+f"(c[0]), "+f"(c[1]), "+f"(c[2]), "+f"(c[3])
                 : "r"(a[0]), "r"(a[1]), "r"(a[2]), "r"(a[3]), "r"(b[0]), "r"(b[1]));
}
__device__ __forceinline__ float ex2(float x) {
    float y;
    asm("ex2.approx.ftz.f32 %0, %1;" : "=f"(y) : "f"(x));
    return y;
}

// ---------------- fp32 -> bf16 hi/lo split ---------------------------------
__device__ __forceinline__ void split2(float v, __nv_bfloat16& h, __nv_bfloat16& l) {
    h = __float2bfloat16(v);
    l = __float2bfloat16(v - __bfloat162float(h));
}
__device__ __forceinline__ uint32_t packbf(float a, float b) {
    __nv_bfloat162 t(__float2bfloat16(a), __float2bfloat16(b));
    return *(uint32_t*)&t;
}

// One launch: split x (first 4M elems) and all 4 weights (next 4M).
__global__ __launch_bounds__(256)
void split_all(const float* __restrict__ x,  const float* __restrict__ Wq,
               const float* __restrict__ Wk, const float* __restrict__ Wv,
               const float* __restrict__ Wo)
{
    int i = (blockIdx.x * 256 + threadIdx.x) * 4;
    const float* src;
    __nv_bfloat16 *dh, *dl;
    if (i < Mtot * Dd) {
        src = x + i; dh = g_xh + i; dl = g_xl + i;
    } else {
        int j = i - Mtot * Dd;
        int w = j >> 20;                 // Dd*Dd = 2^20
        int r = j & (Dd * Dd - 1);
        src = (w == 0 ? Wq : w == 1 ? Wk : w == 2 ? Wv : Wo) + r;
        dh = g_wh + j; dl = g_wl + j;
    }
    float4 v = *(const float4*)src;
    __nv_bfloat16 h0, h1, h2, h3, l0, l1, l2, l3;
    split2(v.x, h0, l0); split2(v.y, h1, l1); split2(v.z, h2, l2); split2(v.w, h3, l3);
    *(__nv_bfloat162*)(dh)     = __nv_bfloat162(h0, h1);
    *(__nv_bfloat162*)(dh + 2) = __nv_bfloat162(h2, h3);
    *(__nv_bfloat162*)(dl)     = __nv_bfloat162(l0, l1);
    *(__nv_bfloat162*)(dl + 2) = __nv_bfloat162(l2, l3);
}

// ---------------------------------------------------------------------------
// mma.sync GEMM core constants (block 128x128, 8 warps, double-buffered).
// ---------------------------------------------------------------------------
#define TILE_B   10240                 // 128 * 80
#define BUF_B    (4 * TILE_B)
#define GEMM_SMEM (2 * BUF_B + 512)

// Fused QKV projection: gridDim.z selects Q/K/V (one packed launch).
__global__ __launch_bounds__(256)
void gemm_qkv(const float* __restrict__ bq, const float* __restrict__ bk,
              const float* __restrict__ bv)
{
    extern __shared__ char smem[];
    const uint32_t sb = smem_to_u32(smem);
    float* biasS = (float*)(smem + 2 * BUF_B);

    const int tid = threadIdx.x, wid = tid >> 5, lid = tid & 31;
    const int wm = wid >> 2, wn = wid & 3;
    const int m0 = blockIdx.y * 128, n0 = blockIdx.x * 128;
    const int z = blockIdx.z;

    const float* bias = (z == 0) ? bq : (z == 1) ? bk : bv;
    const __nv_bfloat16* Wh = g_wh + (size_t)z * Dd * Dd;
    const __nv_bfloat16* Wl = g_wl + (size_t)z * Dd * Dd;

    if (tid < 128) biasS[tid] = bias[n0 + tid];

    float acc[4][4][4];
#pragma unroll
    for (int i = 0; i < 4; i++)
#pragma unroll
        for (int j = 0; j < 4; j++)
#pragma unroll
            for (int k = 0; k < 4; k++) acc[i][j][k] = 0.f;

    auto issue = [&](int kt, int buf) {
        const int kc = kt * 32;
#pragma unroll
        for (int i = 0; i < 8; i++) {
            int idx = tid + i * 256;
            int tile = idx >> 9, w = idx & 511;
            int r = w >> 2, seg = (w & 3) * 16;
            uint32_t dst = sb + buf * BUF_B + tile * TILE_B + r * 80 + seg;
            const char* src;
            if (tile == 0)      src = (const char*)(g_xh + (size_t)(m0 + r) * Dd + kc) + seg;
            else if (tile == 1) src = (const char*)(g_xl + (size_t)(m0 + r) * Dd + kc) + seg;
            else if (tile == 2) src = (const char*)(Wh + (size_t)(n0 + r) * Dd + kc) + seg;
            else                src = (const char*)(Wl + (size_t)(n0 + r) * Dd + kc) + seg;
            cp_async16(dst, src);
        }
        cp_commit();
    };

    issue(0, 0);
    int buf = 0;
    const int arow0 = wm * 64 + (lid & 15);
    const int abyte0 = (lid >> 4) * 16;
    const int brow0 = wn * 32 + ((lid >> 4) << 3) + (lid & 7);
    const int bbyte0 = ((lid >> 3) & 1) * 16;

    for (int kt = 0; kt < 32; kt++) {
        if (kt + 1 < 32) { issue(kt + 1, buf ^ 1); cp_wait<1>(); }
        else             { cp_wait<0>(); }
        __syncthreads();

        const uint32_t tAh = sb + buf * BUF_B;
        const uint32_t tAl = tAh + TILE_B;
        const uint32_t tBh = tAh + 2 * TILE_B;
        const uint32_t tBl = tAh + 3 * TILE_B;

#pragma unroll
        for (int kk = 0; kk < 2; kk++) {
            uint32_t aH[4][4], aL[4][4], bH[4][2], bL[4][2];
            const int ab = kk * 32 + abyte0;
            const int bb = kk * 32 + bbyte0;
#pragma unroll
            for (int mf = 0; mf < 4; mf++) {
                uint32_t ro = (arow0 + mf * 16) * 80;
                ldsm_x4(aH[mf], tAh + ro + ab);
                ldsm_x4(aL[mf], tAl + ro + ab);
            }
#pragma unroll
            for (int nf2 = 0; nf2 < 2; nf2++) {
                uint32_t ro = (brow0 + nf2 * 16) * 80;
                uint32_t r4[4];
                ldsm_x4(r4, tBh + ro + bb);
                bH[nf2 * 2][0] = r4[0]; bH[nf2 * 2][1] = r4[1];
                bH[nf2 * 2 + 1][0] = r4[2]; bH[nf2 * 2 + 1][1] = r4[3];
                ldsm_x4(r4, tBl + ro + bb);
                bL[nf2 * 2][0] = r4[0]; bL[nf2 * 2][1] = r4[1];
                bL[nf2 * 2 + 1][0] = r4[2]; bL[nf2 * 2 + 1][1] = r4[3];
            }
#pragma unroll
            for (int mf = 0; mf < 4; mf++)
#pragma unroll
                for (int nf = 0; nf < 4; nf++) {
                    mma16816(acc[mf][nf], aH[mf], bH[nf]);
                    mma16816(acc[mf][nf], aH[mf], bL[nf]);
                    mma16816(acc[mf][nf], aL[mf], bH[nf]);
                }
        }
        __syncthreads();
        buf ^= 1;
    }

    const float scale = (z == 0) ? QSCALE : 1.f;
    __nv_bfloat16* dh = (z == 0) ? g_qh : (z == 1) ? g_kh : g_vh;
    __nv_bfloat16* dl = (z == 0) ? g_ql : (z == 1) ? g_kl : g_vl;
#pragma unroll
    for (int mf = 0; mf < 4; mf++) {
#pragma unroll
        for (int nf = 0; nf < 4; nf++) {
            int nl = wn * 32 + nf * 8 + (lid & 3) * 2;
            int n = n0 + nl;
            float b0 = biasS[nl], b1 = biasS[nl + 1];
#pragma unroll
            for (int half = 0; half < 2; half++) {
                int m = m0 + wm * 64 + mf * 16 + (lid >> 2) + half * 8;
                float v0 = (acc[mf][nf][half * 2 + 0] + b0) * scale;
                float v1 = (acc[mf][nf][half * 2 + 1] + b1) * scale;
                __nv_bfloat16 h0, l0, h1, l1;
                split2(v0, h0, l0); split2(v1, h1, l1);
                int b = m >> 11, s = m & (Ss - 1);
                int hh = n >> 6, d = n & (HD - 1);
                size_t o = (((size_t)(b * Hh + hh)) * Ss + s) * HD + d;
                *(__nv_bfloat162*)(dh + o) = __nv_bfloat162(h0, h1);
                *(__nv_bfloat162*)(dl + o) = __nv_bfloat162(l0, l1);
            }
        }
    }
}

// Output GEMM: out = ctx @ Wo^T + bo, fp32 result.
__global__ __launch_bounds__(256)
void gemm_out(const float* __restrict__ bias, float* __restrict__ Cout)
{
    extern __shared__ char smem[];
    const uint32_t sb = smem_to_u32(smem);
    float* biasS = (float*)(smem + 2 * BUF_B);

    const int tid = threadIdx.x, wid = tid >> 5, lid = tid & 31;
    const int wm = wid >> 2, wn = wid & 3;
    const int m0 = blockIdx.y * 128, n0 = blockIdx.x * 128;

    const __nv_bfloat16* Wh = g_wh + (size_t)3 * Dd * Dd;
    const __nv_bfloat16* Wl = g_wl + (size_t)3 * Dd * Dd;

    if (tid < 128) biasS[tid] = bias[n0 + tid];

    float acc[4][4][4];
#pragma unroll
    for (int i = 0; i < 4; i++)
#pragma unroll
        for (int j = 0; j < 4; j++)
#pragma unroll
            for (int k = 0; k < 4; k++) acc[i][j][k] = 0.f;

    auto issue = [&](int kt, int buf) {
        const int kc = kt * 32;
#pragma unroll
        for (int i = 0; i < 8; i++) {
            int idx = tid + i * 256;
            int tile = idx >> 9, w = idx & 511;
            int r = w >> 2, seg = (w & 3) * 16;
            uint32_t dst = sb + buf * BUF_B + tile * TILE_B + r * 80 + seg;
            const char* src;
            if (tile == 0)      src = (const char*)(g_ch + (size_t)(m0 + r) * Dd + kc) + seg;
            else if (tile == 1) src = (const char*)(g_cl + (size_t)(m0 + r) * Dd + kc) + seg;
            else if (tile == 2) src = (const char*)(Wh + (size_t)(n0 + r) * Dd + kc) + seg;
            else                src = (const char*)(Wl + (size_t)(n0 + r) * Dd + kc) + seg;
            cp_async16(dst, src);
        }
        cp_commit();
    };

    issue(0, 0);
    int buf = 0;
    const int arow0 = wm * 64 + (lid & 15);
    const int abyte0 = (lid >> 4) * 16;
    const int brow0 = wn * 32 + ((lid >> 4) << 3) + (lid & 7);
    const int bbyte0 = ((lid >> 3) & 1) * 16;

    for (int kt = 0; kt < 32; kt++) {
        if (kt + 1 < 32) { issue(kt + 1, buf ^ 1); cp_wait<1>(); }
        else             { cp_wait<0>(); }
        __syncthreads();

        const uint32_t tAh = sb + buf * BUF_B;
        const uint32_t tAl = tAh + TILE_B;
        const uint32_t tBh = tAh + 2 * TILE_B;
        const uint32_t tBl = tAh + 3 * TILE_B;

#pragma unroll
        for (int kk = 0; kk < 2; kk++) {
            uint32_t aH[4][4], aL[4][4], bH[4][2], bL[4][2];
            const int ab = kk * 32 + abyte0;
            const int bb = kk * 32 + bbyte0;
#pragma unroll
            for (int mf = 0; mf < 4; mf++) {
                uint32_t ro = (arow0 + mf * 16) * 80;
                ldsm_x4(aH[mf], tAh + ro + ab);
                ldsm_x4(aL[mf], tAl + ro + ab);
            }
#pragma unroll
            for (int nf2 = 0; nf2 < 2; nf2++) {
                uint32_t ro = (brow0 + nf2 * 16) * 80;
                uint32_t r4[4];
                ldsm_x4(r4, tBh + ro + bb);
                bH[nf2 * 2][0] = r4[0]; bH[nf2 * 2][1] = r4[1];
                bH[nf2 * 2 + 1][0] = r4[2]; bH[nf2 * 2 + 1][1] = r4[3];
                ldsm_x4(r4, tBl + ro + bb);
                bL[nf2 * 2][0] = r4[0]; bL[nf2 * 2][1] = r4[1];
                bL[nf2 * 2 + 1][0] = r4[2]; bL[nf2 * 2 + 1][1] = r4[3];
            }
#pragma unroll
            for (int mf = 0; mf < 4; mf++)
#pragma unroll
                for (int nf = 0; nf < 4; nf++) {
                    mma16816(acc[mf][nf], aH[mf], bH[nf]);
                    mma16816(acc[mf][nf], aH[mf], bL[nf]);
                    mma16816(acc[mf][nf], aL[mf], bH[nf]);
                }
        }
        __syncthreads();
        buf ^= 1;
    }

#pragma unroll
    for (int mf = 0; mf < 4; mf++) {
#pragma unroll
        for (int nf = 0; nf < 4; nf++) {
            int nl = wn * 32 + nf * 8 + (lid & 3) * 2;
            int n = n0 + nl;
            float b0 = biasS[nl], b1 = biasS[nl + 1];
#pragma unroll
            for (int half = 0; half < 2; half++) {
                int m = m0 + wm * 64 + mf * 16 + (lid >> 2) + half * 8;
                *(float2*)(Cout + (size_t)m * Dd + n) =
                    make_float2(acc[mf][nf][half * 2 + 0] + b0,
                                acc[mf][nf][half * 2 + 1] + b1);
            }
        }
    }
}

// ---------------------------------------------------------------------------
// Tensor-core causal flash attention, bf16 3-term split, exp2-domain softmax.
// Each CTA processes the PAIRED q-tiles (pr, 31-pr) -> uniform 33 k-tiles of
// work per CTA (removes causal load imbalance). 128 threads / 4 warps.
// ---------------------------------------------------------------------------
#define AT_STRIDE 144
#define AT_TILE   (64 * AT_STRIDE)           // 9216
#define AT_KV0    (2 * AT_TILE)
#define ATTN_SMEM (2 * AT_TILE + 2 * 4 * AT_TILE)   // 92160

__global__ __launch_bounds__(128)
void attn_mma()
{
    extern __shared__ char smem[];
    const uint32_t sb = smem_to_u32(smem);
    const int pr = blockIdx.x;                 // pair index 0..15
    const int bh = blockIdx.y;
    const int b = bh >> 4, h = bh & 15;
    const int tid = threadIdx.x, wid = tid >> 5, lid = tid & 31;

    const __nv_bfloat16* bases[4] = {
        g_kh + (size_t)bh * Ss * HD, g_kl + (size_t)bh * Ss * HD,
        g_vh + (size_t)bh * Ss * HD, g_vl + (size_t)bh * Ss * HD };

    auto issue = [&](int kt, int bf) {
#pragma unroll
        for (int i = 0; i < 16; i++) {
            int idx = tid + i * 128;
            int t = idx >> 9, w = idx & 511;
            int r = w >> 3, c = w & 7;
            cp_async16(sb + AT_KV0 + bf * (4 * AT_TILE) + t * AT_TILE + r * AT_STRIDE + c * 16,
                       bases[t] + (size_t)(kt * 64 + r) * HD + c * 8);
        }
        cp_commit();
    };

    const uint32_t qrowb = (wid * 16 + (lid & 15)) * AT_STRIDE + (lid >> 4) * 16;
    const uint32_t krowb = (((lid >> 4) << 3) + (lid & 7)) * AT_STRIDE + ((lid >> 3) & 1) * 16;
    const uint32_t vrowb = (lid & 15) * AT_STRIDE + ((lid >> 4) & 1) * 16;
    int buf = 0;

    for (int half_t = 0; half_t < 2; half_t++) {
        const int qt = half_t ? (31 - pr) : pr;
        const __nv_bfloat16* QH = g_qh + ((size_t)bh * Ss + qt * 64) * HD;
        const __nv_bfloat16* QL = g_ql + ((size_t)bh * Ss + qt * 64) * HD;

        // Q tile (Qh, Ql): 64 rows x 128B
#pragma unroll
        for (int i = 0; i < 8; i++) {
            int idx = tid + i * 128;
            int s = idx >> 9, w = idx & 511;
            int r = w >> 3, c = w & 7;
            cp_async16(sb + s * AT_TILE + r * AT_STRIDE + c * 16,
                       (s ? QL : QH) + r * HD + c * 8);
        }
        cp_commit();
        issue(0, buf);

        float acc[8][4];
#pragma unroll
        for (int i = 0; i < 8; i++)
#pragma unroll
            for (int j = 0; j < 4; j++) acc[i][j] = 0.f;
        float mrow[2] = { -1e30f, -1e30f }, lrow[2] = { 0.f, 0.f };

        for (int kt = 0; kt <= qt; kt++) {
            if (kt < qt) { issue(kt + 1, buf ^ 1); cp_wait<1>(); }
            else         { cp_wait<0>(); }
            __syncthreads();

            const uint32_t kbh = sb + AT_KV0 + buf * (4 * AT_TILE);
            const uint32_t kbl = kbh + AT_TILE;
            const uint32_t vbh = kbh + 2 * AT_TILE;
            const uint32_t vbl = kbh + 3 * AT_TILE;

            // ---- S = Qh Kh^T + Qh Kl^T + Ql Kh^T (log2-scaled) ----
            float sf[8][4];
#pragma unroll
            for (int i = 0; i < 8; i++)
#pragma unroll
                for (int j = 0; j < 4; j++) sf[i][j] = 0.f;

#pragma unroll
            for (int kk = 0; kk < 4; kk++) {
                uint32_t aH[4], aL[4];
                ldsm_x4(aH, sb + qrowb + kk * 32);
                ldsm_x4(aL, sb + AT_TILE + qrowb + kk * 32);
#pragma unroll
                for (int nf2 = 0; nf2 < 4; nf2++) {
                    uint32_t ba = nf2 * 16 * AT_STRIDE + krowb + kk * 32;
                    uint32_t rH[4], rL[4];
                    ldsm_x4(rH, kbh + ba);
                    ldsm_x4(rL, kbl + ba);
                    mma16816(sf[nf2 * 2],     aH, rH);
                    mma16816(sf[nf2 * 2 + 1], aH, rH + 2);
                    mma16816(sf[nf2 * 2],     aH, rL);
                    mma16816(sf[nf2 * 2 + 1], aH, rL + 2);
                    mma16816(sf[nf2 * 2],     aL, rH);
                    mma16816(sf[nf2 * 2 + 1], aL, rH + 2);
                }
            }

            if (kt == qt) {       // causal mask on diagonal tile
                int r0 = wid * 16 + (lid >> 2);
#pragma unroll
                for (int nf = 0; nf < 8; nf++) {
                    int c0 = nf * 8 + (lid & 3) * 2;
                    if (c0     > r0)     sf[nf][0] = -1e30f;
                    if (c0 + 1 > r0)     sf[nf][1] = -1e30f;
                    if (c0     > r0 + 8) sf[nf][2] = -1e30f;
                    if (c0 + 1 > r0 + 8) sf[nf][3] = -1e30f;
                }
            }

            // ---- online softmax in exp2 domain ----
#pragma unroll
            for (int hf = 0; hf < 2; hf++) {
                float mx = -1e30f;
#pragma unroll
                for (int nf = 0; nf < 8; nf++)
                    mx = fmaxf(mx, fmaxf(sf[nf][hf * 2], sf[nf][hf * 2 + 1]));
                mx = fmaxf(mx, __shfl_xor_sync(0xffffffffu, mx, 1));
                mx = fmaxf(mx, __shfl_xor_sync(0xffffffffu, mx, 2));
                float mnew = fmaxf(mrow[hf], mx);
                float alpha = ex2(mrow[hf] - mnew);
                mrow[hf] = mnew;
                float sum = 0.f;
#pragma unroll
                for (int nf = 0; nf < 8; nf++) {
                    sf[nf][hf * 2]     = ex2(sf[nf][hf * 2] - mnew);
                    sf[nf][hf * 2 + 1] = ex2(sf[nf][hf * 2 + 1] - mnew);
                    sum += sf[nf][hf * 2] + sf[nf][hf * 2 + 1];
                }
                sum += __shfl_xor_sync(0xffffffffu, sum, 1);
                sum += __shfl_xor_sync(0xffffffffu, sum, 2);
                lrow[hf] = lrow[hf] * alpha + sum;
#pragma unroll
                for (int nf = 0; nf < 8; nf++) {
                    acc[nf][hf * 2]     *= alpha;
                    acc[nf][hf * 2 + 1] *= alpha;
                }
            }

            // ---- O += Ph Vh + Ph Vl + Pl Vh ----
#pragma unroll
            for (int kk2 = 0; kk2 < 4; kk2++) {
                uint32_t aPh[4], aPl[4];
#pragma unroll
                for (int q = 0; q < 2; q++) {
                    const float* c = sf[kk2 * 2 + q];
                    float h0f = __bfloat162float(__float2bfloat16(c[0]));
                    float h1f = __bfloat162float(__float2bfloat16(c[1]));
                    float h2f = __bfloat162float(__float2bfloat16(c[2]));
                    float h3f = __bfloat162float(__float2bfloat16(c[3]));
                    aPh[q * 2]     = packbf(c[0], c[1]);
                    aPh[q * 2 + 1] = packbf(c[2], c[3]);
                    aPl[q * 2]     = packbf(c[0] - h0f, c[1] - h1f);
                    aPl[q * 2 + 1] = packbf(c[2] - h2f, c[3] - h3f);
                }
#pragma unroll
                for (int nf2 = 0; nf2 < 4; nf2++) {
                    uint32_t va = (kk2 * 16) * AT_STRIDE + vrowb + nf2 * 32;
                    uint32_t vH[4], vL[4];
                    ldsm_x4_t(vH, vbh + va);
                    ldsm_x4_t(vL, vbl + va);
                    mma16816(acc[nf2 * 2],     aPh, vH);
                    mma16816(acc[nf2 * 2 + 1], aPh, vH + 2);
                    mma16816(acc[nf2 * 2],     aPh, vL);
                    mma16816(acc[nf2 * 2 + 1], aPh, vL + 2);
                    mma16816(acc[nf2 * 2],     aPl, vH);
                    mma16816(acc[nf2 * 2 + 1], aPl, vH + 2);
                }
            }
            __syncthreads();    // all reads of buf done before next overwrite
            buf ^= 1;
        }

        // ---- epilogue: ctx -> bf16 hi/lo (B,S,D) ----
        float inv0 = 1.f / lrow[0], inv1 = 1.f / lrow[1];
        int r0 = qt * 64 + wid * 16 + (lid >> 2);
#pragma unroll
        for (int nf = 0; nf < 8; nf++) {
            int d0 = h * HD + nf * 8 + (lid & 3) * 2;
            size_t o0 = ((size_t)b * Ss + r0) * Dd + d0;
            size_t o1 = ((size_t)b * Ss + r0 + 8) * Dd + d0;
            float v0 = acc[nf][0] * inv0, v1 = acc[nf][1] * inv0;
            float v2 = acc[nf][2] * inv1, v3 = acc[nf][3] * inv1;
            __nv_bfloat16 h0, l0, h1, l1, h2, l2, h3, l3;
            split2(v0, h0, l0); split2(v1, h1, l1);
            split2(v2, h2, l2); split2(v3, h3, l3);
            *(__nv_bfloat162*)(g_ch + o0) = __nv_bfloat162(h0, h1);
            *(__nv_bfloat162*)(g_cl + o0) = __nv_bfloat162(l0, l1);
            *(__nv_bfloat162*)(g_ch + o1) = __nv_bfloat162(h2, h3);
            *(__nv_bfloat162*)(g_cl + o1) = __nv_bfloat162(l2, l3);
        }
    }
}

// ---------------------------------------------------------------------------
extern "C" void kernel_launch(void* const* d_in, const int* in_sizes, int n_in,
                              void* d_out, int out_size)
{
    const float* x  = (const float*)d_in[0];
    const float* Wq = (const float*)d_in[1];
    const float* bq = (const float*)d_in[2];
    const float* Wk = (const float*)d_in[3];
    const float* bk = (const float*)d_in[4];
    const float* Wv = (const float*)d_in[5];
    const float* bv = (const float*)d_in[6];
    const float* Wo = (const float*)d_in[7];
    const float* bo = (const float*)d_in[8];
    float* out = (float*)d_out;

    cudaFuncSetAttribute(gemm_qkv, cudaFuncAttributeMaxDynamicSharedMemorySize, GEMM_SMEM);
    cudaFuncSetAttribute(gemm_out, cudaFuncAttributeMaxDynamicSharedMemorySize, GEMM_SMEM);
    cudaFuncSetAttribute(attn_mma, cudaFuncAttributeMaxDynamicSharedMemorySize, ATTN_SMEM);

    split_all<<<(Mtot * Dd + 4 * Dd * Dd) / 1024, 256>>>(x, Wq, Wk, Wv, Wo);

    gemm_qkv<<<dim3(Dd / 128, Mtot / 128, 3), 256, GEMM_SMEM>>>(bq, bk, bv);

    attn_mma<<<dim3(16, Bb * Hh), 128, ATTN_SMEM>>>();

    gemm_out<<<dim3(Dd / 128, Mtot / 128), 256, GEMM_SMEM>>>(bo, out);
}

// round 6
// speedup vs baseline: 2.9329x; 1.0115x over previous
#include <cuda_runtime.h>
#include <cuda_bf16.h>
#include <cstdint>

#define Bb 2
#define Ss 2048
#define Dd 1024
#define Hh 16
#define HD 64
#define Mtot (Bb*Ss)   // 4096
#define QSCALE 0.1803368801111244f   // 0.125 * log2(e): softmax in exp2 domain

// ---------------- scratch (static device arrays; alloc APIs forbidden) -----
__device__ __align__(16) __nv_bfloat16 g_qh[Bb*Hh*Ss*HD];  // (B,H,S,hd) bf16 hi/lo
__device__ __align__(16) __nv_bfloat16 g_ql[Bb*Hh*Ss*HD];
__device__ __align__(16) __nv_bfloat16 g_kh[Bb*Hh*Ss*HD];
__device__ __align__(16) __nv_bfloat16 g_kl[Bb*Hh*Ss*HD];
__device__ __align__(16) __nv_bfloat16 g_vh[Bb*Hh*Ss*HD];
__device__ __align__(16) __nv_bfloat16 g_vl[Bb*Hh*Ss*HD];
__device__ __align__(16) __nv_bfloat16 g_xh[Mtot*Dd];      // x split hi/lo
__device__ __align__(16) __nv_bfloat16 g_xl[Mtot*Dd];
__device__ __align__(16) __nv_bfloat16 g_wh[4u*Dd*Dd];     // Wq,Wk,Wv,Wo hi
__device__ __align__(16) __nv_bfloat16 g_wl[4u*Dd*Dd];     // lo
__device__ __align__(16) __nv_bfloat16 g_ch[Mtot*Dd];      // ctx hi/lo (B,S,D)
__device__ __align__(16) __nv_bfloat16 g_cl[Mtot*Dd];

// ---------------- PTX helpers (sm_80/75-era only) --------------------------
__device__ __forceinline__ uint32_t smem_to_u32(const void* p) {
    uint32_t a;
    asm("{ .reg .u64 t; cvta.to.shared.u64 t, %1; cvt.u32.u64 %0, t; }"
        : "=r"(a) : "l"(p));
    return a;
}
__device__ __forceinline__ void cp_async16(uint32_t dst, const void* src) {
    asm volatile("cp.async.cg.shared.global [%0], [%1], 16;"
                 :: "r"(dst), "l"(src) : "memory");
}
__device__ __forceinline__ void cp_commit() {
    asm volatile("cp.async.commit_group;" ::: "memory");
}
template<int N> __device__ __forceinline__ void cp_wait() {
    asm volatile("cp.async.wait_group %0;" :: "n"(N) : "memory");
}
__device__ __forceinline__ void ldsm_x4(uint32_t* r, uint32_t addr) {
    asm volatile("ldmatrix.sync.aligned.m8n8.x4.shared.b16 {%0,%1,%2,%3}, [%4];"
                 : "=r"(r[0]), "=r"(r[1]), "=r"(r[2]), "=r"(r[3]) : "r"(addr));
}
__device__ __forceinline__ void ldsm_x4_t(uint32_t* r, uint32_t addr) {
    asm volatile("ldmatrix.sync.aligned.m8n8.x4.trans.shared.b16 {%0,%1,%2,%3}, [%4];"
                 : "=r"(r[0]), "=r"(r[1]), "=r"(r[2]), "=r"(r[3]) : "r"(addr));
}
__device__ __forceinline__ void mma16816(float* c, const uint32_t* a, const uint32_t* b) {
    asm volatile("mma.sync.aligned.m16n8k16.row.col.f32.bf16.bf16.f32 "
                 "{%0,%1,%2,%3}, {%4,%5,%6,%7}, {%8,%9}, {%0,%1,%2,%3};"
                 : "+f"(c[0]), "+f"(c[1]), "+f"(c[2]), "+f"(c[3])
                 : "r"(a[0]), "r"(a[1]), "r"(a[2]), "r"(a[3]), "r"(b[0]), "r"(b[1]));
}
__device__ __forceinline__ float ex2(float x) {
    float y;
    asm("ex2.approx.ftz.f32 %0, %1;" : "=f"(y) : "f"(x));
    return y;
}

// ---------------- fp32 -> bf16 hi/lo split ---------------------------------
__device__ __forceinline__ void split2(float v, __nv_bfloat16& h, __nv_bfloat16& l) {
    h = __float2bfloat16(v);
    l = __float2bfloat16(v - __bfloat162float(h));
}
__device__ __forceinline__ uint32_t packbf(float a, float b) {
    __nv_bfloat162 t(__float2bfloat16(a), __float2bfloat16(b));
    return *(uint32_t*)&t;
}

// One launch: split x (first 4M elems) and all 4 weights (next 4M).
__global__ __launch_bounds__(256)
void split_all(const float* __restrict__ x,  const float* __restrict__ Wq,
               const float* __restrict__ Wk, const float* __restrict__ Wv,
               const float* __restrict__ Wo)
{
    int i = (blockIdx.x * 256 + threadIdx.x) * 4;
    const float* src;
    __nv_bfloat16 *dh, *dl;
    if (i < Mtot * Dd) {
        src = x + i; dh = g_xh + i; dl = g_xl + i;
    } else {
        int j = i - Mtot * Dd;
        int w = j >> 20;                 // Dd*Dd = 2^20
        int r = j & (Dd * Dd - 1);
        src = (w == 0 ? Wq : w == 1 ? Wk : w == 2 ? Wv : Wo) + r;
        dh = g_wh + j; dl = g_wl + j;
    }
    float4 v = *(const float4*)src;
    __nv_bfloat16 h0, h1, h2, h3, l0, l1, l2, l3;
    split2(v.x, h0, l0); split2(v.y, h1, l1); split2(v.z, h2, l2); split2(v.w, h3, l3);
    *(__nv_bfloat162*)(dh)     = __nv_bfloat162(h0, h1);
    *(__nv_bfloat162*)(dh + 2) = __nv_bfloat162(h2, h3);
    *(__nv_bfloat162*)(dl)     = __nv_bfloat162(l0, l1);
    *(__nv_bfloat162*)(dl + 2) = __nv_bfloat162(l2, l3);
}

// ---------------------------------------------------------------------------
// mma.sync GEMM core constants (block 128x128, 8 warps, double-buffered,
// ONE __syncthreads per K-iteration).
// ---------------------------------------------------------------------------
#define TILE_B   10240                 // 128 * 80
#define BUF_B    (4 * TILE_B)
#define GEMM_SMEM (2 * BUF_B + 512)

// Fused QKV projection: gridDim.z selects Q/K/V.
__global__ __launch_bounds__(256)
void gemm_qkv(const float* __restrict__ bq, const float* __restrict__ bk,
              const float* __restrict__ bv)
{
    extern __shared__ char smem[];
    const uint32_t sb = smem_to_u32(smem);
    float* biasS = (float*)(smem + 2 * BUF_B);

    const int tid = threadIdx.x, wid = tid >> 5, lid = tid & 31;
    const int wm = wid >> 2, wn = wid & 3;
    const int m0 = blockIdx.y * 128, n0 = blockIdx.x * 128;
    const int z = blockIdx.z;

    const float* bias = (z == 0) ? bq : (z == 1) ? bk : bv;
    const __nv_bfloat16* Wh = g_wh + (size_t)z * Dd * Dd;
    const __nv_bfloat16* Wl = g_wl + (size_t)z * Dd * Dd;

    if (tid < 128) biasS[tid] = bias[n0 + tid];

    float acc[4][4][4];
#pragma unroll
    for (int i = 0; i < 4; i++)
#pragma unroll
        for (int j = 0; j < 4; j++)
#pragma unroll
            for (int k = 0; k < 4; k++) acc[i][j][k] = 0.f;

    auto issue = [&](int kt, int buf) {
        const int kc = kt * 32;
#pragma unroll
        for (int i = 0; i < 8; i++) {
            int idx = tid + i * 256;
            int tile = idx >> 9, w = idx & 511;
            int r = w >> 2, seg = (w & 3) * 16;
            uint32_t dst = sb + buf * BUF_B + tile * TILE_B + r * 80 + seg;
            const char* src;
            if (tile == 0)      src = (const char*)(g_xh + (size_t)(m0 + r) * Dd + kc) + seg;
            else if (tile == 1) src = (const char*)(g_xl + (size_t)(m0 + r) * Dd + kc) + seg;
            else if (tile == 2) src = (const char*)(Wh + (size_t)(n0 + r) * Dd + kc) + seg;
            else                src = (const char*)(Wl + (size_t)(n0 + r) * Dd + kc) + seg;
            cp_async16(dst, src);
        }
        cp_commit();
    };

    issue(0, 0);
    int buf = 0;
    const int arow0 = wm * 64 + (lid & 15);
    const int abyte0 = (lid >> 4) * 16;
    const int brow0 = wn * 32 + ((lid >> 4) << 3) + (lid & 7);
    const int bbyte0 = ((lid >> 3) & 1) * 16;

    for (int kt = 0; kt < 32; kt++) {
        cp_wait<0>();
        __syncthreads();               // data ready + prior reads of buf^1 done
        if (kt + 1 < 32) issue(kt + 1, buf ^ 1);

        const uint32_t tAh = sb + buf * BUF_B;
        const uint32_t tAl = tAh + TILE_B;
        const uint32_t tBh = tAh + 2 * TILE_B;
        const uint32_t tBl = tAh + 3 * TILE_B;

#pragma unroll
        for (int kk = 0; kk < 2; kk++) {
            uint32_t aH[4][4], aL[4][4], bH[4][2], bL[4][2];
            const int ab = kk * 32 + abyte0;
            const int bb = kk * 32 + bbyte0;
#pragma unroll
            for (int mf = 0; mf < 4; mf++) {
                uint32_t ro = (arow0 + mf * 16) * 80;
                ldsm_x4(aH[mf], tAh + ro + ab);
                ldsm_x4(aL[mf], tAl + ro + ab);
            }
#pragma unroll
            for (int nf2 = 0; nf2 < 2; nf2++) {
                uint32_t ro = (brow0 + nf2 * 16) * 80;
                uint32_t r4[4];
                ldsm_x4(r4, tBh + ro + bb);
                bH[nf2 * 2][0] = r4[0]; bH[nf2 * 2][1] = r4[1];
                bH[nf2 * 2 + 1][0] = r4[2]; bH[nf2 * 2 + 1][1] = r4[3];
                ldsm_x4(r4, tBl + ro + bb);
                bL[nf2 * 2][0] = r4[0]; bL[nf2 * 2][1] = r4[1];
                bL[nf2 * 2 + 1][0] = r4[2]; bL[nf2 * 2 + 1][1] = r4[3];
            }
#pragma unroll
            for (int mf = 0; mf < 4; mf++)
#pragma unroll
                for (int nf = 0; nf < 4; nf++) {
                    mma16816(acc[mf][nf], aH[mf], bH[nf]);
                    mma16816(acc[mf][nf], aH[mf], bL[nf]);
                    mma16816(acc[mf][nf], aL[mf], bH[nf]);
                }
        }
        buf ^= 1;
    }

    const float scale = (z == 0) ? QSCALE : 1.f;
    __nv_bfloat16* dh = (z == 0) ? g_qh : (z == 1) ? g_kh : g_vh;
    __nv_bfloat16* dl = (z == 0) ? g_ql : (z == 1) ? g_kl : g_vl;
#pragma unroll
    for (int mf = 0; mf < 4; mf++) {
#pragma unroll
        for (int nf = 0; nf < 4; nf++) {
            int nl = wn * 32 + nf * 8 + (lid & 3) * 2;
            int n = n0 + nl;
            float b0 = biasS[nl], b1 = biasS[nl + 1];
#pragma unroll
            for (int half = 0; half < 2; half++) {
                int m = m0 + wm * 64 + mf * 16 + (lid >> 2) + half * 8;
                float v0 = (acc[mf][nf][half * 2 + 0] + b0) * scale;
                float v1 = (acc[mf][nf][half * 2 + 1] + b1) * scale;
                __nv_bfloat16 h0, l0, h1, l1;
                split2(v0, h0, l0); split2(v1, h1, l1);
                int b = m >> 11, s = m & (Ss - 1);
                int hh = n >> 6, d = n & (HD - 1);
                size_t o = (((size_t)(b * Hh + hh)) * Ss + s) * HD + d;
                *(__nv_bfloat162*)(dh + o) = __nv_bfloat162(h0, h1);
                *(__nv_bfloat162*)(dl + o) = __nv_bfloat162(l0, l1);
            }
        }
    }
}

// Output GEMM: out = ctx @ Wo^T + bo, fp32 result.
__global__ __launch_bounds__(256)
void gemm_out(const float* __restrict__ bias, float* __restrict__ Cout)
{
    extern __shared__ char smem[];
    const uint32_t sb = smem_to_u32(smem);
    float* biasS = (float*)(smem + 2 * BUF_B);

    const int tid = threadIdx.x, wid = tid >> 5, lid = tid & 31;
    const int wm = wid >> 2, wn = wid & 3;
    const int m0 = blockIdx.y * 128, n0 = blockIdx.x * 128;

    const __nv_bfloat16* Wh = g_wh + (size_t)3 * Dd * Dd;
    const __nv_bfloat16* Wl = g_wl + (size_t)3 * Dd * Dd;

    if (tid < 128) biasS[tid] = bias[n0 + tid];

    float acc[4][4][4];
#pragma unroll
    for (int i = 0; i < 4; i++)
#pragma unroll
        for (int j = 0; j < 4; j++)
#pragma unroll
            for (int k = 0; k < 4; k++) acc[i][j][k] = 0.f;

    auto issue = [&](int kt, int buf) {
        const int kc = kt * 32;
#pragma unroll
        for (int i = 0; i < 8; i++) {
            int idx = tid + i * 256;
            int tile = idx >> 9, w = idx & 511;
            int r = w >> 2, seg = (w & 3) * 16;
            uint32_t dst = sb + buf * BUF_B + tile * TILE_B + r * 80 + seg;
            const char* src;
            if (tile == 0)      src = (const char*)(g_ch + (size_t)(m0 + r) * Dd + kc) + seg;
            else if (tile == 1) src = (const char*)(g_cl + (size_t)(m0 + r) * Dd + kc) + seg;
            else if (tile == 2) src = (const char*)(Wh + (size_t)(n0 + r) * Dd + kc) + seg;
            else                src = (const char*)(Wl + (size_t)(n0 + r) * Dd + kc) + seg;
            cp_async16(dst, src);
        }
        cp_commit();
    };

    issue(0, 0);
    int buf = 0;
    const int arow0 = wm * 64 + (lid & 15);
    const int abyte0 = (lid >> 4) * 16;
    const int brow0 = wn * 32 + ((lid >> 4) << 3) + (lid & 7);
    const int bbyte0 = ((lid >> 3) & 1) * 16;

    for (int kt = 0; kt < 32; kt++) {
        cp_wait<0>();
        __syncthreads();
        if (kt + 1 < 32) issue(kt + 1, buf ^ 1);

        const uint32_t tAh = sb + buf * BUF_B;
        const uint32_t tAl = tAh + TILE_B;
        const uint32_t tBh = tAh + 2 * TILE_B;
        const uint32_t tBl = tAh + 3 * TILE_B;

#pragma unroll
        for (int kk = 0; kk < 2; kk++) {
            uint32_t aH[4][4], aL[4][4], bH[4][2], bL[4][2];
            const int ab = kk * 32 + abyte0;
            const int bb = kk * 32 + bbyte0;
#pragma unroll
            for (int mf = 0; mf < 4; mf++) {
                uint32_t ro = (arow0 + mf * 16) * 80;
                ldsm_x4(aH[mf], tAh + ro + ab);
                ldsm_x4(aL[mf], tAl + ro + ab);
            }
#pragma unroll
            for (int nf2 = 0; nf2 < 2; nf2++) {
                uint32_t ro = (brow0 + nf2 * 16) * 80;
                uint32_t r4[4];
                ldsm_x4(r4, tBh + ro + bb);
                bH[nf2 * 2][0] = r4[0]; bH[nf2 * 2][1] = r4[1];
                bH[nf2 * 2 + 1][0] = r4[2]; bH[nf2 * 2 + 1][1] = r4[3];
                ldsm_x4(r4, tBl + ro + bb);
                bL[nf2 * 2][0] = r4[0]; bL[nf2 * 2][1] = r4[1];
                bL[nf2 * 2 + 1][0] = r4[2]; bL[nf2 * 2 + 1][1] = r4[3];
            }
#pragma unroll
            for (int mf = 0; mf < 4; mf++)
#pragma unroll
                for (int nf = 0; nf < 4; nf++) {
                    mma16816(acc[mf][nf], aH[mf], bH[nf]);
                    mma16816(acc[mf][nf], aH[mf], bL[nf]);
                    mma16816(acc[mf][nf], aL[mf], bH[nf]);
                }
        }
        buf ^= 1;
    }

#pragma unroll
    for (int mf = 0; mf < 4; mf++) {
#pragma unroll
        for (int nf = 0; nf < 4; nf++) {
            int nl = wn * 32 + nf * 8 + (lid & 3) * 2;
            int n = n0 + nl;
            float b0 = biasS[nl], b1 = biasS[nl + 1];
#pragma unroll
            for (int half = 0; half < 2; half++) {
                int m = m0 + wm * 64 + mf * 16 + (lid >> 2) + half * 8;
                *(float2*)(Cout + (size_t)m * Dd + n) =
                    make_float2(acc[mf][nf][half * 2 + 0] + b0,
                                acc[mf][nf][half * 2 + 1] + b1);
            }
        }
    }
}

// ---------------------------------------------------------------------------
// Tensor-core causal flash attention, bf16 3-term split, exp2-domain softmax.
// q-tile = 128 rows, 256 threads / 8 warps (warp w owns rows w*16..w*16+15).
// KV tiles (64 rows) double-buffered; ONE barrier per k-tile. CTA processes
// paired q-tiles (pr, 15-pr) -> uniform 34 k-tiles per CTA.
// ---------------------------------------------------------------------------
#define AT_STRIDE 144
#define QT_B     (128 * AT_STRIDE)           // 18432
#define KV_TILE  (64 * AT_STRIDE)            // 9216
#define KV0      (2 * QT_B)                  // 36864
#define KV_STAGE (4 * KV_TILE)               // 36864
#define ATTN_SMEM (KV0 + 2 * KV_STAGE)       // 110592

__global__ __launch_bounds__(256)
void attn_mma()
{
    extern __shared__ char smem[];
    const uint32_t sb = smem_to_u32(smem);
    const int pr = blockIdx.x;                 // pair index 0..7
    const int bh = blockIdx.y;
    const int b = bh >> 4, h = bh & 15;
    const int tid = threadIdx.x, wid = tid >> 5, lid = tid & 31;

    const __nv_bfloat16* bases[4] = {
        g_kh + (size_t)bh * Ss * HD, g_kl + (size_t)bh * Ss * HD,
        g_vh + (size_t)bh * Ss * HD, g_vl + (size_t)bh * Ss * HD };

    auto issue = [&](int kt, int bf) {
#pragma unroll
        for (int i = 0; i < 8; i++) {
            int idx = tid + i * 256;
            int t = idx >> 9, w = idx & 511;
            int r = w >> 3, c = w & 7;
            cp_async16(sb + KV0 + bf * KV_STAGE + t * KV_TILE + r * AT_STRIDE + c * 16,
                       bases[t] + (size_t)(kt * 64 + r) * HD + c * 8);
        }
        cp_commit();
    };

    const uint32_t qrowb = (wid * 16 + (lid & 15)) * AT_STRIDE + (lid >> 4) * 16;
    const uint32_t krowb = (((lid >> 4) << 3) + (lid & 7)) * AT_STRIDE + ((lid >> 3) & 1) * 16;
    const uint32_t vrowb = (lid & 15) * AT_STRIDE + ((lid >> 4) & 1) * 16;
    int buf = 0;

    for (int half_t = 0; half_t < 2; half_t++) {
        const int qt = half_t ? (15 - pr) : pr;       // q-tile of 128 rows
        const __nv_bfloat16* QH = g_qh + ((size_t)bh * Ss + qt * 128) * HD;
        const __nv_bfloat16* QL = g_ql + ((size_t)bh * Ss + qt * 128) * HD;

        // Q tile (Qh, Ql): 128 rows x 128B each
#pragma unroll
        for (int i = 0; i < 8; i++) {
            int idx = tid + i * 256;
            int s = idx >> 10, w = idx & 1023;
            int r = w >> 3, c = w & 7;
            cp_async16(sb + s * QT_B + r * AT_STRIDE + c * 16,
                       (s ? QL : QH) + (size_t)r * HD + c * 8);
        }
        cp_commit();
        issue(0, buf);

        float acc[8][4];
#pragma unroll
        for (int i = 0; i < 8; i++)
#pragma unroll
            for (int j = 0; j < 4; j++) acc[i][j] = 0.f;
        float mrow[2] = { -1e30f, -1e30f }, lrow[2] = { 0.f, 0.f };

        const int nk = 2 * qt + 2;
        for (int kt = 0; kt < nk; kt++) {
            cp_wait<0>();
            __syncthreads();          // data ready + prior reads of buf^1 done
            if (kt + 1 < nk) issue(kt + 1, buf ^ 1);

            const uint32_t kbh = sb + KV0 + buf * KV_STAGE;
            const uint32_t kbl = kbh + KV_TILE;
            const uint32_t vbh = kbh + 2 * KV_TILE;
            const uint32_t vbl = kbh + 3 * KV_TILE;

            // ---- S = Qh Kh^T + Qh Kl^T + Ql Kh^T (log2-scaled) ----
            float sf[8][4];
#pragma unroll
            for (int i = 0; i < 8; i++)
#pragma unroll
                for (int j = 0; j < 4; j++) sf[i][j] = 0.f;

#pragma unroll
            for (int kk = 0; kk < 4; kk++) {
                uint32_t aH[4], aL[4];
                ldsm_x4(aH, sb + qrowb + kk * 32);
                ldsm_x4(aL, sb + QT_B + qrowb + kk * 32);
#pragma unroll
                for (int nf2 = 0; nf2 < 4; nf2++) {
                    uint32_t ba = nf2 * 16 * AT_STRIDE + krowb + kk * 32;
                    uint32_t rH[4], rL[4];
                    ldsm_x4(rH, kbh + ba);
                    ldsm_x4(rL, kbl + ba);
                    mma16816(sf[nf2 * 2],     aH, rH);
                    mma16816(sf[nf2 * 2 + 1], aH, rH + 2);
                    mma16816(sf[nf2 * 2],     aH, rL);
                    mma16816(sf[nf2 * 2 + 1], aH, rL + 2);
                    mma16816(sf[nf2 * 2],     aL, rH);
                    mma16816(sf[nf2 * 2 + 1], aL, rH + 2);
                }
            }

            if (kt >= 2 * qt) {     // diagonal region: causal mask
                int r0 = wid * 16 + (lid >> 2);
                int coff = kt * 64 - qt * 128;
#pragma unroll
                for (int nf = 0; nf < 8; nf++) {
                    int c0 = coff + nf * 8 + (lid & 3) * 2;
                    if (c0     > r0)     sf[nf][0] = -1e30f;
                    if (c0 + 1 > r0)     sf[nf][1] = -1e30f;
                    if (c0     > r0 + 8) sf[nf][2] = -1e30f;
                    if (c0 + 1 > r0 + 8) sf[nf][3] = -1e30f;
                }
            }

            // ---- online softmax in exp2 domain ----
#pragma unroll
            for (int hf = 0; hf < 2; hf++) {
                float mx = -1e30f;
#pragma unroll
                for (int nf = 0; nf < 8; nf++)
                    mx = fmaxf(mx, fmaxf(sf[nf][hf * 2], sf[nf][hf * 2 + 1]));
                mx = fmaxf(mx, __shfl_xor_sync(0xffffffffu, mx, 1));
                mx = fmaxf(mx, __shfl_xor_sync(0xffffffffu, mx, 2));
                float mnew = fmaxf(mrow[hf], mx);
                float alpha = ex2(mrow[hf] - mnew);
                mrow[hf] = mnew;
                float sum = 0.f;
#pragma unroll
                for (int nf = 0; nf < 8; nf++) {
                    sf[nf][hf * 2]     = ex2(sf[nf][hf * 2] - mnew);
                    sf[nf][hf * 2 + 1] = ex2(sf[nf][hf * 2 + 1] - mnew);
                    sum += sf[nf][hf * 2] + sf[nf][hf * 2 + 1];
                }
                sum += __shfl_xor_sync(0xffffffffu, sum, 1);
                sum += __shfl_xor_sync(0xffffffffu, sum, 2);
                lrow[hf] = lrow[hf] * alpha + sum;
#pragma unroll
                for (int nf = 0; nf < 8; nf++) {
                    acc[nf][hf * 2]     *= alpha;
                    acc[nf][hf * 2 + 1] *= alpha;
                }
            }

            // ---- O += Ph Vh + Ph Vl + Pl Vh ----
#pragma unroll
            for (int kk2 = 0; kk2 < 4; kk2++) {
                uint32_t aPh[4], aPl[4];
#pragma unroll
                for (int q = 0; q < 2; q++) {
                    const float* c = sf[kk2 * 2 + q];
                    float h0f = __bfloat162float(__float2bfloat16(c[0]));
                    float h1f = __bfloat162float(__float2bfloat16(c[1]));
                    float h2f = __bfloat162float(__float2bfloat16(c[2]));
                    float h3f = __bfloat162float(__float2bfloat16(c[3]));
                    aPh[q * 2]     = packbf(c[0], c[1]);
                    aPh[q * 2 + 1] = packbf(c[2], c[3]);
                    aPl[q * 2]     = packbf(c[0] - h0f, c[1] - h1f);
                    aPl[q * 2 + 1] = packbf(c[2] - h2f, c[3] - h3f);
                }
#pragma unroll
                for (int nf2 = 0; nf2 < 4; nf2++) {
                    uint32_t va = (kk2 * 16) * AT_STRIDE + vrowb + nf2 * 32;
                    uint32_t vH[4], vL[4];
                    ldsm_x4_t(vH, vbh + va);
                    ldsm_x4_t(vL, vbl + va);
                    mma16816(acc[nf2 * 2],     aPh, vH);
                    mma16816(acc[nf2 * 2 + 1], aPh, vH + 2);
                    mma16816(acc[nf2 * 2],     aPh, vL);
                    mma16816(acc[nf2 * 2 + 1], aPh, vL + 2);
                    mma16816(acc[nf2 * 2],     aPl, vH);
                    mma16816(acc[nf2 * 2 + 1], aPl, vH + 2);
                }
            }
            buf ^= 1;
        }

        // ---- epilogue: ctx -> bf16 hi/lo (B,S,D) ----
        float inv0 = 1.f / lrow[0], inv1 = 1.f / lrow[1];
        int r0 = qt * 128 + wid * 16 + (lid >> 2);
#pragma unroll
        for (int nf = 0; nf < 8; nf++) {
            int d0 = h * HD + nf * 8 + (lid & 3) * 2;
            size_t o0 = ((size_t)b * Ss + r0) * Dd + d0;
            size_t o1 = ((size_t)b * Ss + r0 + 8) * Dd + d0;
            float v0 = acc[nf][0] * inv0, v1 = acc[nf][1] * inv0;
            float v2 = acc[nf][2] * inv1, v3 = acc[nf][3] * inv1;
            __nv_bfloat16 h0, l0, h1, l1, h2, l2, h3, l3;
            split2(v0, h0, l0); split2(v1, h1, l1);
            split2(v2, h2, l2); split2(v3, h3, l3);
            *(__nv_bfloat162*)(g_ch + o0) = __nv_bfloat162(h0, h1);
            *(__nv_bfloat162*)(g_cl + o0) = __nv_bfloat162(l0, l1);
            *(__nv_bfloat162*)(g_ch + o1) = __nv_bfloat162(h2, h3);
            *(__nv_bfloat162*)(g_cl + o1) = __nv_bfloat162(l2, l3);
        }
        __syncthreads();    // Q/KV smem reuse safe before next half's loads
    }
}

// ---------------------------------------------------------------------------
extern "C" void kernel_launch(void* const* d_in, const int* in_sizes, int n_in,
                              void* d_out, int out_size)
{
    const float* x  = (const float*)d_in[0];
    const float* Wq = (const float*)d_in[1];
    const float* bq = (const float*)d_in[2];
    const float* Wk = (const float*)d_in[3];
    const float* bk = (const float*)d_in[4];
    const float* Wv = (const float*)d_in[5];
    const float* bv = (const float*)d_in[6];
    const float* Wo = (const float*)d_in[7];
    const float* bo = (const float*)d_in[8];
    float* out = (float*)d_out;

    cudaFuncSetAttribute(gemm_qkv, cudaFuncAttributeMaxDynamicSharedMemorySize, GEMM_SMEM);
    cudaFuncSetAttribute(gemm_out, cudaFuncAttributeMaxDynamicSharedMemorySize, GEMM_SMEM);
    cudaFuncSetAttribute(attn_mma, cudaFuncAttributeMaxDynamicSharedMemorySize, ATTN_SMEM);

    split_all<<<(Mtot * Dd + 4 * Dd * Dd) / 1024, 256>>>(x, Wq, Wk, Wv, Wo);

    gemm_qkv<<<dim3(Dd / 128, Mtot / 128, 3), 256, GEMM_SMEM>>>(bq, bk, bv);

    attn_mma<<<dim3(8, Bb * Hh), 256, ATTN_SMEM>>>();

    gemm_out<<<dim3(Dd / 128, Mtot / 128), 256, GEMM_SMEM>>>(bo, out);
}

// round 7
// speedup vs baseline: 2.9747x; 1.0143x over previous
#include <cuda_runtime.h>
#include <cuda_bf16.h>
#include <cstdint>

#define Bb 2
#define Ss 2048
#define Dd 1024
#define Hh 16
#define HD 64
#define Mtot (Bb*Ss)   // 4096
#define QSCALE 0.1803368801111244f   // 0.125 * log2(e): softmax in exp2 domain

// ---------------- scratch (static device arrays; alloc APIs forbidden) -----
__device__ __align__(16) __nv_bfloat16 g_qh[Bb*Hh*Ss*HD];  // (B,H,S,hd) bf16 hi/lo
__device__ __align__(16) __nv_bfloat16 g_ql[Bb*Hh*Ss*HD];
__device__ __align__(16) __nv_bfloat16 g_kh[Bb*Hh*Ss*HD];
__device__ __align__(16) __nv_bfloat16 g_kl[Bb*Hh*Ss*HD];
__device__ __align__(16) __nv_bfloat16 g_vh[Bb*Hh*Ss*HD];
__device__ __align__(16) __nv_bfloat16 g_vl[Bb*Hh*Ss*HD];
__device__ __align__(16) __nv_bfloat16 g_xh[Mtot*Dd];      // x split hi/lo
__device__ __align__(16) __nv_bfloat16 g_xl[Mtot*Dd];
__device__ __align__(16) __nv_bfloat16 g_wh[4u*Dd*Dd];     // Wq,Wk,Wv,Wo hi
__device__ __align__(16) __nv_bfloat16 g_wl[4u*Dd*Dd];     // lo
__device__ __align__(16) __nv_bfloat16 g_ch[Mtot*Dd];      // ctx hi/lo (B,S,D)
__device__ __align__(16) __nv_bfloat16 g_cl[Mtot*Dd];

// ---------------- PTX helpers (sm_80/75-era only) --------------------------
__device__ __forceinline__ uint32_t smem_to_u32(const void* p) {
    uint32_t a;
    asm("{ .reg .u64 t; cvta.to.shared.u64 t, %1; cvt.u32.u64 %0, t; }"
        : "=r"(a) : "l"(p));
    return a;
}
__device__ __forceinline__ void cp_async16(uint32_t dst, const void* src) {
    asm volatile("cp.async.cg.shared.global [%0], [%1], 16;"
                 :: "r"(dst), "l"(src) : "memory");
}
__device__ __forceinline__ void cp_commit() {
    asm volatile("cp.async.commit_group;" ::: "memory");
}
template<int N> __device__ __forceinline__ void cp_wait() {
    asm volatile("cp.async.wait_group %0;" :: "n"(N) : "memory");
}
__device__ __forceinline__ void ldsm_x4(uint32_t* r, uint32_t addr) {
    asm volatile("ldmatrix.sync.aligned.m8n8.x4.shared.b16 {%0,%1,%2,%3}, [%4];"
                 : "=r"(r[0]), "=r"(r[1]), "=r"(r[2]), "=r"(r[3]) : "r"(addr));
}
__device__ __forceinline__ void ldsm_x4_t(uint32_t* r, uint32_t addr) {
    asm volatile("ldmatrix.sync.aligned.m8n8.x4.trans.shared.b16 {%0,%1,%2,%3}, [%4];"
                 : "=r"(r[0]), "=r"(r[1]), "=r"(r[2]), "=r"(r[3]) : "r"(addr));
}
__device__ __forceinline__ void mma16816(float* c, const uint32_t* a, const uint32_t* b) {
    asm volatile("mma.sync.aligned.m16n8k16.row.col.f32.bf16.bf16.f32 "
                 "{%0,%1,%2,%3}, {%4,%5,%6,%7}, {%8,%9}, {%0,%1,%2,%3};"
                 : "+f"(c[0]), "+f"(c[1]), "+f"(c[2]), "+f"(c[3])
                 : "r"(a[0]), "r"(a[1]), "r"(a[2]), "r"(a[3]), "r"(b[0]), "r"(b[1]));
}
__device__ __forceinline__ float ex2(float x) {
    float y;
    asm("ex2.approx.ftz.f32 %0, %1;" : "=f"(y) : "f"(x));
    return y;
}

// ---------------- fp32 -> bf16 hi/lo split ---------------------------------
__device__ __forceinline__ void split2(float v, __nv_bfloat16& h, __nv_bfloat16& l) {
    h = __float2bfloat16(v);
    l = __float2bfloat16(v - __bfloat162float(h));
}
__device__ __forceinline__ uint32_t packbf(float a, float b) {
    __nv_bfloat162 t(__float2bfloat16(a), __float2bfloat16(b));
    return *(uint32_t*)&t;
}

// One launch: split x (first 4M elems) and all 4 weights (next 4M).
__global__ __launch_bounds__(256)
void split_all(const float* __restrict__ x,  const float* __restrict__ Wq,
               const float* __restrict__ Wk, const float* __restrict__ Wv,
               const float* __restrict__ Wo)
{
    int i = (blockIdx.x * 256 + threadIdx.x) * 4;
    const float* src;
    __nv_bfloat16 *dh, *dl;
    if (i < Mtot * Dd) {
        src = x + i; dh = g_xh + i; dl = g_xl + i;
    } else {
        int j = i - Mtot * Dd;
        int w = j >> 20;                 // Dd*Dd = 2^20
        int r = j & (Dd * Dd - 1);
        src = (w == 0 ? Wq : w == 1 ? Wk : w == 2 ? Wv : Wo) + r;
        dh = g_wh + j; dl = g_wl + j;
    }
    float4 v = *(const float4*)src;
    __nv_bfloat16 h0, h1, h2, h3, l0, l1, l2, l3;
    split2(v.x, h0, l0); split2(v.y, h1, l1); split2(v.z, h2, l2); split2(v.w, h3, l3);
    *(__nv_bfloat162*)(dh)     = __nv_bfloat162(h0, h1);
    *(__nv_bfloat162*)(dh + 2) = __nv_bfloat162(h2, h3);
    *(__nv_bfloat162*)(dl)     = __nv_bfloat162(l0, l1);
    *(__nv_bfloat162*)(dl + 2) = __nv_bfloat162(l2, l3);
}

// ---------------------------------------------------------------------------
// mma.sync GEMM core (block 128x128, 8 warps, double-buffered, one barrier
// per K-iter, TERM-OUTERMOST MMA ordering: RAW distance 16).
// ---------------------------------------------------------------------------
#define TILE_B   10240                 // 128 * 80
#define BUF_B    (4 * TILE_B)
#define GEMM_SMEM (2 * BUF_B + 512)

// Fused QKV projection: gridDim.z selects Q/K/V.
__global__ __launch_bounds__(256)
void gemm_qkv(const float* __restrict__ bq, const float* __restrict__ bk,
              const float* __restrict__ bv)
{
    extern __shared__ char smem[];
    const uint32_t sb = smem_to_u32(smem);
    float* biasS = (float*)(smem + 2 * BUF_B);

    const int tid = threadIdx.x, wid = tid >> 5, lid = tid & 31;
    const int wm = wid >> 2, wn = wid & 3;
    const int m0 = blockIdx.y * 128, n0 = blockIdx.x * 128;
    const int z = blockIdx.z;

    const float* bias = (z == 0) ? bq : (z == 1) ? bk : bv;
    const __nv_bfloat16* Wh = g_wh + (size_t)z * Dd * Dd;
    const __nv_bfloat16* Wl = g_wl + (size_t)z * Dd * Dd;

    if (tid < 128) biasS[tid] = bias[n0 + tid];

    float acc[4][4][4];
#pragma unroll
    for (int i = 0; i < 4; i++)
#pragma unroll
        for (int j = 0; j < 4; j++)
#pragma unroll
            for (int k = 0; k < 4; k++) acc[i][j][k] = 0.f;

    auto issue = [&](int kt, int buf) {
        const int kc = kt * 32;
#pragma unroll
        for (int i = 0; i < 8; i++) {
            int idx = tid + i * 256;
            int tile = idx >> 9, w = idx & 511;
            int r = w >> 2, seg = (w & 3) * 16;
            uint32_t dst = sb + buf * BUF_B + tile * TILE_B + r * 80 + seg;
            const char* src;
            if (tile == 0)      src = (const char*)(g_xh + (size_t)(m0 + r) * Dd + kc) + seg;
            else if (tile == 1) src = (const char*)(g_xl + (size_t)(m0 + r) * Dd + kc) + seg;
            else if (tile == 2) src = (const char*)(Wh + (size_t)(n0 + r) * Dd + kc) + seg;
            else                src = (const char*)(Wl + (size_t)(n0 + r) * Dd + kc) + seg;
            cp_async16(dst, src);
        }
        cp_commit();
    };

    issue(0, 0);
    int buf = 0;
    const int arow0 = wm * 64 + (lid & 15);
    const int abyte0 = (lid >> 4) * 16;
    const int brow0 = wn * 32 + ((lid >> 4) << 3) + (lid & 7);
    const int bbyte0 = ((lid >> 3) & 1) * 16;

    for (int kt = 0; kt < 32; kt++) {
        cp_wait<0>();
        __syncthreads();               // data ready + prior reads of buf^1 done
        if (kt + 1 < 32) issue(kt + 1, buf ^ 1);

        const uint32_t tAh = sb + buf * BUF_B;
        const uint32_t tAl = tAh + TILE_B;
        const uint32_t tBh = tAh + 2 * TILE_B;
        const uint32_t tBl = tAh + 3 * TILE_B;

#pragma unroll
        for (int kk = 0; kk < 2; kk++) {
            uint32_t aH[4][4], aL[4][4], bH[4][2], bL[4][2];
            const int ab = kk * 32 + abyte0;
            const int bb = kk * 32 + bbyte0;
#pragma unroll
            for (int mf = 0; mf < 4; mf++) {
                uint32_t ro = (arow0 + mf * 16) * 80;
                ldsm_x4(aH[mf], tAh + ro + ab);
                ldsm_x4(aL[mf], tAl + ro + ab);
            }
#pragma unroll
            for (int nf2 = 0; nf2 < 2; nf2++) {
                uint32_t ro = (brow0 + nf2 * 16) * 80;
                uint32_t r4[4];
                ldsm_x4(r4, tBh + ro + bb);
                bH[nf2 * 2][0] = r4[0]; bH[nf2 * 2][1] = r4[1];
                bH[nf2 * 2 + 1][0] = r4[2]; bH[nf2 * 2 + 1][1] = r4[3];
                ldsm_x4(r4, tBl + ro + bb);
                bL[nf2 * 2][0] = r4[0]; bL[nf2 * 2][1] = r4[1];
                bL[nf2 * 2 + 1][0] = r4[2]; bL[nf2 * 2 + 1][1] = r4[3];
            }
            // term-outermost: all HH, then all HL, then all LH (RAW dist 16)
#pragma unroll
            for (int mf = 0; mf < 4; mf++)
#pragma unroll
                for (int nf = 0; nf < 4; nf++)
                    mma16816(acc[mf][nf], aH[mf], bH[nf]);
#pragma unroll
            for (int mf = 0; mf < 4; mf++)
#pragma unroll
                for (int nf = 0; nf < 4; nf++)
                    mma16816(acc[mf][nf], aH[mf], bL[nf]);
#pragma unroll
            for (int mf = 0; mf < 4; mf++)
#pragma unroll
                for (int nf = 0; nf < 4; nf++)
                    mma16816(acc[mf][nf], aL[mf], bH[nf]);
        }
        buf ^= 1;
    }

    const float scale = (z == 0) ? QSCALE : 1.f;
    __nv_bfloat16* dh = (z == 0) ? g_qh : (z == 1) ? g_kh : g_vh;
    __nv_bfloat16* dl = (z == 0) ? g_ql : (z == 1) ? g_kl : g_vl;
#pragma unroll
    for (int mf = 0; mf < 4; mf++) {
#pragma unroll
        for (int nf = 0; nf < 4; nf++) {
            int nl = wn * 32 + nf * 8 + (lid & 3) * 2;
            int n = n0 + nl;
            float b0 = biasS[nl], b1 = biasS[nl + 1];
#pragma unroll
            for (int half = 0; half < 2; half++) {
                int m = m0 + wm * 64 + mf * 16 + (lid >> 2) + half * 8;
                float v0 = (acc[mf][nf][half * 2 + 0] + b0) * scale;
                float v1 = (acc[mf][nf][half * 2 + 1] + b1) * scale;
                __nv_bfloat16 h0, l0, h1, l1;
                split2(v0, h0, l0); split2(v1, h1, l1);
                int b = m >> 11, s = m & (Ss - 1);
                int hh = n >> 6, d = n & (HD - 1);
                size_t o = (((size_t)(b * Hh + hh)) * Ss + s) * HD + d;
                *(__nv_bfloat162*)(dh + o) = __nv_bfloat162(h0, h1);
                *(__nv_bfloat162*)(dl + o) = __nv_bfloat162(l0, l1);
            }
        }
    }
}

// Output GEMM: out = ctx @ Wo^T + bo, fp32 result.
__global__ __launch_bounds__(256)
void gemm_out(const float* __restrict__ bias, float* __restrict__ Cout)
{
    extern __shared__ char smem[];
    const uint32_t sb = smem_to_u32(smem);
    float* biasS = (float*)(smem + 2 * BUF_B);

    const int tid = threadIdx.x, wid = tid >> 5, lid = tid & 31;
    const int wm = wid >> 2, wn = wid & 3;
    const int m0 = blockIdx.y * 128, n0 = blockIdx.x * 128;

    const __nv_bfloat16* Wh = g_wh + (size_t)3 * Dd * Dd;
    const __nv_bfloat16* Wl = g_wl + (size_t)3 * Dd * Dd;

    if (tid < 128) biasS[tid] = bias[n0 + tid];

    float acc[4][4][4];
#pragma unroll
    for (int i = 0; i < 4; i++)
#pragma unroll
        for (int j = 0; j < 4; j++)
#pragma unroll
            for (int k = 0; k < 4; k++) acc[i][j][k] = 0.f;

    auto issue = [&](int kt, int buf) {
        const int kc = kt * 32;
#pragma unroll
        for (int i = 0; i < 8; i++) {
            int idx = tid + i * 256;
            int tile = idx >> 9, w = idx & 511;
            int r = w >> 2, seg = (w & 3) * 16;
            uint32_t dst = sb + buf * BUF_B + tile * TILE_B + r * 80 + seg;
            const char* src;
            if (tile == 0)      src = (const char*)(g_ch + (size_t)(m0 + r) * Dd + kc) + seg;
            else if (tile == 1) src = (const char*)(g_cl + (size_t)(m0 + r) * Dd + kc) + seg;
            else if (tile == 2) src = (const char*)(Wh + (size_t)(n0 + r) * Dd + kc) + seg;
            else                src = (const char*)(Wl + (size_t)(n0 + r) * Dd + kc) + seg;
            cp_async16(dst, src);
        }
        cp_commit();
    };

    issue(0, 0);
    int buf = 0;
    const int arow0 = wm * 64 + (lid & 15);
    const int abyte0 = (lid >> 4) * 16;
    const int brow0 = wn * 32 + ((lid >> 4) << 3) + (lid & 7);
    const int bbyte0 = ((lid >> 3) & 1) * 16;

    for (int kt = 0; kt < 32; kt++) {
        cp_wait<0>();
        __syncthreads();
        if (kt + 1 < 32) issue(kt + 1, buf ^ 1);

        const uint32_t tAh = sb + buf * BUF_B;
        const uint32_t tAl = tAh + TILE_B;
        const uint32_t tBh = tAh + 2 * TILE_B;
        const uint32_t tBl = tAh + 3 * TILE_B;

#pragma unroll
        for (int kk = 0; kk < 2; kk++) {
            uint32_t aH[4][4], aL[4][4], bH[4][2], bL[4][2];
            const int ab = kk * 32 + abyte0;
            const int bb = kk * 32 + bbyte0;
#pragma unroll
            for (int mf = 0; mf < 4; mf++) {
                uint32_t ro = (arow0 + mf * 16) * 80;
                ldsm_x4(aH[mf], tAh + ro + ab);
                ldsm_x4(aL[mf], tAl + ro + ab);
            }
#pragma unroll
            for (int nf2 = 0; nf2 < 2; nf2++) {
                uint32_t ro = (brow0 + nf2 * 16) * 80;
                uint32_t r4[4];
                ldsm_x4(r4, tBh + ro + bb);
                bH[nf2 * 2][0] = r4[0]; bH[nf2 * 2][1] = r4[1];
                bH[nf2 * 2 + 1][0] = r4[2]; bH[nf2 * 2 + 1][1] = r4[3];
                ldsm_x4(r4, tBl + ro + bb);
                bL[nf2 * 2][0] = r4[0]; bL[nf2 * 2][1] = r4[1];
                bL[nf2 * 2 + 1][0] = r4[2]; bL[nf2 * 2 + 1][1] = r4[3];
            }
#pragma unroll
            for (int mf = 0; mf < 4; mf++)
#pragma unroll
                for (int nf = 0; nf < 4; nf++)
                    mma16816(acc[mf][nf], aH[mf], bH[nf]);
#pragma unroll
            for (int mf = 0; mf < 4; mf++)
#pragma unroll
                for (int nf = 0; nf < 4; nf++)
                    mma16816(acc[mf][nf], aH[mf], bL[nf]);
#pragma unroll
            for (int mf = 0; mf < 4; mf++)
#pragma unroll
                for (int nf = 0; nf < 4; nf++)
                    mma16816(acc[mf][nf], aL[mf], bH[nf]);
        }
        buf ^= 1;
    }

#pragma unroll
    for (int mf = 0; mf < 4; mf++) {
#pragma unroll
        for (int nf = 0; nf < 4; nf++) {
            int nl = wn * 32 + nf * 8 + (lid & 3) * 2;
            int n = n0 + nl;
            float b0 = biasS[nl], b1 = biasS[nl + 1];
#pragma unroll
            for (int half = 0; half < 2; half++) {
                int m = m0 + wm * 64 + mf * 16 + (lid >> 2) + half * 8;
                *(float2*)(Cout + (size_t)m * Dd + n) =
                    make_float2(acc[mf][nf][half * 2 + 0] + b0,
                                acc[mf][nf][half * 2 + 1] + b1);
            }
        }
    }
}

// ---------------------------------------------------------------------------
// Tensor-core causal flash attention. q-tile 128 rows, 256 threads / 8 warps.
// MMA blocks use nf2-paired, term-separated issue (RAW distance 4).
// ---------------------------------------------------------------------------
#define AT_STRIDE 144
#define QT_B     (128 * AT_STRIDE)           // 18432
#define KV_TILE  (64 * AT_STRIDE)            // 9216
#define KV0      (2 * QT_B)                  // 36864
#define KV_STAGE (4 * KV_TILE)               // 36864
#define ATTN_SMEM (KV0 + 2 * KV_STAGE)       // 110592

__global__ __launch_bounds__(256)
void attn_mma()
{
    extern __shared__ char smem[];
    const uint32_t sb = smem_to_u32(smem);
    const int pr = blockIdx.x;                 // pair index 0..7
    const int bh = blockIdx.y;
    const int b = bh >> 4, h = bh & 15;
    const int tid = threadIdx.x, wid = tid >> 5, lid = tid & 31;

    const __nv_bfloat16* bases[4] = {
        g_kh + (size_t)bh * Ss * HD, g_kl + (size_t)bh * Ss * HD,
        g_vh + (size_t)bh * Ss * HD, g_vl + (size_t)bh * Ss * HD };

    auto issue = [&](int kt, int bf) {
#pragma unroll
        for (int i = 0; i < 8; i++) {
            int idx = tid + i * 256;
            int t = idx >> 9, w = idx & 511;
            int r = w >> 3, c = w & 7;
            cp_async16(sb + KV0 + bf * KV_STAGE + t * KV_TILE + r * AT_STRIDE + c * 16,
                       bases[t] + (size_t)(kt * 64 + r) * HD + c * 8);
        }
        cp_commit();
    };

    const uint32_t qrowb = (wid * 16 + (lid & 15)) * AT_STRIDE + (lid >> 4) * 16;
    const uint32_t krowb = (((lid >> 4) << 3) + (lid & 7)) * AT_STRIDE + ((lid >> 3) & 1) * 16;
    const uint32_t vrowb = (lid & 15) * AT_STRIDE + ((lid >> 4) & 1) * 16;
    int buf = 0;

    for (int half_t = 0; half_t < 2; half_t++) {
        const int qt = half_t ? (15 - pr) : pr;       // q-tile of 128 rows
        const __nv_bfloat16* QH = g_qh + ((size_t)bh * Ss + qt * 128) * HD;
        const __nv_bfloat16* QL = g_ql + ((size_t)bh * Ss + qt * 128) * HD;

        // Q tile (Qh, Ql): 128 rows x 128B each
#pragma unroll
        for (int i = 0; i < 8; i++) {
            int idx = tid + i * 256;
            int s = idx >> 10, w = idx & 1023;
            int r = w >> 3, c = w & 7;
            cp_async16(sb + s * QT_B + r * AT_STRIDE + c * 16,
                       (s ? QL : QH) + (size_t)r * HD + c * 8);
        }
        cp_commit();
        issue(0, buf);

        float acc[8][4];
#pragma unroll
        for (int i = 0; i < 8; i++)
#pragma unroll
            for (int j = 0; j < 4; j++) acc[i][j] = 0.f;
        float mrow[2] = { -1e30f, -1e30f }, lrow[2] = { 0.f, 0.f };

        const int nk = 2 * qt + 2;
        for (int kt = 0; kt < nk; kt++) {
            cp_wait<0>();
            __syncthreads();          // data ready + prior reads of buf^1 done
            if (kt + 1 < nk) issue(kt + 1, buf ^ 1);

            const uint32_t kbh = sb + KV0 + buf * KV_STAGE;
            const uint32_t kbl = kbh + KV_TILE;
            const uint32_t vbh = kbh + 2 * KV_TILE;
            const uint32_t vbl = kbh + 3 * KV_TILE;

            // ---- S = Qh Kh^T + Qh Kl^T + Ql Kh^T (log2-scaled) ----
            float sf[8][4];
#pragma unroll
            for (int i = 0; i < 8; i++)
#pragma unroll
                for (int j = 0; j < 4; j++) sf[i][j] = 0.f;

#pragma unroll
            for (int kk = 0; kk < 4; kk++) {
                uint32_t aH[4], aL[4];
                ldsm_x4(aH, sb + qrowb + kk * 32);
                ldsm_x4(aL, sb + QT_B + qrowb + kk * 32);
#pragma unroll
                for (int np = 0; np < 2; np++) {      // nf2 pairs {0,1},{2,3}
                    uint32_t ba0 = (np * 2)     * 16 * AT_STRIDE + krowb + kk * 32;
                    uint32_t ba1 = (np * 2 + 1) * 16 * AT_STRIDE + krowb + kk * 32;
                    uint32_t rH0[4], rL0[4], rH1[4], rL1[4];
                    ldsm_x4(rH0, kbh + ba0);
                    ldsm_x4(rL0, kbl + ba0);
                    ldsm_x4(rH1, kbh + ba1);
                    ldsm_x4(rL1, kbl + ba1);
                    float* s0 = sf[np * 4 + 0]; float* s1 = sf[np * 4 + 1];
                    float* s2 = sf[np * 4 + 2]; float* s3 = sf[np * 4 + 3];
                    mma16816(s0, aH, rH0); mma16816(s1, aH, rH0 + 2);
                    mma16816(s2, aH, rH1); mma16816(s3, aH, rH1 + 2);
                    mma16816(s0, aH, rL0); mma16816(s1, aH, rL0 + 2);
                    mma16816(s2, aH, rL1); mma16816(s3, aH, rL1 + 2);
                    mma16816(s0, aL, rH0); mma16816(s1, aL, rH0 + 2);
                    mma16816(s2, aL, rH1); mma16816(s3, aL, rH1 + 2);
                }
            }

            if (kt >= 2 * qt) {     // diagonal region: causal mask
                int r0 = wid * 16 + (lid >> 2);
                int coff = kt * 64 - qt * 128;
#pragma unroll
                for (int nf = 0; nf < 8; nf++) {
                    int c0 = coff + nf * 8 + (lid & 3) * 2;
                    if (c0     > r0)     sf[nf][0] = -1e30f;
                    if (c0 + 1 > r0)     sf[nf][1] = -1e30f;
                    if (c0     > r0 + 8) sf[nf][2] = -1e30f;
                    if (c0 + 1 > r0 + 8) sf[nf][3] = -1e30f;
                }
            }

            // ---- online softmax in exp2 domain ----
#pragma unroll
            for (int hf = 0; hf < 2; hf++) {
                float mx = -1e30f;
#pragma unroll
                for (int nf = 0; nf < 8; nf++)
                    mx = fmaxf(mx, fmaxf(sf[nf][hf * 2], sf[nf][hf * 2 + 1]));
                mx = fmaxf(mx, __shfl_xor_sync(0xffffffffu, mx, 1));
                mx = fmaxf(mx, __shfl_xor_sync(0xffffffffu, mx, 2));
                float mnew = fmaxf(mrow[hf], mx);
                float alpha = ex2(mrow[hf] - mnew);
                mrow[hf] = mnew;
                float sum = 0.f;
#pragma unroll
                for (int nf = 0; nf < 8; nf++) {
                    sf[nf][hf * 2]     = ex2(sf[nf][hf * 2] - mnew);
                    sf[nf][hf * 2 + 1] = ex2(sf[nf][hf * 2 + 1] - mnew);
                    sum += sf[nf][hf * 2] + sf[nf][hf * 2 + 1];
                }
                sum += __shfl_xor_sync(0xffffffffu, sum, 1);
                sum += __shfl_xor_sync(0xffffffffu, sum, 2);
                lrow[hf] = lrow[hf] * alpha + sum;
#pragma unroll
                for (int nf = 0; nf < 8; nf++) {
                    acc[nf][hf * 2]     *= alpha;
                    acc[nf][hf * 2 + 1] *= alpha;
                }
            }

            // ---- O += Ph Vh + Ph Vl + Pl Vh ----
#pragma unroll
            for (int kk2 = 0; kk2 < 4; kk2++) {
                uint32_t aPh[4], aPl[4];
#pragma unroll
                for (int q = 0; q < 2; q++) {
                    const float* c = sf[kk2 * 2 + q];
                    float h0f = __bfloat162float(__float2bfloat16(c[0]));
                    float h1f = __bfloat162float(__float2bfloat16(c[1]));
                    float h2f = __bfloat162float(__float2bfloat16(c[2]));
                    float h3f = __bfloat162float(__float2bfloat16(c[3]));
                    aPh[q * 2]     = packbf(c[0], c[1]);
                    aPh[q * 2 + 1] = packbf(c[2], c[3]);
                    aPl[q * 2]     = packbf(c[0] - h0f, c[1] - h1f);
                    aPl[q * 2 + 1] = packbf(c[2] - h2f, c[3] - h3f);
                }
#pragma unroll
                for (int np = 0; np < 2; np++) {      // nf2 pairs
                    uint32_t va0 = (kk2 * 16) * AT_STRIDE + vrowb + (np * 2)     * 32;
                    uint32_t va1 = (kk2 * 16) * AT_STRIDE + vrowb + (np * 2 + 1) * 32;
                    uint32_t vH0[4], vL0[4], vH1[4], vL1[4];
                    ldsm_x4_t(vH0, vbh + va0);
                    ldsm_x4_t(vL0, vbl + va0);
                    ldsm_x4_t(vH1, vbh + va1);
                    ldsm_x4_t(vL1, vbl + va1);
                    float* a0 = acc[np * 4 + 0]; float* a1 = acc[np * 4 + 1];
                    float* a2 = acc[np * 4 + 2]; float* a3 = acc[np * 4 + 3];
                    mma16816(a0, aPh, vH0); mma16816(a1, aPh, vH0 + 2);
                    mma16816(a2, aPh, vH1); mma16816(a3, aPh, vH1 + 2);
                    mma16816(a0, aPh, vL0); mma16816(a1, aPh, vL0 + 2);
                    mma16816(a2, aPh, vL1); mma16816(a3, aPh, vL1 + 2);
                    mma16816(a0, aPl, vH0); mma16816(a1, aPl, vH0 + 2);
                    mma16816(a2, aPl, vH1); mma16816(a3, aPl, vH1 + 2);
                }
            }
            buf ^= 1;
        }

        // ---- epilogue: ctx -> bf16 hi/lo (B,S,D) ----
        float inv0 = 1.f / lrow[0], inv1 = 1.f / lrow[1];
        int r0 = qt * 128 + wid * 16 + (lid >> 2);
#pragma unroll
        for (int nf = 0; nf < 8; nf++) {
            int d0 = h * HD + nf * 8 + (lid & 3) * 2;
            size_t o0 = ((size_t)b * Ss + r0) * Dd + d0;
            size_t o1 = ((size_t)b * Ss + r0 + 8) * Dd + d0;
            float v0 = acc[nf][0] * inv0, v1 = acc[nf][1] * inv0;
            float v2 = acc[nf][2] * inv1, v3 = acc[nf][3] * inv1;
            __nv_bfloat16 h0, l0, h1, l1, h2, l2, h3, l3;
            split2(v0, h0, l0); split2(v1, h1, l1);
            split2(v2, h2, l2); split2(v3, h3, l3);
            *(__nv_bfloat162*)(g_ch + o0) = __nv_bfloat162(h0, h1);
            *(__nv_bfloat162*)(g_cl + o0) = __nv_bfloat162(l0, l1);
            *(__nv_bfloat162*)(g_ch + o1) = __nv_bfloat162(h2, h3);
            *(__nv_bfloat162*)(g_cl + o1) = __nv_bfloat162(l2, l3);
        }
        __syncthreads();    // Q/KV smem reuse safe before next half's loads
    }
}

// ---------------------------------------------------------------------------
extern "C" void kernel_launch(void* const* d_in, const int* in_sizes, int n_in,
                              void* d_out, int out_size)
{
    const float* x  = (const float*)d_in[0];
    const float* Wq = (const float*)d_in[1];
    const float* bq = (const float*)d_in[2];
    const float* Wk = (const float*)d_in[3];
    const float* bk = (const float*)d_in[4];
    const float* Wv = (const float*)d_in[5];
    const float* bv = (const float*)d_in[6];
    const float* Wo = (const float*)d_in[7];
    const float* bo = (const float*)d_in[8];
    float* out = (float*)d_out;

    cudaFuncSetAttribute(gemm_qkv, cudaFuncAttributeMaxDynamicSharedMemorySize, GEMM_SMEM);
    cudaFuncSetAttribute(gemm_out, cudaFuncAttributeMaxDynamicSharedMemorySize, GEMM_SMEM);
    cudaFuncSetAttribute(attn_mma, cudaFuncAttributeMaxDynamicSharedMemorySize, ATTN_SMEM);

    split_all<<<(Mtot * Dd + 4 * Dd * Dd) / 1024, 256>>>(x, Wq, Wk, Wv, Wo);

    gemm_qkv<<<dim3(Dd / 128, Mtot / 128, 3), 256, GEMM_SMEM>>>(bq, bk, bv);

    attn_mma<<<dim3(8, Bb * Hh), 256, ATTN_SMEM>>>();

    gemm_out<<<dim3(Dd / 128, Mtot / 128), 256, GEMM_SMEM>>>(bo, out);
}

// round 8
// speedup vs baseline: 3.0203x; 1.0153x over previous
#include <cuda_runtime.h>
#include <cuda_bf16.h>
#include <cstdint>

#define Bb 2
#define Ss 2048
#define Dd 1024
#define Hh 16
#define HD 64
#define Mtot (Bb*Ss)   // 4096
#define QSCALE 0.1803368801111244f   // 0.125 * log2(e): softmax in exp2 domain

// ---------------- scratch (static device arrays; alloc APIs forbidden) -----
__device__ __align__(16) __nv_bfloat16 g_qh[Bb*Hh*Ss*HD];  // (B,H,S,hd) bf16 hi/lo
__device__ __align__(16) __nv_bfloat16 g_ql[Bb*Hh*Ss*HD];
__device__ __align__(16) __nv_bfloat16 g_kh[Bb*Hh*Ss*HD];
__device__ __align__(16) __nv_bfloat16 g_kl[Bb*Hh*Ss*HD];
__device__ __align__(16) __nv_bfloat16 g_vh[Bb*Hh*Ss*HD];
__device__ __align__(16) __nv_bfloat16 g_vl[Bb*Hh*Ss*HD];
__device__ __align__(16) __nv_bfloat16 g_xh[Mtot*Dd];      // x split hi/lo
__device__ __align__(16) __nv_bfloat16 g_xl[Mtot*Dd];
__device__ __align__(16) __nv_bfloat16 g_wh[4u*Dd*Dd];     // Wq,Wk,Wv,Wo hi
__device__ __align__(16) __nv_bfloat16 g_wl[4u*Dd*Dd];     // lo
__device__ __align__(16) __nv_bfloat16 g_ch[Mtot*Dd];      // ctx hi/lo (B,S,D)
__device__ __align__(16) __nv_bfloat16 g_cl[Mtot*Dd];

// ---------------- PTX helpers (sm_80/75-era only) --------------------------
__device__ __forceinline__ uint32_t smem_to_u32(const void* p) {
    uint32_t a;
    asm("{ .reg .u64 t; cvta.to.shared.u64 t, %1; cvt.u32.u64 %0, t; }"
        : "=r"(a) : "l"(p));
    return a;
}
__device__ __forceinline__ void cp_async16(uint32_t dst, const void* src) {
    asm volatile("cp.async.cg.shared.global [%0], [%1], 16;"
                 :: "r"(dst), "l"(src) : "memory");
}
__device__ __forceinline__ void cp_commit() {
    asm volatile("cp.async.commit_group;" ::: "memory");
}
template<int N> __device__ __forceinline__ void cp_wait() {
    asm volatile("cp.async.wait_group %0;" :: "n"(N) : "memory");
}
__device__ __forceinline__ void ldsm_x4(uint32_t* r, uint32_t addr) {
    asm volatile("ldmatrix.sync.aligned.m8n8.x4.shared.b16 {%0,%1,%2,%3}, [%4];"
                 : "=r"(r[0]), "=r"(r[1]), "=r"(r[2]), "=r"(r[3]) : "r"(addr));
}
__device__ __forceinline__ void ldsm_x4_t(uint32_t* r, uint32_t addr) {
    asm volatile("ldmatrix.sync.aligned.m8n8.x4.trans.shared.b16 {%0,%1,%2,%3}, [%4];"
                 : "=r"(r[0]), "=r"(r[1]), "=r"(r[2]), "=r"(r[3]) : "r"(addr));
}
__device__ __forceinline__ void mma16816(float* c, const uint32_t* a, const uint32_t* b) {
    asm volatile("mma.sync.aligned.m16n8k16.row.col.f32.bf16.bf16.f32 "
                 "{%0,%1,%2,%3}, {%4,%5,%6,%7}, {%8,%9}, {%0,%1,%2,%3};"
                 : "+f"(c[0]), "+f"(c[1]), "+f"(c[2]), "+f"(c[3])
                 : "r"(a[0]), "r"(a[1]), "r"(a[2]), "r"(a[3]), "r"(b[0]), "r"(b[1]));
}
__device__ __forceinline__ float ex2(float x) {
    float y;
    asm("ex2.approx.ftz.f32 %0, %1;" : "=f"(y) : "f"(x));
    return y;
}

// ---------------- fp32 -> bf16 hi/lo split ---------------------------------
__device__ __forceinline__ void split2(float v, __nv_bfloat16& h, __nv_bfloat16& l) {
    h = __float2bfloat16(v);
    l = __float2bfloat16(v - __bfloat162float(h));
}
__device__ __forceinline__ uint32_t packbf(float a, float b) {
    __nv_bfloat162 t(__float2bfloat16(a), __float2bfloat16(b));
    return *(uint32_t*)&t;
}

// One launch: split x (first 4M elems) and all 4 weights (next 4M).
__global__ __launch_bounds__(256)
void split_all(const float* __restrict__ x,  const float* __restrict__ Wq,
               const float* __restrict__ Wk, const float* __restrict__ Wv,
               const float* __restrict__ Wo)
{
    int i = (blockIdx.x * 256 + threadIdx.x) * 4;
    const float* src;
    __nv_bfloat16 *dh, *dl;
    if (i < Mtot * Dd) {
        src = x + i; dh = g_xh + i; dl = g_xl + i;
    } else {
        int j = i - Mtot * Dd;
        int w = j >> 20;                 // Dd*Dd = 2^20
        int r = j & (Dd * Dd - 1);
        src = (w == 0 ? Wq : w == 1 ? Wk : w == 2 ? Wv : Wo) + r;
        dh = g_wh + j; dl = g_wl + j;
    }
    float4 v = *(const float4*)src;
    __nv_bfloat16 h0, h1, h2, h3, l0, l1, l2, l3;
    split2(v.x, h0, l0); split2(v.y, h1, l1); split2(v.z, h2, l2); split2(v.w, h3, l3);
    *(__nv_bfloat162*)(dh)     = __nv_bfloat162(h0, h1);
    *(__nv_bfloat162*)(dh + 2) = __nv_bfloat162(h2, h3);
    *(__nv_bfloat162*)(dl)     = __nv_bfloat162(l0, l1);
    *(__nv_bfloat162*)(dl + 2) = __nv_bfloat162(l2, l3);
}

// ---------------------------------------------------------------------------
// mma.sync GEMM core (block 128x128, 8 warps, double-buffered smem, A-fragment
// software pipelining: LDSM of a[mf+1] overlaps the 12 HMMAs of a[mf]).
// ---------------------------------------------------------------------------
#define TILE_B   10240                 // 128 * 80
#define BUF_B    (4 * TILE_B)
#define GEMM_SMEM (2 * BUF_B + 512)

// The shared mainloop body for one kt iteration.
#define GEMM_KT_BODY(tAh, tAl, tBh, tBl)                                       \
    _Pragma("unroll")                                                          \
    for (int kk = 0; kk < 2; kk++) {                                           \
        const int ab = kk * 32 + abyte0;                                       \
        const int bb = kk * 32 + bbyte0;                                       \
        uint32_t bH[4][2], bL[4][2];                                           \
        _Pragma("unroll")                                                      \
        for (int nf2 = 0; nf2 < 2; nf2++) {                                    \
            uint32_t ro = (brow0 + nf2 * 16) * 80;                             \
            uint32_t r4[4];                                                    \
            ldsm_x4(r4, (tBh) + ro + bb);                                      \
            bH[nf2 * 2][0] = r4[0]; bH[nf2 * 2][1] = r4[1];                    \
            bH[nf2 * 2 + 1][0] = r4[2]; bH[nf2 * 2 + 1][1] = r4[3];            \
            ldsm_x4(r4, (tBl) + ro + bb);                                      \
            bL[nf2 * 2][0] = r4[0]; bL[nf2 * 2][1] = r4[1];                    \
            bL[nf2 * 2 + 1][0] = r4[2]; bL[nf2 * 2 + 1][1] = r4[3];            \
        }                                                                      \
        uint32_t aH[2][4], aL[2][4];                                           \
        ldsm_x4(aH[0], (tAh) + arow0 * 80 + ab);                               \
        ldsm_x4(aL[0], (tAl) + arow0 * 80 + ab);                               \
        _Pragma("unroll")                                                      \
        for (int mf = 0; mf < 4; mf++) {                                       \
            const int cur = mf & 1, nxt = cur ^ 1;                             \
            if (mf < 3) {                                                      \
                uint32_t ro = (arow0 + (mf + 1) * 16) * 80;                    \
                ldsm_x4(aH[nxt], (tAh) + ro + ab);                             \
                ldsm_x4(aL[nxt], (tAl) + ro + ab);                             \
            }                                                                  \
            _Pragma("unroll")                                                  \
            for (int nf = 0; nf < 4; nf++)                                     \
                mma16816(acc[mf][nf], aH[cur], bH[nf]);                        \
            _Pragma("unroll")                                                  \
            for (int nf = 0; nf < 4; nf++)                                     \
                mma16816(acc[mf][nf], aH[cur], bL[nf]);                        \
            _Pragma("unroll")                                                  \
            for (int nf = 0; nf < 4; nf++)                                     \
                mma16816(acc[mf][nf], aL[cur], bH[nf]);                        \
        }                                                                      \
    }

// Fused QKV projection: gridDim.z selects Q/K/V.
__global__ __launch_bounds__(256)
void gemm_qkv(const float* __restrict__ bq, const float* __restrict__ bk,
              const float* __restrict__ bv)
{
    extern __shared__ char smem[];
    const uint32_t sb = smem_to_u32(smem);
    float* biasS = (float*)(smem + 2 * BUF_B);

    const int tid = threadIdx.x, wid = tid >> 5, lid = tid & 31;
    const int wm = wid >> 2, wn = wid & 3;
    const int m0 = blockIdx.y * 128, n0 = blockIdx.x * 128;
    const int z = blockIdx.z;

    const float* bias = (z == 0) ? bq : (z == 1) ? bk : bv;
    const __nv_bfloat16* Wh = g_wh + (size_t)z * Dd * Dd;
    const __nv_bfloat16* Wl = g_wl + (size_t)z * Dd * Dd;

    if (tid < 128) biasS[tid] = bias[n0 + tid];

    float acc[4][4][4];
#pragma unroll
    for (int i = 0; i < 4; i++)
#pragma unroll
        for (int j = 0; j < 4; j++)
#pragma unroll
            for (int k = 0; k < 4; k++) acc[i][j][k] = 0.f;

    auto issue = [&](int kt, int buf) {
        const int kc = kt * 32;
#pragma unroll
        for (int i = 0; i < 8; i++) {
            int idx = tid + i * 256;
            int tile = idx >> 9, w = idx & 511;
            int r = w >> 2, seg = (w & 3) * 16;
            uint32_t dst = sb + buf * BUF_B + tile * TILE_B + r * 80 + seg;
            const char* src;
            if (tile == 0)      src = (const char*)(g_xh + (size_t)(m0 + r) * Dd + kc) + seg;
            else if (tile == 1) src = (const char*)(g_xl + (size_t)(m0 + r) * Dd + kc) + seg;
            else if (tile == 2) src = (const char*)(Wh + (size_t)(n0 + r) * Dd + kc) + seg;
            else                src = (const char*)(Wl + (size_t)(n0 + r) * Dd + kc) + seg;
            cp_async16(dst, src);
        }
        cp_commit();
    };

    issue(0, 0);
    int buf = 0;
    const int arow0 = wm * 64 + (lid & 15);
    const int abyte0 = (lid >> 4) * 16;
    const int brow0 = wn * 32 + ((lid >> 4) << 3) + (lid & 7);
    const int bbyte0 = ((lid >> 3) & 1) * 16;

    for (int kt = 0; kt < 32; kt++) {
        cp_wait<0>();
        __syncthreads();               // data ready + prior reads of buf^1 done
        if (kt + 1 < 32) issue(kt + 1, buf ^ 1);

        const uint32_t tAh = sb + buf * BUF_B;
        const uint32_t tAl = tAh + TILE_B;
        const uint32_t tBh = tAh + 2 * TILE_B;
        const uint32_t tBl = tAh + 3 * TILE_B;
        GEMM_KT_BODY(tAh, tAl, tBh, tBl)
        buf ^= 1;
    }

    const float scale = (z == 0) ? QSCALE : 1.f;
    __nv_bfloat16* dh = (z == 0) ? g_qh : (z == 1) ? g_kh : g_vh;
    __nv_bfloat16* dl = (z == 0) ? g_ql : (z == 1) ? g_kl : g_vl;
#pragma unroll
    for (int mf = 0; mf < 4; mf++) {
#pragma unroll
        for (int nf = 0; nf < 4; nf++) {
            int nl = wn * 32 + nf * 8 + (lid & 3) * 2;
            int n = n0 + nl;
            float b0 = biasS[nl], b1 = biasS[nl + 1];
#pragma unroll
            for (int half = 0; half < 2; half++) {
                int m = m0 + wm * 64 + mf * 16 + (lid >> 2) + half * 8;
                float v0 = (acc[mf][nf][half * 2 + 0] + b0) * scale;
                float v1 = (acc[mf][nf][half * 2 + 1] + b1) * scale;
                __nv_bfloat16 h0, l0, h1, l1;
                split2(v0, h0, l0); split2(v1, h1, l1);
                int b = m >> 11, s = m & (Ss - 1);
                int hh = n >> 6, d = n & (HD - 1);
                size_t o = (((size_t)(b * Hh + hh)) * Ss + s) * HD + d;
                *(__nv_bfloat162*)(dh + o) = __nv_bfloat162(h0, h1);
                *(__nv_bfloat162*)(dl + o) = __nv_bfloat162(l0, l1);
            }
        }
    }
}

// Output GEMM: out = ctx @ Wo^T + bo, fp32 result.
__global__ __launch_bounds__(256)
void gemm_out(const float* __restrict__ bias, float* __restrict__ Cout)
{
    extern __shared__ char smem[];
    const uint32_t sb = smem_to_u32(smem);
    float* biasS = (float*)(smem + 2 * BUF_B);

    const int tid = threadIdx.x, wid = tid >> 5, lid = tid & 31;
    const int wm = wid >> 2, wn = wid & 3;
    const int m0 = blockIdx.y * 128, n0 = blockIdx.x * 128;

    const __nv_bfloat16* Wh = g_wh + (size_t)3 * Dd * Dd;
    const __nv_bfloat16* Wl = g_wl + (size_t)3 * Dd * Dd;

    if (tid < 128) biasS[tid] = bias[n0 + tid];

    float acc[4][4][4];
#pragma unroll
    for (int i = 0; i < 4; i++)
#pragma unroll
        for (int j = 0; j < 4; j++)
#pragma unroll
            for (int k = 0; k < 4; k++) acc[i][j][k] = 0.f;

    auto issue = [&](int kt, int buf) {
        const int kc = kt * 32;
#pragma unroll
        for (int i = 0; i < 8; i++) {
            int idx = tid + i * 256;
            int tile = idx >> 9, w = idx & 511;
            int r = w >> 2, seg = (w & 3) * 16;
            uint32_t dst = sb + buf * BUF_B + tile * TILE_B + r * 80 + seg;
            const char* src;
            if (tile == 0)      src = (const char*)(g_ch + (size_t)(m0 + r) * Dd + kc) + seg;
            else if (tile == 1) src = (const char*)(g_cl + (size_t)(m0 + r) * Dd + kc) + seg;
            else if (tile == 2) src = (const char*)(Wh + (size_t)(n0 + r) * Dd + kc) + seg;
            else                src = (const char*)(Wl + (size_t)(n0 + r) * Dd + kc) + seg;
            cp_async16(dst, src);
        }
        cp_commit();
    };

    issue(0, 0);
    int buf = 0;
    const int arow0 = wm * 64 + (lid & 15);
    const int abyte0 = (lid >> 4) * 16;
    const int brow0 = wn * 32 + ((lid >> 4) << 3) + (lid & 7);
    const int bbyte0 = ((lid >> 3) & 1) * 16;

    for (int kt = 0; kt < 32; kt++) {
        cp_wait<0>();
        __syncthreads();
        if (kt + 1 < 32) issue(kt + 1, buf ^ 1);

        const uint32_t tAh = sb + buf * BUF_B;
        const uint32_t tAl = tAh + TILE_B;
        const uint32_t tBh = tAh + 2 * TILE_B;
        const uint32_t tBl = tAh + 3 * TILE_B;
        GEMM_KT_BODY(tAh, tAl, tBh, tBl)
        buf ^= 1;
    }

#pragma unroll
    for (int mf = 0; mf < 4; mf++) {
#pragma unroll
        for (int nf = 0; nf < 4; nf++) {
            int nl = wn * 32 + nf * 8 + (lid & 3) * 2;
            int n = n0 + nl;
            float b0 = biasS[nl], b1 = biasS[nl + 1];
#pragma unroll
            for (int half = 0; half < 2; half++) {
                int m = m0 + wm * 64 + mf * 16 + (lid >> 2) + half * 8;
                *(float2*)(Cout + (size_t)m * Dd + n) =
                    make_float2(acc[mf][nf][half * 2 + 0] + b0,
                                acc[mf][nf][half * 2 + 1] + b1);
            }
        }
    }
}

// ---------------------------------------------------------------------------
// Tensor-core causal flash attention. q-tile 128 rows, 256 threads / 8 warps.
// S-loop and PV-loop flattened to 8 steps with one-step fragment lookahead
// (LDSM of step s+1 overlaps the 12 HMMAs of step s).
// ---------------------------------------------------------------------------
#define AT_STRIDE 144
#define QT_B     (128 * AT_STRIDE)           // 18432
#define KV_TILE  (64 * AT_STRIDE)            // 9216
#define KV0      (2 * QT_B)                  // 36864
#define KV_STAGE (4 * KV_TILE)               // 36864
#define ATTN_SMEM (KV0 + 2 * KV_STAGE)       // 110592

__global__ __launch_bounds__(256)
void attn_mma()
{
    extern __shared__ char smem[];
    const uint32_t sb = smem_to_u32(smem);
    const int pr = blockIdx.x;                 // pair index 0..7
    const int bh = blockIdx.y;
    const int b = bh >> 4, h = bh & 15;
    const int tid = threadIdx.x, wid = tid >> 5, lid = tid & 31;

    const __nv_bfloat16* bases[4] = {
        g_kh + (size_t)bh * Ss * HD, g_kl + (size_t)bh * Ss * HD,
        g_vh + (size_t)bh * Ss * HD, g_vl + (size_t)bh * Ss * HD };

    auto issue = [&](int kt, int bf) {
#pragma unroll
        for (int i = 0; i < 8; i++) {
            int idx = tid + i * 256;
            int t = idx >> 9, w = idx & 511;
            int r = w >> 3, c = w & 7;
            cp_async16(sb + KV0 + bf * KV_STAGE + t * KV_TILE + r * AT_STRIDE + c * 16,
                       bases[t] + (size_t)(kt * 64 + r) * HD + c * 8);
        }
        cp_commit();
    };

    const uint32_t qrowb = (wid * 16 + (lid & 15)) * AT_STRIDE + (lid >> 4) * 16;
    const uint32_t krowb = (((lid >> 4) << 3) + (lid & 7)) * AT_STRIDE + ((lid >> 3) & 1) * 16;
    const uint32_t vrowb = (lid & 15) * AT_STRIDE + ((lid >> 4) & 1) * 16;
    int buf = 0;

    for (int half_t = 0; half_t < 2; half_t++) {
        const int qt = half_t ? (15 - pr) : pr;       // q-tile of 128 rows
        const __nv_bfloat16* QH = g_qh + ((size_t)bh * Ss + qt * 128) * HD;
        const __nv_bfloat16* QL = g_ql + ((size_t)bh * Ss + qt * 128) * HD;

        // Q tile (Qh, Ql): 128 rows x 128B each
#pragma unroll
        for (int i = 0; i < 8; i++) {
            int idx = tid + i * 256;
            int s = idx >> 10, w = idx & 1023;
            int r = w >> 3, c = w & 7;
            cp_async16(sb + s * QT_B + r * AT_STRIDE + c * 16,
                       (s ? QL : QH) + (size_t)r * HD + c * 8);
        }
        cp_commit();
        issue(0, buf);

        float acc[8][4];
#pragma unroll
        for (int i = 0; i < 8; i++)
#pragma unroll
            for (int j = 0; j < 4; j++) acc[i][j] = 0.f;
        float mrow[2] = { -1e30f, -1e30f }, lrow[2] = { 0.f, 0.f };

        const int nk = 2 * qt + 2;
        for (int kt = 0; kt < nk; kt++) {
            cp_wait<0>();
            __syncthreads();          // data ready + prior reads of buf^1 done
            if (kt + 1 < nk) issue(kt + 1, buf ^ 1);

            const uint32_t kbh = sb + KV0 + buf * KV_STAGE;
            const uint32_t kbl = kbh + KV_TILE;
            const uint32_t vbh = kbh + 2 * KV_TILE;
            const uint32_t vbl = kbh + 3 * KV_TILE;

            // ---- S = Qh Kh^T + Qh Kl^T + Ql Kh^T, pipelined 8 steps ----
            float sf[8][4];
#pragma unroll
            for (int i = 0; i < 8; i++)
#pragma unroll
                for (int j = 0; j < 4; j++) sf[i][j] = 0.f;

            {
                uint32_t aH[2][4], aL[2][4], kf[2][16];
                ldsm_x4(aH[0], sb + qrowb);
                ldsm_x4(aL[0], sb + QT_B + qrowb);
                ldsm_x4(kf[0] + 0,  kbh + krowb);                    // rH0 (np=0)
                ldsm_x4(kf[0] + 4,  kbl + krowb);                    // rL0
                ldsm_x4(kf[0] + 8,  kbh + 16 * AT_STRIDE + krowb);   // rH1
                ldsm_x4(kf[0] + 12, kbl + 16 * AT_STRIDE + krowb);   // rL1
#pragma unroll
                for (int step = 0; step < 8; step++) {
                    const int kk = step >> 1, np = step & 1;
                    const int cp = step & 1 ? 1 : 0;  // kf parity
                    if (step + 1 < 8) {
                        const int nkk = (step + 1) >> 1, nnp = (step + 1) & 1;
                        const uint32_t nka = nnp * 32 * AT_STRIDE + krowb + nkk * 32;
                        if (nnp == 0) {
                            ldsm_x4(aH[nkk & 1], sb + qrowb + nkk * 32);
                            ldsm_x4(aL[nkk & 1], sb + QT_B + qrowb + nkk * 32);
                        }
                        uint32_t* nf = kf[(step + 1) & 1];
                        ldsm_x4(nf + 0,  kbh + nka);
                        ldsm_x4(nf + 4,  kbl + nka);
                        ldsm_x4(nf + 8,  kbh + 16 * AT_STRIDE + nka);
                        ldsm_x4(nf + 12, kbl + 16 * AT_STRIDE + nka);
                    }
                    const uint32_t* aHc = aH[kk & 1];
                    const uint32_t* aLc = aL[kk & 1];
                    const uint32_t* f = kf[cp];
                    float* s0 = sf[np * 4 + 0]; float* s1 = sf[np * 4 + 1];
                    float* s2 = sf[np * 4 + 2]; float* s3 = sf[np * 4 + 3];
                    mma16816(s0, aHc, f + 0); mma16816(s1, aHc, f + 2);
                    mma16816(s2, aHc, f + 8); mma16816(s3, aHc, f + 10);
                    mma16816(s0, aHc, f + 4); mma16816(s1, aHc, f + 6);
                    mma16816(s2, aHc, f + 12); mma16816(s3, aHc, f + 14);
                    mma16816(s0, aLc, f + 0); mma16816(s1, aLc, f + 2);
                    mma16816(s2, aLc, f + 8); mma16816(s3, aLc, f + 10);
                }
            }

            if (kt >= 2 * qt) {     // diagonal region: causal mask
                int r0 = wid * 16 + (lid >> 2);
                int coff = kt * 64 - qt * 128;
#pragma unroll
                for (int nf = 0; nf < 8; nf++) {
                    int c0 = coff + nf * 8 + (lid & 3) * 2;
                    if (c0     > r0)     sf[nf][0] = -1e30f;
                    if (c0 + 1 > r0)     sf[nf][1] = -1e30f;
                    if (c0     > r0 + 8) sf[nf][2] = -1e30f;
                    if (c0 + 1 > r0 + 8) sf[nf][3] = -1e30f;
                }
            }

            // ---- online softmax in exp2 domain ----
#pragma unroll
            for (int hf = 0; hf < 2; hf++) {
                float mx = -1e30f;
#pragma unroll
                for (int nf = 0; nf < 8; nf++)
                    mx = fmaxf(mx, fmaxf(sf[nf][hf * 2], sf[nf][hf * 2 + 1]));
                mx = fmaxf(mx, __shfl_xor_sync(0xffffffffu, mx, 1));
                mx = fmaxf(mx, __shfl_xor_sync(0xffffffffu, mx, 2));
                float mnew = fmaxf(mrow[hf], mx);
                float alpha = ex2(mrow[hf] - mnew);
                mrow[hf] = mnew;
                float sum = 0.f;
#pragma unroll
                for (int nf = 0; nf < 8; nf++) {
                    sf[nf][hf * 2]     = ex2(sf[nf][hf * 2] - mnew);
                    sf[nf][hf * 2 + 1] = ex2(sf[nf][hf * 2 + 1] - mnew);
                    sum += sf[nf][hf * 2] + sf[nf][hf * 2 + 1];
                }
                sum += __shfl_xor_sync(0xffffffffu, sum, 1);
                sum += __shfl_xor_sync(0xffffffffu, sum, 2);
                lrow[hf] = lrow[hf] * alpha + sum;
#pragma unroll
                for (int nf = 0; nf < 8; nf++) {
                    acc[nf][hf * 2]     *= alpha;
                    acc[nf][hf * 2 + 1] *= alpha;
                }
            }

            // ---- O += Ph Vh + Ph Vl + Pl Vh, pipelined 8 steps ----
            {
                uint32_t vf[2][16], aPh[4], aPl[4];
                ldsm_x4_t(vf[0] + 0,  vbh + vrowb);
                ldsm_x4_t(vf[0] + 4,  vbl + vrowb);
                ldsm_x4_t(vf[0] + 8,  vbh + vrowb + 32);
                ldsm_x4_t(vf[0] + 12, vbl + vrowb + 32);
#pragma unroll
                for (int step = 0; step < 8; step++) {
                    const int kk2 = step >> 1, np = step & 1;
                    if (np == 0) {    // build P fragments for this kk2
#pragma unroll
                        for (int q = 0; q < 2; q++) {
                            const float* c = sf[kk2 * 2 + q];
                            float h0f = __bfloat162float(__float2bfloat16(c[0]));
                            float h1f = __bfloat162float(__float2bfloat16(c[1]));
                            float h2f = __bfloat162float(__float2bfloat16(c[2]));
                            float h3f = __bfloat162float(__float2bfloat16(c[3]));
                            aPh[q * 2]     = packbf(c[0], c[1]);
                            aPh[q * 2 + 1] = packbf(c[2], c[3]);
                            aPl[q * 2]     = packbf(c[0] - h0f, c[1] - h1f);
                            aPl[q * 2 + 1] = packbf(c[2] - h2f, c[3] - h3f);
                        }
                    }
                    if (step + 1 < 8) {
                        const int nkk2 = (step + 1) >> 1, nnp = (step + 1) & 1;
                        const uint32_t nva = (nkk2 * 16) * AT_STRIDE + vrowb + nnp * 64;
                        uint32_t* nf = vf[(step + 1) & 1];
                        ldsm_x4_t(nf + 0,  vbh + nva);
                        ldsm_x4_t(nf + 4,  vbl + nva);
                        ldsm_x4_t(nf + 8,  vbh + nva + 32);
                        ldsm_x4_t(nf + 12, vbl + nva + 32);
                    }
                    const uint32_t* f = vf[step & 1];
                    float* a0 = acc[np * 4 + 0]; float* a1 = acc[np * 4 + 1];
                    float* a2 = acc[np * 4 + 2]; float* a3 = acc[np * 4 + 3];
                    mma16816(a0, aPh, f + 0); mma16816(a1, aPh, f + 2);
                    mma16816(a2, aPh, f + 8); mma16816(a3, aPh, f + 10);
                    mma16816(a0, aPh, f + 4); mma16816(a1, aPh, f + 6);
                    mma16816(a2, aPh, f + 12); mma16816(a3, aPh, f + 14);
                    mma16816(a0, aPl, f + 0); mma16816(a1, aPl, f + 2);
                    mma16816(a2, aPl, f + 8); mma16816(a3, aPl, f + 10);
                }
            }
            buf ^= 1;
        }

        // ---- epilogue: ctx -> bf16 hi/lo (B,S,D) ----
        float inv0 = 1.f / lrow[0], inv1 = 1.f / lrow[1];
        int r0 = qt * 128 + wid * 16 + (lid >> 2);
#pragma unroll
        for (int nf = 0; nf < 8; nf++) {
            int d0 = h * HD + nf * 8 + (lid & 3) * 2;
            size_t o0 = ((size_t)b * Ss + r0) * Dd + d0;
            size_t o1 = ((size_t)b * Ss + r0 + 8) * Dd + d0;
            float v0 = acc[nf][0] * inv0, v1 = acc[nf][1] * inv0;
            float v2 = acc[nf][2] * inv1, v3 = acc[nf][3] * inv1;
            __nv_bfloat16 h0, l0, h1, l1, h2, l2, h3, l3;
            split2(v0, h0, l0); split2(v1, h1, l1);
            split2(v2, h2, l2); split2(v3, h3, l3);
            *(__nv_bfloat162*)(g_ch + o0) = __nv_bfloat162(h0, h1);
            *(__nv_bfloat162*)(g_cl + o0) = __nv_bfloat162(l0, l1);
            *(__nv_bfloat162*)(g_ch + o1) = __nv_bfloat162(h2, h3);
            *(__nv_bfloat162*)(g_cl + o1) = __nv_bfloat162(l2, l3);
        }
        __syncthreads();    // Q/KV smem reuse safe before next half's loads
    }
}

// ---------------------------------------------------------------------------
extern "C" void kernel_launch(void* const* d_in, const int* in_sizes, int n_in,
                              void* d_out, int out_size)
{
    const float* x  = (const float*)d_in[0];
    const float* Wq = (const float*)d_in[1];
    const float* bq = (const float*)d_in[2];
    const float* Wk = (const float*)d_in[3];
    const float* bk = (const float*)d_in[4];
    const float* Wv = (const float*)d_in[5];
    const float* bv = (const float*)d_in[6];
    const float* Wo = (const float*)d_in[7];
    const float* bo = (const float*)d_in[8];
    float* out = (float*)d_out;

    cudaFuncSetAttribute(gemm_qkv, cudaFuncAttributeMaxDynamicSharedMemorySize, GEMM_SMEM);
    cudaFuncSetAttribute(gemm_out, cudaFuncAttributeMaxDynamicSharedMemorySize, GEMM_SMEM);
    cudaFuncSetAttribute(attn_mma, cudaFuncAttributeMaxDynamicSharedMemorySize, ATTN_SMEM);

    split_all<<<(Mtot * Dd + 4 * Dd * Dd) / 1024, 256>>>(x, Wq, Wk, Wv, Wo);

    gemm_qkv<<<dim3(Dd / 128, Mtot / 128, 3), 256, GEMM_SMEM>>>(bq, bk, bv);

    attn_mma<<<dim3(8, Bb * Hh), 256, ATTN_SMEM>>>();

    gemm_out<<<dim3(Dd / 128, Mtot / 128), 256, GEMM_SMEM>>>(bo, out);
}

// round 9
// speedup vs baseline: 4.7201x; 1.5628x over previous
#include <cuda_runtime.h>
#include <cuda_fp16.h>
#include <cstdint>

#define Bb 2
#define Ss 2048
#define Dd 1024
#define Hh 16
#define HD 64
#define Mtot (Bb*Ss)   // 4096
#define QSCALE 0.1803368801111244f   // 0.125 * log2(e): softmax in exp2 domain

// ---------------- scratch (static device arrays; alloc APIs forbidden) -----
__device__ __align__(16) __half g_qh[Bb*Hh*Ss*HD];  // q split hi/lo (B,H,S,hd)
__device__ __align__(16) __half g_ql[Bb*Hh*Ss*HD];
__device__ __align__(16) __half g_kh[Bb*Hh*Ss*HD];  // k single fp16
__device__ __align__(16) __half g_vh[Bb*Hh*Ss*HD];  // v single fp16
__device__ __align__(16) __half g_xh[Mtot*Dd];      // x split hi/lo
__device__ __align__(16) __half g_xl[Mtot*Dd];
__device__ __align__(16) __half g_w [4u*Dd*Dd];     // Wq,Wk,Wv,Wo single fp16
__device__ __align__(16) __half g_ch[Mtot*Dd];      // ctx split hi/lo (B,S,D)
__device__ __align__(16) __half g_cl[Mtot*Dd];

// ---------------- PTX helpers (sm_80/75-era only) --------------------------
__device__ __forceinline__ uint32_t smem_to_u32(const void* p) {
    uint32_t a;
    asm("{ .reg .u64 t; cvta.to.shared.u64 t, %1; cvt.u32.u64 %0, t; }"
        : "=r"(a) : "l"(p));
    return a;
}
__device__ __forceinline__ void cp_async16(uint32_t dst, const void* src) {
    asm volatile("cp.async.cg.shared.global [%0], [%1], 16;"
                 :: "r"(dst), "l"(src) : "memory");
}
__device__ __forceinline__ void cp_commit() {
    asm volatile("cp.async.commit_group;" ::: "memory");
}
template<int N> __device__ __forceinline__ void cp_wait() {
    asm volatile("cp.async.wait_group %0;" :: "n"(N) : "memory");
}
__device__ __forceinline__ void ldsm_x4(uint32_t* r, uint32_t addr) {
    asm volatile("ldmatrix.sync.aligned.m8n8.x4.shared.b16 {%0,%1,%2,%3}, [%4];"
                 : "=r"(r[0]), "=r"(r[1]), "=r"(r[2]), "=r"(r[3]) : "r"(addr));
}
__device__ __forceinline__ void ldsm_x4_t(uint32_t* r, uint32_t addr) {
    asm volatile("ldmatrix.sync.aligned.m8n8.x4.trans.shared.b16 {%0,%1,%2,%3}, [%4];"
                 : "=r"(r[0]), "=r"(r[1]), "=r"(r[2]), "=r"(r[3]) : "r"(addr));
}
__device__ __forceinline__ void mma16816(float* c, const uint32_t* a, const uint32_t* b) {
    asm volatile("mma.sync.aligned.m16n8k16.row.col.f32.f16.f16.f32 "
                 "{%0,%1,%2,%3}, {%4,%5,%6,%7}, {%8,%9}, {%0,%1,%2,%3};"
                 : "+f"(c[0]), "+f"(c[1]), "+f"(c[2]), "+f"(c[3])
                 : "r"(a[0]), "r"(a[1]), "r"(a[2]), "r"(a[3]), "r"(b[0]), "r"(b[1]));
}
__device__ __forceinline__ float ex2(float x) {
    float y;
    asm("ex2.approx.ftz.f32 %0, %1;" : "=f"(y) : "f"(x));
    return y;
}

// ---------------- fp32 -> fp16 hi/lo split ---------------------------------
__device__ __forceinline__ void split2h(float v, __half& h, __half& l) {
    h = __float2half(v);
    l = __float2half(v - __half2float(h));
}
__device__ __forceinline__ uint32_t packh(float a, float b) {
    __half2 t = __floats2half2_rn(a, b);
    return *(uint32_t*)&t;
}

// One launch: split x (first 4M elems, hi/lo) + round all 4 weights (single).
__global__ __launch_bounds__(256)
void split_all(const float* __restrict__ x,  const float* __restrict__ Wq,
               const float* __restrict__ Wk, const float* __restrict__ Wv,
               const float* __restrict__ Wo)
{
    int i = (blockIdx.x * 256 + threadIdx.x) * 4;
    if (i < Mtot * Dd) {
        float4 v = *(const float4*)(x + i);
        __half h0, h1, h2, h3, l0, l1, l2, l3;
        split2h(v.x, h0, l0); split2h(v.y, h1, l1);
        split2h(v.z, h2, l2); split2h(v.w, h3, l3);
        *(__half2*)(g_xh + i)     = __half2(h0, h1);
        *(__half2*)(g_xh + i + 2) = __half2(h2, h3);
        *(__half2*)(g_xl + i)     = __half2(l0, l1);
        *(__half2*)(g_xl + i + 2) = __half2(l2, l3);
    } else {
        int j = i - Mtot * Dd;
        int w = j >> 20;                 // Dd*Dd = 2^20
        int r = j & (Dd * Dd - 1);
        const float* src = (w == 0 ? Wq : w == 1 ? Wk : w == 2 ? Wv : Wo) + r;
        float4 v = *(const float4*)src;
        *(__half2*)(g_w + j)     = __floats2half2_rn(v.x, v.y);
        *(__half2*)(g_w + j + 2) = __floats2half2_rn(v.z, v.w);
    }
}

// ---------------------------------------------------------------------------
// mma.sync GEMM core: C = (Ah+Al) @ B16^T (+bias). Block 128x128, 8 warps,
// double-buffered cp.async, 2 MMA terms (HH + LH). Tiles: Ah, Al, B.
// ---------------------------------------------------------------------------
#define TILE_B   10240                 // 128 rows * 80 B
#define BUF3_B   (3 * TILE_B)
#define GEMM_SMEM (2 * BUF3_B + 512)   // 61952

#define GEMM_KT_BODY(tAh, tAl, tBh)                                            \
    _Pragma("unroll")                                                          \
    for (int kk = 0; kk < 2; kk++) {                                           \
        const int ab = kk * 32 + abyte0;                                       \
        const int bb = kk * 32 + bbyte0;                                       \
        uint32_t aH[4][4], aL[4][4], bH[4][2];                                 \
        _Pragma("unroll")                                                      \
        for (int mf = 0; mf < 4; mf++) {                                       \
            uint32_t ro = (arow0 + mf * 16) * 80;                              \
            ldsm_x4(aH[mf], (tAh) + ro + ab);                                  \
            ldsm_x4(aL[mf], (tAl) + ro + ab);                                  \
        }                                                                      \
        _Pragma("unroll")                                                      \
        for (int nf2 = 0; nf2 < 2; nf2++) {                                    \
            uint32_t ro = (brow0 + nf2 * 16) * 80;                             \
            uint32_t r4[4];                                                    \
            ldsm_x4(r4, (tBh) + ro + bb);                                      \
            bH[nf2 * 2][0] = r4[0]; bH[nf2 * 2][1] = r4[1];                    \
            bH[nf2 * 2 + 1][0] = r4[2]; bH[nf2 * 2 + 1][1] = r4[3];            \
        }                                                                      \
        _Pragma("unroll")                                                      \
        for (int mf = 0; mf < 4; mf++)                                         \
            _Pragma("unroll")                                                  \
            for (int nf = 0; nf < 4; nf++)                                     \
                mma16816(acc[mf][nf], aH[mf], bH[nf]);                         \
        _Pragma("unroll")                                                      \
        for (int mf = 0; mf < 4; mf++)                                         \
            _Pragma("unroll")                                                  \
            for (int nf = 0; nf < 4; nf++)                                     \
                mma16816(acc[mf][nf], aL[mf], bH[nf]);                         \
    }

// Fused QKV projection: gridDim.z selects Q/K/V.
__global__ __launch_bounds__(256)
void gemm_qkv(const float* __restrict__ bq, const float* __restrict__ bk,
              const float* __restrict__ bv)
{
    extern __shared__ char smem[];
    const uint32_t sb = smem_to_u32(smem);
    float* biasS = (float*)(smem + 2 * BUF3_B);

    const int tid = threadIdx.x, wid = tid >> 5, lid = tid & 31;
    const int wm = wid >> 2, wn = wid & 3;
    const int m0 = blockIdx.y * 128, n0 = blockIdx.x * 128;
    const int z = blockIdx.z;

    const float* bias = (z == 0) ? bq : (z == 1) ? bk : bv;
    const __half* W16 = g_w + (size_t)z * Dd * Dd;

    if (tid < 128) biasS[tid] = bias[n0 + tid];

    float acc[4][4][4];
#pragma unroll
    for (int i = 0; i < 4; i++)
#pragma unroll
        for (int j = 0; j < 4; j++)
#pragma unroll
            for (int k = 0; k < 4; k++) acc[i][j][k] = 0.f;

    auto issue = [&](int kt, int buf) {
        const int kc = kt * 32;
#pragma unroll
        for (int i = 0; i < 6; i++) {
            int idx = tid + i * 256;
            int tile = idx >> 9, w = idx & 511;
            int r = w >> 2, seg = (w & 3) * 16;
            uint32_t dst = sb + buf * BUF3_B + tile * TILE_B + r * 80 + seg;
            const char* src;
            if (tile == 0)      src = (const char*)(g_xh + (size_t)(m0 + r) * Dd + kc) + seg;
            else if (tile == 1) src = (const char*)(g_xl + (size_t)(m0 + r) * Dd + kc) + seg;
            else                src = (const char*)(W16 + (size_t)(n0 + r) * Dd + kc) + seg;
            cp_async16(dst, src);
        }
        cp_commit();
    };

    issue(0, 0);
    int buf = 0;
    const int arow0 = wm * 64 + (lid & 15);
    const int abyte0 = (lid >> 4) * 16;
    const int brow0 = wn * 32 + ((lid >> 4) << 3) + (lid & 7);
    const int bbyte0 = ((lid >> 3) & 1) * 16;

    for (int kt = 0; kt < 32; kt++) {
        cp_wait<0>();
        __syncthreads();               // data ready + prior reads of buf^1 done
        if (kt + 1 < 32) issue(kt + 1, buf ^ 1);

        const uint32_t tAh = sb + buf * BUF3_B;
        const uint32_t tAl = tAh + TILE_B;
        const uint32_t tBh = tAh + 2 * TILE_B;
        GEMM_KT_BODY(tAh, tAl, tBh)
        buf ^= 1;
    }

#pragma unroll
    for (int mf = 0; mf < 4; mf++) {
#pragma unroll
        for (int nf = 0; nf < 4; nf++) {
            int nl = wn * 32 + nf * 8 + (lid & 3) * 2;
            int n = n0 + nl;
            float b0 = biasS[nl], b1 = biasS[nl + 1];
#pragma unroll
            for (int half = 0; half < 2; half++) {
                int m = m0 + wm * 64 + mf * 16 + (lid >> 2) + half * 8;
                float v0 = acc[mf][nf][half * 2 + 0] + b0;
                float v1 = acc[mf][nf][half * 2 + 1] + b1;
                int b = m >> 11, s = m & (Ss - 1);
                int hh = n >> 6, d = n & (HD - 1);
                size_t o = (((size_t)(b * Hh + hh)) * Ss + s) * HD + d;
                if (z == 0) {          // Q: pre-scale + split hi/lo
                    v0 *= QSCALE; v1 *= QSCALE;
                    __half h0, l0, h1, l1;
                    split2h(v0, h0, l0); split2h(v1, h1, l1);
                    *(__half2*)(g_qh + o) = __half2(h0, h1);
                    *(__half2*)(g_ql + o) = __half2(l0, l1);
                } else {               // K/V: single fp16
                    __half* dst = (z == 1) ? g_kh : g_vh;
                    *(__half2*)(dst + o) = __floats2half2_rn(v0, v1);
                }
            }
        }
    }
}

// Output GEMM: out = (ch+cl) @ Wo16^T + bo, fp32 result.
__global__ __launch_bounds__(256)
void gemm_out(const float* __restrict__ bias, float* __restrict__ Cout)
{
    extern __shared__ char smem[];
    const uint32_t sb = smem_to_u32(smem);
    float* biasS = (float*)(smem + 2 * BUF3_B);

    const int tid = threadIdx.x, wid = tid >> 5, lid = tid & 31;
    const int wm = wid >> 2, wn = wid & 3;
    const int m0 = blockIdx.y * 128, n0 = blockIdx.x * 128;

    const __half* W16 = g_w + (size_t)3 * Dd * Dd;

    if (tid < 128) biasS[tid] = bias[n0 + tid];

    float acc[4][4][4];
#pragma unroll
    for (int i = 0; i < 4; i++)
#pragma unroll
        for (int j = 0; j < 4; j++)
#pragma unroll
            for (int k = 0; k < 4; k++) acc[i][j][k] = 0.f;

    auto issue = [&](int kt, int buf) {
        const int kc = kt * 32;
#pragma unroll
        for (int i = 0; i < 6; i++) {
            int idx = tid + i * 256;
            int tile = idx >> 9, w = idx & 511;
            int r = w >> 2, seg = (w & 3) * 16;
            uint32_t dst = sb + buf * BUF3_B + tile * TILE_B + r * 80 + seg;
            const char* src;
            if (tile == 0)      src = (const char*)(g_ch + (size_t)(m0 + r) * Dd + kc) + seg;
            else if (tile == 1) src = (const char*)(g_cl + (size_t)(m0 + r) * Dd + kc) + seg;
            else                src = (const char*)(W16 + (size_t)(n0 + r) * Dd + kc) + seg;
            cp_async16(dst, src);
        }
        cp_commit();
    };

    issue(0, 0);
    int buf = 0;
    const int arow0 = wm * 64 + (lid & 15);
    const int abyte0 = (lid >> 4) * 16;
    const int brow0 = wn * 32 + ((lid >> 4) << 3) + (lid & 7);
    const int bbyte0 = ((lid >> 3) & 1) * 16;

    for (int kt = 0; kt < 32; kt++) {
        cp_wait<0>();
        __syncthreads();
        if (kt + 1 < 32) issue(kt + 1, buf ^ 1);

        const uint32_t tAh = sb + buf * BUF3_B;
        const uint32_t tAl = tAh + TILE_B;
        const uint32_t tBh = tAh + 2 * TILE_B;
        GEMM_KT_BODY(tAh, tAl, tBh)
        buf ^= 1;
    }

#pragma unroll
    for (int mf = 0; mf < 4; mf++) {
#pragma unroll
        for (int nf = 0; nf < 4; nf++) {
            int nl = wn * 32 + nf * 8 + (lid & 3) * 2;
            int n = n0 + nl;
            float b0 = biasS[nl], b1 = biasS[nl + 1];
#pragma unroll
            for (int half = 0; half < 2; half++) {
                int m = m0 + wm * 64 + mf * 16 + (lid >> 2) + half * 8;
                *(float2*)(Cout + (size_t)m * Dd + n) =
                    make_float2(acc[mf][nf][half * 2 + 0] + b0,
                                acc[mf][nf][half * 2 + 1] + b1);
            }
        }
    }
}

// ---------------------------------------------------------------------------
// Tensor-core causal flash attention, fp16 2-term (q/P split, k/v single).
// q-tile 128 rows, 256 threads / 8 warps; paired (pr, 15-pr) -> uniform work.
// smem 72KB -> 2 CTAs/SM co-residency hides softmax serialization.
// ---------------------------------------------------------------------------
#define AT_STRIDE 144
#define QT_B     (128 * AT_STRIDE)           // 18432
#define KV_TILE  (64 * AT_STRIDE)            // 9216
#define KV0      (2 * QT_B)                  // 36864
#define KV_STAGE (2 * KV_TILE)               // 18432 (k + v)
#define ATTN_SMEM (KV0 + 2 * KV_STAGE)       // 73728

__global__ __launch_bounds__(256, 2)
void attn_mma()
{
    extern __shared__ char smem[];
    const uint32_t sb = smem_to_u32(smem);
    const int pr = blockIdx.x;                 // pair index 0..7
    const int bh = blockIdx.y;
    const int b = bh >> 4, h = bh & 15;
    const int tid = threadIdx.x, wid = tid >> 5, lid = tid & 31;

    const __half* kbase = g_kh + (size_t)bh * Ss * HD;
    const __half* vbase = g_vh + (size_t)bh * Ss * HD;

    auto issue = [&](int kt, int bf) {
#pragma unroll
        for (int i = 0; i < 4; i++) {
            int idx = tid + i * 256;
            int t = idx >> 9, w = idx & 511;
            int r = w >> 3, c = w & 7;
            const __half* src = (t ? vbase : kbase) + (size_t)(kt * 64 + r) * HD + c * 8;
            cp_async16(sb + KV0 + bf * KV_STAGE + t * KV_TILE + r * AT_STRIDE + c * 16, src);
        }
        cp_commit();
    };

    const uint32_t qrowb = (wid * 16 + (lid & 15)) * AT_STRIDE + (lid >> 4) * 16;
    const uint32_t krowb = (((lid >> 4) << 3) + (lid & 7)) * AT_STRIDE + ((lid >> 3) & 1) * 16;
    const uint32_t vrowb = (lid & 15) * AT_STRIDE + ((lid >> 4) & 1) * 16;
    int buf = 0;

    for (int half_t = 0; half_t < 2; half_t++) {
        const int qt = half_t ? (15 - pr) : pr;       // q-tile of 128 rows
        const __half* QH = g_qh + ((size_t)bh * Ss + qt * 128) * HD;
        const __half* QL = g_ql + ((size_t)bh * Ss + qt * 128) * HD;

        // Q tile (qh, ql): 128 rows x 128B each
#pragma unroll
        for (int i = 0; i < 8; i++) {
            int idx = tid + i * 256;
            int s = idx >> 10, w = idx & 1023;
            int r = w >> 3, c = w & 7;
            cp_async16(sb + s * QT_B + r * AT_STRIDE + c * 16,
                       (s ? QL : QH) + (size_t)r * HD + c * 8);
        }
        cp_commit();
        issue(0, buf);

        float acc[8][4];
#pragma unroll
        for (int i = 0; i < 8; i++)
#pragma unroll
            for (int j = 0; j < 4; j++) acc[i][j] = 0.f;
        float mrow[2] = { -1e30f, -1e30f }, lrow[2] = { 0.f, 0.f };

        const int nk = 2 * qt + 2;
        for (int kt = 0; kt < nk; kt++) {
            cp_wait<0>();
            __syncthreads();          // data ready + prior reads of buf^1 done
            if (kt + 1 < nk) issue(kt + 1, buf ^ 1);

            const uint32_t kbt = sb + KV0 + buf * KV_STAGE;
            const uint32_t vbt = kbt + KV_TILE;

            // ---- S = (qh + ql) @ k16^T  (2 MMA terms) ----
            float sf[8][4];
#pragma unroll
            for (int i = 0; i < 8; i++)
#pragma unroll
                for (int j = 0; j < 4; j++) sf[i][j] = 0.f;

#pragma unroll
            for (int kk = 0; kk < 4; kk++) {
                uint32_t aH[4], aL[4];
                ldsm_x4(aH, sb + qrowb + kk * 32);
                ldsm_x4(aL, sb + QT_B + qrowb + kk * 32);
#pragma unroll
                for (int nf2 = 0; nf2 < 4; nf2++) {
                    uint32_t rH[4];
                    ldsm_x4(rH, kbt + nf2 * 16 * AT_STRIDE + krowb + kk * 32);
                    mma16816(sf[nf2 * 2],     aH, rH);
                    mma16816(sf[nf2 * 2 + 1], aH, rH + 2);
                    mma16816(sf[nf2 * 2],     aL, rH);
                    mma16816(sf[nf2 * 2 + 1], aL, rH + 2);
                }
            }

            if (kt >= 2 * qt) {     // diagonal region: causal mask
                int r0 = wid * 16 + (lid >> 2);
                int coff = kt * 64 - qt * 128;
#pragma unroll
                for (int nf = 0; nf < 8; nf++) {
                    int c0 = coff + nf * 8 + (lid & 3) * 2;
                    if (c0     > r0)     sf[nf][0] = -1e30f;
                    if (c0 + 1 > r0)     sf[nf][1] = -1e30f;
                    if (c0     > r0 + 8) sf[nf][2] = -1e30f;
                    if (c0 + 1 > r0 + 8) sf[nf][3] = -1e30f;
                }
            }

            // ---- online softmax in exp2 domain ----
#pragma unroll
            for (int hf = 0; hf < 2; hf++) {
                float mx = -1e30f;
#pragma unroll
                for (int nf = 0; nf < 8; nf++)
                    mx = fmaxf(mx, fmaxf(sf[nf][hf * 2], sf[nf][hf * 2 + 1]));
                mx = fmaxf(mx, __shfl_xor_sync(0xffffffffu, mx, 1));
                mx = fmaxf(mx, __shfl_xor_sync(0xffffffffu, mx, 2));
                float mnew = fmaxf(mrow[hf], mx);
                float alpha = ex2(mrow[hf] - mnew);
                mrow[hf] = mnew;
                float sum = 0.f;
#pragma unroll
                for (int nf = 0; nf < 8; nf++) {
                    sf[nf][hf * 2]     = ex2(sf[nf][hf * 2] - mnew);
                    sf[nf][hf * 2 + 1] = ex2(sf[nf][hf * 2 + 1] - mnew);
                    sum += sf[nf][hf * 2] + sf[nf][hf * 2 + 1];
                }
                sum += __shfl_xor_sync(0xffffffffu, sum, 1);
                sum += __shfl_xor_sync(0xffffffffu, sum, 2);
                lrow[hf] = lrow[hf] * alpha + sum;
#pragma unroll
                for (int nf = 0; nf < 8; nf++) {
                    acc[nf][hf * 2]     *= alpha;
                    acc[nf][hf * 2 + 1] *= alpha;
                }
            }

            // ---- O += (Ph + Pl) @ v16  (2 MMA terms) ----
#pragma unroll
            for (int kk2 = 0; kk2 < 4; kk2++) {
                uint32_t aPh[4], aPl[4];
#pragma unroll
                for (int q = 0; q < 2; q++) {
                    const float* c = sf[kk2 * 2 + q];
                    float h0f = __half2float(__float2half(c[0]));
                    float h1f = __half2float(__float2half(c[1]));
                    float h2f = __half2float(__float2half(c[2]));
                    float h3f = __half2float(__float2half(c[3]));
                    aPh[q * 2]     = packh(c[0], c[1]);
                    aPh[q * 2 + 1] = packh(c[2], c[3]);
                    aPl[q * 2]     = packh(c[0] - h0f, c[1] - h1f);
                    aPl[q * 2 + 1] = packh(c[2] - h2f, c[3] - h3f);
                }
#pragma unroll
                for (int nf2 = 0; nf2 < 4; nf2++) {
                    uint32_t vH[4];
                    ldsm_x4_t(vH, vbt + (kk2 * 16) * AT_STRIDE + vrowb + nf2 * 32);
                    mma16816(acc[nf2 * 2],     aPh, vH);
                    mma16816(acc[nf2 * 2 + 1], aPh, vH + 2);
                    mma16816(acc[nf2 * 2],     aPl, vH);
                    mma16816(acc[nf2 * 2 + 1], aPl, vH + 2);
                }
            }
            buf ^= 1;
        }

        // ---- epilogue: ctx -> fp16 hi/lo (B,S,D) ----
        float inv0 = 1.f / lrow[0], inv1 = 1.f / lrow[1];
        int r0 = qt * 128 + wid * 16 + (lid >> 2);
#pragma unroll
        for (int nf = 0; nf < 8; nf++) {
            int d0 = h * HD + nf * 8 + (lid & 3) * 2;
            size_t o0 = ((size_t)b * Ss + r0) * Dd + d0;
            size_t o1 = ((size_t)b * Ss + r0 + 8) * Dd + d0;
            float v0 = acc[nf][0] * inv0, v1 = acc[nf][1] * inv0;
            float v2 = acc[nf][2] * inv1, v3 = acc[nf][3] * inv1;
            __half h0, l0, h1, l1, h2, l2, h3, l3;
            split2h(v0, h0, l0); split2h(v1, h1, l1);
            split2h(v2, h2, l2); split2h(v3, h3, l3);
            *(__half2*)(g_ch + o0) = __half2(h0, h1);
            *(__half2*)(g_cl + o0) = __half2(l0, l1);
            *(__half2*)(g_ch + o1) = __half2(h2, h3);
            *(__half2*)(g_cl + o1) = __half2(l2, l3);
        }
        __syncthreads();    // Q/KV smem reuse safe before next half's loads
    }
}

// ---------------------------------------------------------------------------
extern "C" void kernel_launch(void* const* d_in, const int* in_sizes, int n_in,
                              void* d_out, int out_size)
{
    const float* x  = (const float*)d_in[0];
    const float* Wq = (const float*)d_in[1];
    const float* bq = (const float*)d_in[2];
    const float* Wk = (const float*)d_in[3];
    const float* bk = (const float*)d_in[4];
    const float* Wv = (const float*)d_in[5];
    const float* bv = (const float*)d_in[6];
    const float* Wo = (const float*)d_in[7];
    const float* bo = (const float*)d_in[8];
    float* out = (float*)d_out;

    cudaFuncSetAttribute(gemm_qkv, cudaFuncAttributeMaxDynamicSharedMemorySize, GEMM_SMEM);
    cudaFuncSetAttribute(gemm_out, cudaFuncAttributeMaxDynamicSharedMemorySize, GEMM_SMEM);
    cudaFuncSetAttribute(attn_mma, cudaFuncAttributeMaxDynamicSharedMemorySize, ATTN_SMEM);

    split_all<<<(Mtot * Dd + 4 * Dd * Dd) / 1024, 256>>>(x, Wq, Wk, Wv, Wo);

    gemm_qkv<<<dim3(Dd / 128, Mtot / 128, 3), 256, GEMM_SMEM>>>(bq, bk, bv);

    attn_mma<<<dim3(8, Bb * Hh), 256, ATTN_SMEM>>>();

    gemm_out<<<dim3(Dd / 128, Mtot / 128), 256, GEMM_SMEM>>>(bo, out);
}

// round 10
// speedup vs baseline: 5.5031x; 1.1659x over previous
#include <cuda_runtime.h>
#include <cuda_fp16.h>
#include <cstdint>

#define Bb 2
#define Ss 2048
#define Dd 1024
#define Hh 16
#define HD 64
#define Mtot (Bb*Ss)   // 4096
#define QSCALE 0.1803368801111244f   // 0.125 * log2(e): softmax in exp2 domain

// ---------------- scratch (static device arrays; alloc APIs forbidden) -----
__device__ __align__(16) __half g_qh[Bb*Hh*Ss*HD];  // q split hi/lo (B,H,S,hd)
__device__ __align__(16) __half g_ql[Bb*Hh*Ss*HD];
__device__ __align__(16) __half g_kh[Bb*Hh*Ss*HD];  // k single fp16
__device__ __align__(16) __half g_vh[Bb*Hh*Ss*HD];  // v single fp16
__device__ __align__(16) __half g_xh[Mtot*Dd];      // x split hi/lo
__device__ __align__(16) __half g_xl[Mtot*Dd];
__device__ __align__(16) __half g_w [4u*Dd*Dd];     // Wq,Wk,Wv,Wo single fp16
__device__ __align__(16) __half g_ch[Mtot*Dd];      // ctx split hi/lo (B,S,D)
__device__ __align__(16) __half g_cl[Mtot*Dd];

// ---------------- PTX helpers (sm_80/75-era only) --------------------------
__device__ __forceinline__ uint32_t smem_to_u32(const void* p) {
    uint32_t a;
    asm("{ .reg .u64 t; cvta.to.shared.u64 t, %1; cvt.u32.u64 %0, t; }"
        : "=r"(a) : "l"(p));
    return a;
}
__device__ __forceinline__ void cp_async16(uint32_t dst, const void* src) {
    asm volatile("cp.async.cg.shared.global [%0], [%1], 16;"
                 :: "r"(dst), "l"(src) : "memory");
}
__device__ __forceinline__ void cp_commit() {
    asm volatile("cp.async.commit_group;" ::: "memory");
}
template<int N> __device__ __forceinline__ void cp_wait() {
    asm volatile("cp.async.wait_group %0;" :: "n"(N) : "memory");
}
__device__ __forceinline__ void ldsm_x4(uint32_t* r, uint32_t addr) {
    asm volatile("ldmatrix.sync.aligned.m8n8.x4.shared.b16 {%0,%1,%2,%3}, [%4];"
                 : "=r"(r[0]), "=r"(r[1]), "=r"(r[2]), "=r"(r[3]) : "r"(addr));
}
__device__ __forceinline__ void ldsm_x4_t(uint32_t* r, uint32_t addr) {
    asm volatile("ldmatrix.sync.aligned.m8n8.x4.trans.shared.b16 {%0,%1,%2,%3}, [%4];"
                 : "=r"(r[0]), "=r"(r[1]), "=r"(r[2]), "=r"(r[3]) : "r"(addr));
}
__device__ __forceinline__ void mma16816(float* c, const uint32_t* a, const uint32_t* b) {
    asm volatile("mma.sync.aligned.m16n8k16.row.col.f32.f16.f16.f32 "
                 "{%0,%1,%2,%3}, {%4,%5,%6,%7}, {%8,%9}, {%0,%1,%2,%3};"
                 : "+f"(c[0]), "+f"(c[1]), "+f"(c[2]), "+f"(c[3])
                 : "r"(a[0]), "r"(a[1]), "r"(a[2]), "r"(a[3]), "r"(b[0]), "r"(b[1]));
}
__device__ __forceinline__ float ex2(float x) {
    float y;
    asm("ex2.approx.ftz.f32 %0, %1;" : "=f"(y) : "f"(x));
    return y;
}

// ---------------- fp32 -> fp16 hi/lo split ---------------------------------
__device__ __forceinline__ void split2h(float v, __half& h, __half& l) {
    h = __float2half(v);
    l = __float2half(v - __half2float(h));
}
__device__ __forceinline__ uint32_t packh(float a, float b) {
    __half2 t = __floats2half2_rn(a, b);
    return *(uint32_t*)&t;
}

// One launch: split x (first 4M elems, hi/lo) + round all 4 weights (single).
__global__ __launch_bounds__(256)
void split_all(const float* __restrict__ x,  const float* __restrict__ Wq,
               const float* __restrict__ Wk, const float* __restrict__ Wv,
               const float* __restrict__ Wo)
{
    int i = (blockIdx.x * 256 + threadIdx.x) * 4;
    if (i < Mtot * Dd) {
        float4 v = *(const float4*)(x + i);
        __half h0, h1, h2, h3, l0, l1, l2, l3;
        split2h(v.x, h0, l0); split2h(v.y, h1, l1);
        split2h(v.z, h2, l2); split2h(v.w, h3, l3);
        *(__half2*)(g_xh + i)     = __half2(h0, h1);
        *(__half2*)(g_xh + i + 2) = __half2(h2, h3);
        *(__half2*)(g_xl + i)     = __half2(l0, l1);
        *(__half2*)(g_xl + i + 2) = __half2(l2, l3);
    } else {
        int j = i - Mtot * Dd;
        int w = j >> 20;                 // Dd*Dd = 2^20
        int r = j & (Dd * Dd - 1);
        const float* src = (w == 0 ? Wq : w == 1 ? Wk : w == 2 ? Wv : Wo) + r;
        float4 v = *(const float4*)src;
        *(__half2*)(g_w + j)     = __floats2half2_rn(v.x, v.y);
        *(__half2*)(g_w + j + 2) = __floats2half2_rn(v.z, v.w);
    }
}

// ---------------------------------------------------------------------------
// mma.sync GEMM core. Block 128x128, 8 warps, double-buffered cp.async.
// Q / out paths: C = (Ah+Al) @ B16^T (2 terms). K/V paths: C = Ah @ B16^T
// (1 term — the dropped correction is smaller than the subsequent fp16
// storage rounding of k/v).
// ---------------------------------------------------------------------------
#define TILE_B   10240                 // 128 rows * 80 B
#define BUF3_B   (3 * TILE_B)
#define GEMM_SMEM (2 * BUF3_B + 512)   // 61952

#define GEMM_KT_BODY2(tAh, tAl, tBh)                                           \
    _Pragma("unroll")                                                          \
    for (int kk = 0; kk < 2; kk++) {                                           \
        const int ab = kk * 32 + abyte0;                                       \
        const int bb = kk * 32 + bbyte0;                                       \
        uint32_t aH[4][4], aL[4][4], bH[4][2];                                 \
        _Pragma("unroll")                                                      \
        for (int mf = 0; mf < 4; mf++) {                                       \
            uint32_t ro = (arow0 + mf * 16) * 80;                              \
            ldsm_x4(aH[mf], (tAh) + ro + ab);                                  \
            ldsm_x4(aL[mf], (tAl) + ro + ab);                                  \
        }                                                                      \
        _Pragma("unroll")                                                      \
        for (int nf2 = 0; nf2 < 2; nf2++) {                                    \
            uint32_t ro = (brow0 + nf2 * 16) * 80;                             \
            uint32_t r4[4];                                                    \
            ldsm_x4(r4, (tBh) + ro + bb);                                      \
            bH[nf2 * 2][0] = r4[0]; bH[nf2 * 2][1] = r4[1];                    \
            bH[nf2 * 2 + 1][0] = r4[2]; bH[nf2 * 2 + 1][1] = r4[3];            \
        }                                                                      \
        _Pragma("unroll")                                                      \
        for (int mf = 0; mf < 4; mf++)                                         \
            _Pragma("unroll")                                                  \
            for (int nf = 0; nf < 4; nf++)                                     \
                mma16816(acc[mf][nf], aH[mf], bH[nf]);                         \
        _Pragma("unroll")                                                      \
        for (int mf = 0; mf < 4; mf++)                                         \
            _Pragma("unroll")                                                  \
            for (int nf = 0; nf < 4; nf++)                                     \
                mma16816(acc[mf][nf], aL[mf], bH[nf]);                         \
    }

// Fused QKV projection: gridDim.z selects Q(2-term)/K(1-term)/V(1-term).
__global__ __launch_bounds__(256)
void gemm_qkv(const float* __restrict__ bq, const float* __restrict__ bk,
              const float* __restrict__ bv)
{
    extern __shared__ char smem[];
    const uint32_t sb = smem_to_u32(smem);
    float* biasS = (float*)(smem + 2 * BUF3_B);

    const int tid = threadIdx.x, wid = tid >> 5, lid = tid & 31;
    const int wm = wid >> 2, wn = wid & 3;
    const int m0 = blockIdx.y * 128, n0 = blockIdx.x * 128;
    const int z = blockIdx.z;
    const bool doLo = (z == 0);

    const float* bias = (z == 0) ? bq : (z == 1) ? bk : bv;
    const __half* W16 = g_w + (size_t)z * Dd * Dd;

    if (tid < 128) biasS[tid] = bias[n0 + tid];

    float acc[4][4][4];
#pragma unroll
    for (int i = 0; i < 4; i++)
#pragma unroll
        for (int j = 0; j < 4; j++)
#pragma unroll
            for (int k = 0; k < 4; k++) acc[i][j][k] = 0.f;

    auto issue = [&](int kt, int buf) {
        const int kc = kt * 32;
#pragma unroll
        for (int i = 0; i < 6; i++) {
            int idx = tid + i * 256;
            int tile = idx >> 9, w = idx & 511;
            if (tile == 1 && !doLo) continue;      // xl unused for K/V
            int r = w >> 2, seg = (w & 3) * 16;
            uint32_t dst = sb + buf * BUF3_B + tile * TILE_B + r * 80 + seg;
            const char* src;
            if (tile == 0)      src = (const char*)(g_xh + (size_t)(m0 + r) * Dd + kc) + seg;
            else if (tile == 1) src = (const char*)(g_xl + (size_t)(m0 + r) * Dd + kc) + seg;
            else                src = (const char*)(W16 + (size_t)(n0 + r) * Dd + kc) + seg;
            cp_async16(dst, src);
        }
        cp_commit();
    };

    issue(0, 0);
    int buf = 0;
    const int arow0 = wm * 64 + (lid & 15);
    const int abyte0 = (lid >> 4) * 16;
    const int brow0 = wn * 32 + ((lid >> 4) << 3) + (lid & 7);
    const int bbyte0 = ((lid >> 3) & 1) * 16;

    for (int kt = 0; kt < 32; kt++) {
        cp_wait<0>();
        __syncthreads();               // data ready + prior reads of buf^1 done
        if (kt + 1 < 32) issue(kt + 1, buf ^ 1);

        const uint32_t tAh = sb + buf * BUF3_B;
        const uint32_t tAl = tAh + TILE_B;
        const uint32_t tBh = tAh + 2 * TILE_B;

#pragma unroll
        for (int kk = 0; kk < 2; kk++) {
            const int ab = kk * 32 + abyte0;
            const int bb = kk * 32 + bbyte0;
            uint32_t aH[4][4], bH[4][2];
#pragma unroll
            for (int mf = 0; mf < 4; mf++)
                ldsm_x4(aH[mf], tAh + (arow0 + mf * 16) * 80 + ab);
#pragma unroll
            for (int nf2 = 0; nf2 < 2; nf2++) {
                uint32_t ro = (brow0 + nf2 * 16) * 80;
                uint32_t r4[4];
                ldsm_x4(r4, tBh + ro + bb);
                bH[nf2 * 2][0] = r4[0]; bH[nf2 * 2][1] = r4[1];
                bH[nf2 * 2 + 1][0] = r4[2]; bH[nf2 * 2 + 1][1] = r4[3];
            }
#pragma unroll
            for (int mf = 0; mf < 4; mf++)
#pragma unroll
                for (int nf = 0; nf < 4; nf++)
                    mma16816(acc[mf][nf], aH[mf], bH[nf]);
            if (doLo) {
                uint32_t aL[4][4];
#pragma unroll
                for (int mf = 0; mf < 4; mf++)
                    ldsm_x4(aL[mf], tAl + (arow0 + mf * 16) * 80 + ab);
#pragma unroll
                for (int mf = 0; mf < 4; mf++)
#pragma unroll
                    for (int nf = 0; nf < 4; nf++)
                        mma16816(acc[mf][nf], aL[mf], bH[nf]);
            }
        }
        buf ^= 1;
    }

#pragma unroll
    for (int mf = 0; mf < 4; mf++) {
#pragma unroll
        for (int nf = 0; nf < 4; nf++) {
            int nl = wn * 32 + nf * 8 + (lid & 3) * 2;
            int n = n0 + nl;
            float b0 = biasS[nl], b1 = biasS[nl + 1];
#pragma unroll
            for (int half = 0; half < 2; half++) {
                int m = m0 + wm * 64 + mf * 16 + (lid >> 2) + half * 8;
                float v0 = acc[mf][nf][half * 2 + 0] + b0;
                float v1 = acc[mf][nf][half * 2 + 1] + b1;
                int b = m >> 11, s = m & (Ss - 1);
                int hh = n >> 6, d = n & (HD - 1);
                size_t o = (((size_t)(b * Hh + hh)) * Ss + s) * HD + d;
                if (z == 0) {          // Q: pre-scale + split hi/lo
                    v0 *= QSCALE; v1 *= QSCALE;
                    __half h0, l0, h1, l1;
                    split2h(v0, h0, l0); split2h(v1, h1, l1);
                    *(__half2*)(g_qh + o) = __half2(h0, h1);
                    *(__half2*)(g_ql + o) = __half2(l0, l1);
                } else {               // K/V: single fp16
                    __half* dst = (z == 1) ? g_kh : g_vh;
                    *(__half2*)(dst + o) = __floats2half2_rn(v0, v1);
                }
            }
        }
    }
}

// Output GEMM: out = (ch+cl) @ Wo16^T + bo, fp32 result (2 terms).
__global__ __launch_bounds__(256)
void gemm_out(const float* __restrict__ bias, float* __restrict__ Cout)
{
    extern __shared__ char smem[];
    const uint32_t sb = smem_to_u32(smem);
    float* biasS = (float*)(smem + 2 * BUF3_B);

    const int tid = threadIdx.x, wid = tid >> 5, lid = tid & 31;
    const int wm = wid >> 2, wn = wid & 3;
    const int m0 = blockIdx.y * 128, n0 = blockIdx.x * 128;

    const __half* W16 = g_w + (size_t)3 * Dd * Dd;

    if (tid < 128) biasS[tid] = bias[n0 + tid];

    float acc[4][4][4];
#pragma unroll
    for (int i = 0; i < 4; i++)
#pragma unroll
        for (int j = 0; j < 4; j++)
#pragma unroll
            for (int k = 0; k < 4; k++) acc[i][j][k] = 0.f;

    auto issue = [&](int kt, int buf) {
        const int kc = kt * 32;
#pragma unroll
        for (int i = 0; i < 6; i++) {
            int idx = tid + i * 256;
            int tile = idx >> 9, w = idx & 511;
            int r = w >> 2, seg = (w & 3) * 16;
            uint32_t dst = sb + buf * BUF3_B + tile * TILE_B + r * 80 + seg;
            const char* src;
            if (tile == 0)      src = (const char*)(g_ch + (size_t)(m0 + r) * Dd + kc) + seg;
            else if (tile == 1) src = (const char*)(g_cl + (size_t)(m0 + r) * Dd + kc) + seg;
            else                src = (const char*)(W16 + (size_t)(n0 + r) * Dd + kc) + seg;
            cp_async16(dst, src);
        }
        cp_commit();
    };

    issue(0, 0);
    int buf = 0;
    const int arow0 = wm * 64 + (lid & 15);
    const int abyte0 = (lid >> 4) * 16;
    const int brow0 = wn * 32 + ((lid >> 4) << 3) + (lid & 7);
    const int bbyte0 = ((lid >> 3) & 1) * 16;

    for (int kt = 0; kt < 32; kt++) {
        cp_wait<0>();
        __syncthreads();
        if (kt + 1 < 32) issue(kt + 1, buf ^ 1);

        const uint32_t tAh = sb + buf * BUF3_B;
        const uint32_t tAl = tAh + TILE_B;
        const uint32_t tBh = tAh + 2 * TILE_B;
        GEMM_KT_BODY2(tAh, tAl, tBh)
        buf ^= 1;
    }

#pragma unroll
    for (int mf = 0; mf < 4; mf++) {
#pragma unroll
        for (int nf = 0; nf < 4; nf++) {
            int nl = wn * 32 + nf * 8 + (lid & 3) * 2;
            int n = n0 + nl;
            float b0 = biasS[nl], b1 = biasS[nl + 1];
#pragma unroll
            for (int half = 0; half < 2; half++) {
                int m = m0 + wm * 64 + mf * 16 + (lid >> 2) + half * 8;
                *(float2*)(Cout + (size_t)m * Dd + n) =
                    make_float2(acc[mf][nf][half * 2 + 0] + b0,
                                acc[mf][nf][half * 2 + 1] + b1);
            }
        }
    }
}

// ---------------------------------------------------------------------------
// Tensor-core causal flash attention, fp16 2-term (q/P split, k/v single).
// q-tile 128 rows, 256 threads / 8 warps; paired (pr, 15-pr) -> uniform work.
// ---------------------------------------------------------------------------
#define AT_STRIDE 144
#define QT_B     (128 * AT_STRIDE)           // 18432
#define KV_TILE  (64 * AT_STRIDE)            // 9216
#define KV0      (2 * QT_B)                  // 36864
#define KV_STAGE (2 * KV_TILE)               // 18432 (k + v)
#define ATTN_SMEM (KV0 + 2 * KV_STAGE)       // 73728

__global__ __launch_bounds__(256, 2)
void attn_mma()
{
    extern __shared__ char smem[];
    const uint32_t sb = smem_to_u32(smem);
    const int pr = blockIdx.x;                 // pair index 0..7
    const int bh = blockIdx.y;
    const int b = bh >> 4, h = bh & 15;
    const int tid = threadIdx.x, wid = tid >> 5, lid = tid & 31;

    const __half* kbase = g_kh + (size_t)bh * Ss * HD;
    const __half* vbase = g_vh + (size_t)bh * Ss * HD;

    auto issue = [&](int kt, int bf) {
#pragma unroll
        for (int i = 0; i < 4; i++) {
            int idx = tid + i * 256;
            int t = idx >> 9, w = idx & 511;
            int r = w >> 3, c = w & 7;
            const __half* src = (t ? vbase : kbase) + (size_t)(kt * 64 + r) * HD + c * 8;
            cp_async16(sb + KV0 + bf * KV_STAGE + t * KV_TILE + r * AT_STRIDE + c * 16, src);
        }
        cp_commit();
    };

    const uint32_t qrowb = (wid * 16 + (lid & 15)) * AT_STRIDE + (lid >> 4) * 16;
    const uint32_t krowb = (((lid >> 4) << 3) + (lid & 7)) * AT_STRIDE + ((lid >> 3) & 1) * 16;
    const uint32_t vrowb = (lid & 15) * AT_STRIDE + ((lid >> 4) & 1) * 16;
    int buf = 0;

    for (int half_t = 0; half_t < 2; half_t++) {
        const int qt = half_t ? (15 - pr) : pr;       // q-tile of 128 rows
        const __half* QH = g_qh + ((size_t)bh * Ss + qt * 128) * HD;
        const __half* QL = g_ql + ((size_t)bh * Ss + qt * 128) * HD;

        // Q tile (qh, ql): 128 rows x 128B each
#pragma unroll
        for (int i = 0; i < 8; i++) {
            int idx = tid + i * 256;
            int s = idx >> 10, w = idx & 1023;
            int r = w >> 3, c = w & 7;
            cp_async16(sb + s * QT_B + r * AT_STRIDE + c * 16,
                       (s ? QL : QH) + (size_t)r * HD + c * 8);
        }
        cp_commit();
        issue(0, buf);

        float acc[8][4];
#pragma unroll
        for (int i = 0; i < 8; i++)
#pragma unroll
            for (int j = 0; j < 4; j++) acc[i][j] = 0.f;
        float mrow[2] = { -1e30f, -1e30f }, lrow[2] = { 0.f, 0.f };

        const int nk = 2 * qt + 2;
        for (int kt = 0; kt < nk; kt++) {
            cp_wait<0>();
            __syncthreads();          // data ready + prior reads of buf^1 done
            if (kt + 1 < nk) issue(kt + 1, buf ^ 1);

            const uint32_t kbt = sb + KV0 + buf * KV_STAGE;
            const uint32_t vbt = kbt + KV_TILE;

            // ---- S = (qh + ql) @ k16^T  (2 MMA terms) ----
            float sf[8][4];
#pragma unroll
            for (int i = 0; i < 8; i++)
#pragma unroll
                for (int j = 0; j < 4; j++) sf[i][j] = 0.f;

#pragma unroll
            for (int kk = 0; kk < 4; kk++) {
                uint32_t aH[4], aL[4];
                ldsm_x4(aH, sb + qrowb + kk * 32);
                ldsm_x4(aL, sb + QT_B + qrowb + kk * 32);
#pragma unroll
                for (int nf2 = 0; nf2 < 4; nf2++) {
                    uint32_t rH[4];
                    ldsm_x4(rH, kbt + nf2 * 16 * AT_STRIDE + krowb + kk * 32);
                    mma16816(sf[nf2 * 2],     aH, rH);
                    mma16816(sf[nf2 * 2 + 1], aH, rH + 2);
                    mma16816(sf[nf2 * 2],     aL, rH);
                    mma16816(sf[nf2 * 2 + 1], aL, rH + 2);
                }
            }

            if (kt >= 2 * qt) {     // diagonal region: causal mask
                int r0 = wid * 16 + (lid >> 2);
                int coff = kt * 64 - qt * 128;
#pragma unroll
                for (int nf = 0; nf < 8; nf++) {
                    int c0 = coff + nf * 8 + (lid & 3) * 2;
                    if (c0     > r0)     sf[nf][0] = -1e30f;
                    if (c0 + 1 > r0)     sf[nf][1] = -1e30f;
                    if (c0     > r0 + 8) sf[nf][2] = -1e30f;
                    if (c0 + 1 > r0 + 8) sf[nf][3] = -1e30f;
                }
            }

            // ---- online softmax in exp2 domain ----
#pragma unroll
            for (int hf = 0; hf < 2; hf++) {
                float mx = -1e30f;
#pragma unroll
                for (int nf = 0; nf < 8; nf++)
                    mx = fmaxf(mx, fmaxf(sf[nf][hf * 2], sf[nf][hf * 2 + 1]));
                mx = fmaxf(mx, __shfl_xor_sync(0xffffffffu, mx, 1));
                mx = fmaxf(mx, __shfl_xor_sync(0xffffffffu, mx, 2));
                float mnew = fmaxf(mrow[hf], mx);
                float alpha = ex2(mrow[hf] - mnew);
                mrow[hf] = mnew;
                float sum = 0.f;
#pragma unroll
                for (int nf = 0; nf < 8; nf++) {
                    sf[nf][hf * 2]     = ex2(sf[nf][hf * 2] - mnew);
                    sf[nf][hf * 2 + 1] = ex2(sf[nf][hf * 2 + 1] - mnew);
                    sum += sf[nf][hf * 2] + sf[nf][hf * 2 + 1];
                }
                sum += __shfl_xor_sync(0xffffffffu, sum, 1);
                sum += __shfl_xor_sync(0xffffffffu, sum, 2);
                lrow[hf] = lrow[hf] * alpha + sum;
#pragma unroll
                for (int nf = 0; nf < 8; nf++) {
                    acc[nf][hf * 2]     *= alpha;
                    acc[nf][hf * 2 + 1] *= alpha;
                }
            }

            // ---- O += (Ph + Pl) @ v16  (2 MMA terms) ----
#pragma unroll
            for (int kk2 = 0; kk2 < 4; kk2++) {
                uint32_t aPh[4], aPl[4];
#pragma unroll
                for (int q = 0; q < 2; q++) {
                    const float* c = sf[kk2 * 2 + q];
                    float h0f = __half2float(__float2half(c[0]));
                    float h1f = __half2float(__float2half(c[1]));
                    float h2f = __half2float(__float2half(c[2]));
                    float h3f = __half2float(__float2half(c[3]));
                    aPh[q * 2]     = packh(c[0], c[1]);
                    aPh[q * 2 + 1] = packh(c[2], c[3]);
                    aPl[q * 2]     = packh(c[0] - h0f, c[1] - h1f);
                    aPl[q * 2 + 1] = packh(c[2] - h2f, c[3] - h3f);
                }
#pragma unroll
                for (int nf2 = 0; nf2 < 4; nf2++) {
                    uint32_t vH[4];
                    ldsm_x4_t(vH, vbt + (kk2 * 16) * AT_STRIDE + vrowb + nf2 * 32);
                    mma16816(acc[nf2 * 2],     aPh, vH);
                    mma16816(acc[nf2 * 2 + 1], aPh, vH + 2);
                    mma16816(acc[nf2 * 2],     aPl, vH);
                    mma16816(acc[nf2 * 2 + 1], aPl, vH + 2);
                }
            }
            buf ^= 1;
        }

        // ---- epilogue: ctx -> fp16 hi/lo (B,S,D) ----
        float inv0 = 1.f / lrow[0], inv1 = 1.f / lrow[1];
        int r0 = qt * 128 + wid * 16 + (lid >> 2);
#pragma unroll
        for (int nf = 0; nf < 8; nf++) {
            int d0 = h * HD + nf * 8 + (lid & 3) * 2;
            size_t o0 = ((size_t)b * Ss + r0) * Dd + d0;
            size_t o1 = ((size_t)b * Ss + r0 + 8) * Dd + d0;
            float v0 = acc[nf][0] * inv0, v1 = acc[nf][1] * inv0;
            float v2 = acc[nf][2] * inv1, v3 = acc[nf][3] * inv1;
            __half h0, l0, h1, l1, h2, l2, h3, l3;
            split2h(v0, h0, l0); split2h(v1, h1, l1);
            split2h(v2, h2, l2); split2h(v3, h3, l3);
            *(__half2*)(g_ch + o0) = __half2(h0, h1);
            *(__half2*)(g_cl + o0) = __half2(l0, l1);
            *(__half2*)(g_ch + o1) = __half2(h2, h3);
            *(__half2*)(g_cl + o1) = __half2(l2, l3);
        }
        __syncthreads();    // Q/KV smem reuse safe before next half's loads
    }
}

// ---------------------------------------------------------------------------
extern "C" void kernel_launch(void* const* d_in, const int* in_sizes, int n_in,
                              void* d_out, int out_size)
{
    const float* x  = (const float*)d_in[0];
    const float* Wq = (const float*)d_in[1];
    const float* bq = (const float*)d_in[2];
    const float* Wk = (const float*)d_in[3];
    const float* bk = (const float*)d_in[4];
    const float* Wv = (const float*)d_in[5];
    const float* bv = (const float*)d_in[6];
    const float* Wo = (const float*)d_in[7];
    const float* bo = (const float*)d_in[8];
    float* out = (float*)d_out;

    cudaFuncSetAttribute(gemm_qkv, cudaFuncAttributeMaxDynamicSharedMemorySize, GEMM_SMEM);
    cudaFuncSetAttribute(gemm_out, cudaFuncAttributeMaxDynamicSharedMemorySize, GEMM_SMEM);
    cudaFuncSetAttribute(attn_mma, cudaFuncAttributeMaxDynamicSharedMemorySize, ATTN_SMEM);

    split_all<<<(Mtot * Dd + 4 * Dd * Dd) / 1024, 256>>>(x, Wq, Wk, Wv, Wo);

    gemm_qkv<<<dim3(Dd / 128, Mtot / 128, 3), 256, GEMM_SMEM>>>(bq, bk, bv);

    attn_mma<<<dim3(8, Bb * Hh), 256, ATTN_SMEM>>>();

    gemm_out<<<dim3(Dd / 128, Mtot / 128), 256, GEMM_SMEM>>>(bo, out);
}

// round 11
// speedup vs baseline: 6.5401x; 1.1884x over previous
#include <cuda_runtime.h>
#include <cuda_fp16.h>
#include <cstdint>

#define Bb 2
#define Ss 2048
#define Dd 1024
#define Hh 16
#define HD 64
#define Mtot (Bb*Ss)   // 4096
#define QSCALE 0.1803368801111244f   // 0.125 * log2(e): softmax in exp2 domain

// ---------------- scratch (static device arrays; alloc APIs forbidden) -----
__device__ __align__(16) __half g_qh[Bb*Hh*Ss*HD];  // q split hi/lo (B,H,S,hd)
__device__ __align__(16) __half g_ql[Bb*Hh*Ss*HD];
__device__ __align__(16) __half g_kh[Bb*Hh*Ss*HD];  // k single fp16
__device__ __align__(16) __half g_vh[Bb*Hh*Ss*HD];  // v single fp16
__device__ __align__(16) __half g_xh[Mtot*Dd];      // x split hi/lo
__device__ __align__(16) __half g_xl[Mtot*Dd];
__device__ __align__(16) __half g_w [4u*Dd*Dd];     // Wq,Wk,Wv,Wo single fp16
__device__ __align__(16) __half g_c16[Mtot*Dd];     // ctx single fp16 (B,S,D)

// ---------------- PTX helpers (sm_80/75-era only) --------------------------
__device__ __forceinline__ uint32_t smem_to_u32(const void* p) {
    uint32_t a;
    asm("{ .reg .u64 t; cvta.to.shared.u64 t, %1; cvt.u32.u64 %0, t; }"
        : "=r"(a) : "l"(p));
    return a;
}
__device__ __forceinline__ void cp_async16(uint32_t dst, const void* src) {
    asm volatile("cp.async.cg.shared.global [%0], [%1], 16;"
                 :: "r"(dst), "l"(src) : "memory");
}
__device__ __forceinline__ void cp_commit() {
    asm volatile("cp.async.commit_group;" ::: "memory");
}
template<int N> __device__ __forceinline__ void cp_wait() {
    asm volatile("cp.async.wait_group %0;" :: "n"(N) : "memory");
}
__device__ __forceinline__ void ldsm_x4(uint32_t* r, uint32_t addr) {
    asm volatile("ldmatrix.sync.aligned.m8n8.x4.shared.b16 {%0,%1,%2,%3}, [%4];"
                 : "=r"(r[0]), "=r"(r[1]), "=r"(r[2]), "=r"(r[3]) : "r"(addr));
}
__device__ __forceinline__ void ldsm_x4_t(uint32_t* r, uint32_t addr) {
    asm volatile("ldmatrix.sync.aligned.m8n8.x4.trans.shared.b16 {%0,%1,%2,%3}, [%4];"
                 : "=r"(r[0]), "=r"(r[1]), "=r"(r[2]), "=r"(r[3]) : "r"(addr));
}
__device__ __forceinline__ void mma16816(float* c, const uint32_t* a, const uint32_t* b) {
    asm volatile("mma.sync.aligned.m16n8k16.row.col.f32.f16.f16.f32 "
                 "{%0,%1,%2,%3}, {%4,%5,%6,%7}, {%8,%9}, {%0,%1,%2,%3};"
                 : "+f"(c[0]), "+f"(c[1]), "+f"(c[2]), "+f"(c[3])
                 : "r"(a[0]), "r"(a[1]), "r"(a[2]), "r"(a[3]), "r"(b[0]), "r"(b[1]));
}
__device__ __forceinline__ float ex2(float x) {
    float y;
    asm("ex2.approx.ftz.f32 %0, %1;" : "=f"(y) : "f"(x));
    return y;
}

// ---------------- fp32 -> fp16 hi/lo split ---------------------------------
__device__ __forceinline__ void split2h(float v, __half& h, __half& l) {
    h = __float2half(v);
    l = __float2half(v - __half2float(h));
}
__device__ __forceinline__ uint32_t packh(float a, float b) {
    __half2 t = __floats2half2_rn(a, b);
    return *(uint32_t*)&t;
}

// One launch: split x (first 4M elems, hi/lo) + round all 4 weights (single).
__global__ __launch_bounds__(256)
void split_all(const float* __restrict__ x,  const float* __restrict__ Wq,
               const float* __restrict__ Wk, const float* __restrict__ Wv,
               const float* __restrict__ Wo)
{
    int i = (blockIdx.x * 256 + threadIdx.x) * 4;
    if (i < Mtot * Dd) {
        float4 v = *(const float4*)(x + i);
        __half h0, h1, h2, h3, l0, l1, l2, l3;
        split2h(v.x, h0, l0); split2h(v.y, h1, l1);
        split2h(v.z, h2, l2); split2h(v.w, h3, l3);
        *(__half2*)(g_xh + i)     = __half2(h0, h1);
        *(__half2*)(g_xh + i + 2) = __half2(h2, h3);
        *(__half2*)(g_xl + i)     = __half2(l0, l1);
        *(__half2*)(g_xl + i + 2) = __half2(l2, l3);
    } else {
        int j = i - Mtot * Dd;
        int w = j >> 20;                 // Dd*Dd = 2^20
        int r = j & (Dd * Dd - 1);
        const float* src = (w == 0 ? Wq : w == 1 ? Wk : w == 2 ? Wv : Wo) + r;
        float4 v = *(const float4*)src;
        *(__half2*)(g_w + j)     = __floats2half2_rn(v.x, v.y);
        *(__half2*)(g_w + j + 2) = __floats2half2_rn(v.z, v.w);
    }
}

// ---------------------------------------------------------------------------
// mma.sync GEMM cores. Block 128x128, 8 warps, double-buffered cp.async.
// qkv: Q = (xh+xl)@W (2 terms, stored hi/lo); K/V = xh@W (1 term, fp16).
// out: out = c16@Wo (1 term, fp32 result).
// ---------------------------------------------------------------------------
#define TILE_B   10240                 // 128 rows * 80 B
#define BUF3_B   (3 * TILE_B)
#define QKV_SMEM (2 * BUF3_B + 512)    // 61952
#define BUF2_B   (2 * TILE_B)
#define OUT_SMEM (2 * BUF2_B + 512)    // 41472

// Fused QKV projection: gridDim.z selects Q(2-term)/K(1-term)/V(1-term).
__global__ __launch_bounds__(256)
void gemm_qkv(const float* __restrict__ bq, const float* __restrict__ bk,
              const float* __restrict__ bv)
{
    extern __shared__ char smem[];
    const uint32_t sb = smem_to_u32(smem);
    float* biasS = (float*)(smem + 2 * BUF3_B);

    const int tid = threadIdx.x, wid = tid >> 5, lid = tid & 31;
    const int wm = wid >> 2, wn = wid & 3;
    const int m0 = blockIdx.y * 128, n0 = blockIdx.x * 128;
    const int z = blockIdx.z;
    const bool doLo = (z == 0);

    const float* bias = (z == 0) ? bq : (z == 1) ? bk : bv;
    const __half* W16 = g_w + (size_t)z * Dd * Dd;

    if (tid < 128) biasS[tid] = bias[n0 + tid];

    float acc[4][4][4];
#pragma unroll
    for (int i = 0; i < 4; i++)
#pragma unroll
        for (int j = 0; j < 4; j++)
#pragma unroll
            for (int k = 0; k < 4; k++) acc[i][j][k] = 0.f;

    auto issue = [&](int kt, int buf) {
        const int kc = kt * 32;
#pragma unroll
        for (int i = 0; i < 6; i++) {
            int idx = tid + i * 256;
            int tile = idx >> 9, w = idx & 511;
            if (tile == 1 && !doLo) continue;      // xl unused for K/V
            int r = w >> 2, seg = (w & 3) * 16;
            uint32_t dst = sb + buf * BUF3_B + tile * TILE_B + r * 80 + seg;
            const char* src;
            if (tile == 0)      src = (const char*)(g_xh + (size_t)(m0 + r) * Dd + kc) + seg;
            else if (tile == 1) src = (const char*)(g_xl + (size_t)(m0 + r) * Dd + kc) + seg;
            else                src = (const char*)(W16 + (size_t)(n0 + r) * Dd + kc) + seg;
            cp_async16(dst, src);
        }
        cp_commit();
    };

    issue(0, 0);
    int buf = 0;
    const int arow0 = wm * 64 + (lid & 15);
    const int abyte0 = (lid >> 4) * 16;
    const int brow0 = wn * 32 + ((lid >> 4) << 3) + (lid & 7);
    const int bbyte0 = ((lid >> 3) & 1) * 16;

    for (int kt = 0; kt < 32; kt++) {
        cp_wait<0>();
        __syncthreads();               // data ready + prior reads of buf^1 done
        if (kt + 1 < 32) issue(kt + 1, buf ^ 1);

        const uint32_t tAh = sb + buf * BUF3_B;
        const uint32_t tAl = tAh + TILE_B;
        const uint32_t tBh = tAh + 2 * TILE_B;

#pragma unroll
        for (int kk = 0; kk < 2; kk++) {
            const int ab = kk * 32 + abyte0;
            const int bb = kk * 32 + bbyte0;
            uint32_t aH[4][4], bH[4][2];
#pragma unroll
            for (int mf = 0; mf < 4; mf++)
                ldsm_x4(aH[mf], tAh + (arow0 + mf * 16) * 80 + ab);
#pragma unroll
            for (int nf2 = 0; nf2 < 2; nf2++) {
                uint32_t ro = (brow0 + nf2 * 16) * 80;
                uint32_t r4[4];
                ldsm_x4(r4, tBh + ro + bb);
                bH[nf2 * 2][0] = r4[0]; bH[nf2 * 2][1] = r4[1];
                bH[nf2 * 2 + 1][0] = r4[2]; bH[nf2 * 2 + 1][1] = r4[3];
            }
#pragma unroll
            for (int mf = 0; mf < 4; mf++)
#pragma unroll
                for (int nf = 0; nf < 4; nf++)
                    mma16816(acc[mf][nf], aH[mf], bH[nf]);
            if (doLo) {
                uint32_t aL[4][4];
#pragma unroll
                for (int mf = 0; mf < 4; mf++)
                    ldsm_x4(aL[mf], tAl + (arow0 + mf * 16) * 80 + ab);
#pragma unroll
                for (int mf = 0; mf < 4; mf++)
#pragma unroll
                    for (int nf = 0; nf < 4; nf++)
                        mma16816(acc[mf][nf], aL[mf], bH[nf]);
            }
        }
        buf ^= 1;
    }

#pragma unroll
    for (int mf = 0; mf < 4; mf++) {
#pragma unroll
        for (int nf = 0; nf < 4; nf++) {
            int nl = wn * 32 + nf * 8 + (lid & 3) * 2;
            int n = n0 + nl;
            float b0 = biasS[nl], b1 = biasS[nl + 1];
#pragma unroll
            for (int half = 0; half < 2; half++) {
                int m = m0 + wm * 64 + mf * 16 + (lid >> 2) + half * 8;
                float v0 = acc[mf][nf][half * 2 + 0] + b0;
                float v1 = acc[mf][nf][half * 2 + 1] + b1;
                int b = m >> 11, s = m & (Ss - 1);
                int hh = n >> 6, d = n & (HD - 1);
                size_t o = (((size_t)(b * Hh + hh)) * Ss + s) * HD + d;
                if (z == 0) {          // Q: pre-scale + split hi/lo
                    v0 *= QSCALE; v1 *= QSCALE;
                    __half h0, l0, h1, l1;
                    split2h(v0, h0, l0); split2h(v1, h1, l1);
                    *(__half2*)(g_qh + o) = __half2(h0, h1);
                    *(__half2*)(g_ql + o) = __half2(l0, l1);
                } else {               // K/V: single fp16
                    __half* dst = (z == 1) ? g_kh : g_vh;
                    *(__half2*)(dst + o) = __floats2half2_rn(v0, v1);
                }
            }
        }
    }
}

// Output GEMM: out = c16 @ Wo16^T + bo, fp32 result (1 term, 2 smem tiles).
__global__ __launch_bounds__(256)
void gemm_out(const float* __restrict__ bias, float* __restrict__ Cout)
{
    extern __shared__ char smem[];
    const uint32_t sb = smem_to_u32(smem);
    float* biasS = (float*)(smem + 2 * BUF2_B);

    const int tid = threadIdx.x, wid = tid >> 5, lid = tid & 31;
    const int wm = wid >> 2, wn = wid & 3;
    const int m0 = blockIdx.y * 128, n0 = blockIdx.x * 128;

    const __half* W16 = g_w + (size_t)3 * Dd * Dd;

    if (tid < 128) biasS[tid] = bias[n0 + tid];

    float acc[4][4][4];
#pragma unroll
    for (int i = 0; i < 4; i++)
#pragma unroll
        for (int j = 0; j < 4; j++)
#pragma unroll
            for (int k = 0; k < 4; k++) acc[i][j][k] = 0.f;

    auto issue = [&](int kt, int buf) {
        const int kc = kt * 32;
#pragma unroll
        for (int i = 0; i < 4; i++) {
            int idx = tid + i * 256;
            int tile = idx >> 9, w = idx & 511;
            int r = w >> 2, seg = (w & 3) * 16;
            uint32_t dst = sb + buf * BUF2_B + tile * TILE_B + r * 80 + seg;
            const char* src;
            if (tile == 0) src = (const char*)(g_c16 + (size_t)(m0 + r) * Dd + kc) + seg;
            else           src = (const char*)(W16 + (size_t)(n0 + r) * Dd + kc) + seg;
            cp_async16(dst, src);
        }
        cp_commit();
    };

    issue(0, 0);
    int buf = 0;
    const int arow0 = wm * 64 + (lid & 15);
    const int abyte0 = (lid >> 4) * 16;
    const int brow0 = wn * 32 + ((lid >> 4) << 3) + (lid & 7);
    const int bbyte0 = ((lid >> 3) & 1) * 16;

    for (int kt = 0; kt < 32; kt++) {
        cp_wait<0>();
        __syncthreads();
        if (kt + 1 < 32) issue(kt + 1, buf ^ 1);

        const uint32_t tA = sb + buf * BUF2_B;
        const uint32_t tB = tA + TILE_B;

#pragma unroll
        for (int kk = 0; kk < 2; kk++) {
            const int ab = kk * 32 + abyte0;
            const int bb = kk * 32 + bbyte0;
            uint32_t aH[4][4], bH[4][2];
#pragma unroll
            for (int mf = 0; mf < 4; mf++)
                ldsm_x4(aH[mf], tA + (arow0 + mf * 16) * 80 + ab);
#pragma unroll
            for (int nf2 = 0; nf2 < 2; nf2++) {
                uint32_t ro = (brow0 + nf2 * 16) * 80;
                uint32_t r4[4];
                ldsm_x4(r4, tB + ro + bb);
                bH[nf2 * 2][0] = r4[0]; bH[nf2 * 2][1] = r4[1];
                bH[nf2 * 2 + 1][0] = r4[2]; bH[nf2 * 2 + 1][1] = r4[3];
            }
#pragma unroll
            for (int mf = 0; mf < 4; mf++)
#pragma unroll
                for (int nf = 0; nf < 4; nf++)
                    mma16816(acc[mf][nf], aH[mf], bH[nf]);
        }
        buf ^= 1;
    }

#pragma unroll
    for (int mf = 0; mf < 4; mf++) {
#pragma unroll
        for (int nf = 0; nf < 4; nf++) {
            int nl = wn * 32 + nf * 8 + (lid & 3) * 2;
            int n = n0 + nl;
            float b0 = biasS[nl], b1 = biasS[nl + 1];
#pragma unroll
            for (int half = 0; half < 2; half++) {
                int m = m0 + wm * 64 + mf * 16 + (lid >> 2) + half * 8;
                *(float2*)(Cout + (size_t)m * Dd + n) =
                    make_float2(acc[mf][nf][half * 2 + 0] + b0,
                                acc[mf][nf][half * 2 + 1] + b1);
            }
        }
    }
}

// ---------------------------------------------------------------------------
// Tensor-core causal flash attention. S = (qh+ql)@k16 (2 terms);
// O += P16@v16 (1 term — P's fp16 rounding is averaged by the softmax sum).
// q-tile 128 rows, 256 threads / 8 warps; paired (pr, 15-pr) -> uniform work.
// ---------------------------------------------------------------------------
#define AT_STRIDE 144
#define QT_B     (128 * AT_STRIDE)           // 18432
#define KV_TILE  (64 * AT_STRIDE)            // 9216
#define KV0      (2 * QT_B)                  // 36864
#define KV_STAGE (2 * KV_TILE)               // 18432 (k + v)
#define ATTN_SMEM (KV0 + 2 * KV_STAGE)       // 73728

__global__ __launch_bounds__(256, 2)
void attn_mma()
{
    extern __shared__ char smem[];
    const uint32_t sb = smem_to_u32(smem);
    const int pr = blockIdx.x;                 // pair index 0..7
    const int bh = blockIdx.y;
    const int b = bh >> 4, h = bh & 15;
    const int tid = threadIdx.x, wid = tid >> 5, lid = tid & 31;

    const __half* kbase = g_kh + (size_t)bh * Ss * HD;
    const __half* vbase = g_vh + (size_t)bh * Ss * HD;

    auto issue = [&](int kt, int bf) {
#pragma unroll
        for (int i = 0; i < 4; i++) {
            int idx = tid + i * 256;
            int t = idx >> 9, w = idx & 511;
            int r = w >> 3, c = w & 7;
            const __half* src = (t ? vbase : kbase) + (size_t)(kt * 64 + r) * HD + c * 8;
            cp_async16(sb + KV0 + bf * KV_STAGE + t * KV_TILE + r * AT_STRIDE + c * 16, src);
        }
        cp_commit();
    };

    const uint32_t qrowb = (wid * 16 + (lid & 15)) * AT_STRIDE + (lid >> 4) * 16;
    const uint32_t krowb = (((lid >> 4) << 3) + (lid & 7)) * AT_STRIDE + ((lid >> 3) & 1) * 16;
    const uint32_t vrowb = (lid & 15) * AT_STRIDE + ((lid >> 4) & 1) * 16;
    int buf = 0;

    for (int half_t = 0; half_t < 2; half_t++) {
        const int qt = half_t ? (15 - pr) : pr;       // q-tile of 128 rows
        const __half* QH = g_qh + ((size_t)bh * Ss + qt * 128) * HD;
        const __half* QL = g_ql + ((size_t)bh * Ss + qt * 128) * HD;

        // Q tile (qh, ql): 128 rows x 128B each
#pragma unroll
        for (int i = 0; i < 8; i++) {
            int idx = tid + i * 256;
            int s = idx >> 10, w = idx & 1023;
            int r = w >> 3, c = w & 7;
            cp_async16(sb + s * QT_B + r * AT_STRIDE + c * 16,
                       (s ? QL : QH) + (size_t)r * HD + c * 8);
        }
        cp_commit();
        issue(0, buf);

        float acc[8][4];
#pragma unroll
        for (int i = 0; i < 8; i++)
#pragma unroll
            for (int j = 0; j < 4; j++) acc[i][j] = 0.f;
        float mrow[2] = { -1e30f, -1e30f }, lrow[2] = { 0.f, 0.f };

        const int nk = 2 * qt + 2;
        for (int kt = 0; kt < nk; kt++) {
            cp_wait<0>();
            __syncthreads();          // data ready + prior reads of buf^1 done
            if (kt + 1 < nk) issue(kt + 1, buf ^ 1);

            const uint32_t kbt = sb + KV0 + buf * KV_STAGE;
            const uint32_t vbt = kbt + KV_TILE;

            // ---- S = (qh + ql) @ k16^T  (2 MMA terms) ----
            float sf[8][4];
#pragma unroll
            for (int i = 0; i < 8; i++)
#pragma unroll
                for (int j = 0; j < 4; j++) sf[i][j] = 0.f;

#pragma unroll
            for (int kk = 0; kk < 4; kk++) {
                uint32_t aH[4], aL[4];
                ldsm_x4(aH, sb + qrowb + kk * 32);
                ldsm_x4(aL, sb + QT_B + qrowb + kk * 32);
#pragma unroll
                for (int nf2 = 0; nf2 < 4; nf2++) {
                    uint32_t rH[4];
                    ldsm_x4(rH, kbt + nf2 * 16 * AT_STRIDE + krowb + kk * 32);
                    mma16816(sf[nf2 * 2],     aH, rH);
                    mma16816(sf[nf2 * 2 + 1], aH, rH + 2);
                    mma16816(sf[nf2 * 2],     aL, rH);
                    mma16816(sf[nf2 * 2 + 1], aL, rH + 2);
                }
            }

            if (kt >= 2 * qt) {     // diagonal region: causal mask
                int r0 = wid * 16 + (lid >> 2);
                int coff = kt * 64 - qt * 128;
#pragma unroll
                for (int nf = 0; nf < 8; nf++) {
                    int c0 = coff + nf * 8 + (lid & 3) * 2;
                    if (c0     > r0)     sf[nf][0] = -1e30f;
                    if (c0 + 1 > r0)     sf[nf][1] = -1e30f;
                    if (c0     > r0 + 8) sf[nf][2] = -1e30f;
                    if (c0 + 1 > r0 + 8) sf[nf][3] = -1e30f;
                }
            }

            // ---- online softmax in exp2 domain ----
#pragma unroll
            for (int hf = 0; hf < 2; hf++) {
                float mx = -1e30f;
#pragma unroll
                for (int nf = 0; nf < 8; nf++)
                    mx = fmaxf(mx, fmaxf(sf[nf][hf * 2], sf[nf][hf * 2 + 1]));
                mx = fmaxf(mx, __shfl_xor_sync(0xffffffffu, mx, 1));
                mx = fmaxf(mx, __shfl_xor_sync(0xffffffffu, mx, 2));
                float mnew = fmaxf(mrow[hf], mx);
                float alpha = ex2(mrow[hf] - mnew);
                mrow[hf] = mnew;
                float sum = 0.f;
#pragma unroll
                for (int nf = 0; nf < 8; nf++) {
                    sf[nf][hf * 2]     = ex2(sf[nf][hf * 2] - mnew);
                    sf[nf][hf * 2 + 1] = ex2(sf[nf][hf * 2 + 1] - mnew);
                    sum += sf[nf][hf * 2] + sf[nf][hf * 2 + 1];
                }
                sum += __shfl_xor_sync(0xffffffffu, sum, 1);
                sum += __shfl_xor_sync(0xffffffffu, sum, 2);
                lrow[hf] = lrow[hf] * alpha + sum;
#pragma unroll
                for (int nf = 0; nf < 8; nf++) {
                    acc[nf][hf * 2]     *= alpha;
                    acc[nf][hf * 2 + 1] *= alpha;
                }
            }

            // ---- O += P16 @ v16  (1 MMA term) ----
#pragma unroll
            for (int kk2 = 0; kk2 < 4; kk2++) {
                uint32_t aPh[4];
#pragma unroll
                for (int q = 0; q < 2; q++) {
                    const float* c = sf[kk2 * 2 + q];
                    aPh[q * 2]     = packh(c[0], c[1]);
                    aPh[q * 2 + 1] = packh(c[2], c[3]);
                }
#pragma unroll
                for (int nf2 = 0; nf2 < 4; nf2++) {
                    uint32_t vH[4];
                    ldsm_x4_t(vH, vbt + (kk2 * 16) * AT_STRIDE + vrowb + nf2 * 32);
                    mma16816(acc[nf2 * 2],     aPh, vH);
                    mma16816(acc[nf2 * 2 + 1], aPh, vH + 2);
                }
            }
            buf ^= 1;
        }

        // ---- epilogue: ctx -> single fp16 (B,S,D) ----
        float inv0 = 1.f / lrow[0], inv1 = 1.f / lrow[1];
        int r0 = qt * 128 + wid * 16 + (lid >> 2);
#pragma unroll
        for (int nf = 0; nf < 8; nf++) {
            int d0 = h * HD + nf * 8 + (lid & 3) * 2;
            size_t o0 = ((size_t)b * Ss + r0) * Dd + d0;
            size_t o1 = ((size_t)b * Ss + r0 + 8) * Dd + d0;
            *(__half2*)(g_c16 + o0) =
                __floats2half2_rn(acc[nf][0] * inv0, acc[nf][1] * inv0);
            *(__half2*)(g_c16 + o1) =
                __floats2half2_rn(acc[nf][2] * inv1, acc[nf][3] * inv1);
        }
        __syncthreads();    // Q/KV smem reuse safe before next half's loads
    }
}

// ---------------------------------------------------------------------------
extern "C" void kernel_launch(void* const* d_in, const int* in_sizes, int n_in,
                              void* d_out, int out_size)
{
    const float* x  = (const float*)d_in[0];
    const float* Wq = (const float*)d_in[1];
    const float* bq = (const float*)d_in[2];
    const float* Wk = (const float*)d_in[3];
    const float* bk = (const float*)d_in[4];
    const float* Wv = (const float*)d_in[5];
    const float* bv = (const float*)d_in[6];
    const float* Wo = (const float*)d_in[7];
    const float* bo = (const float*)d_in[8];
    float* out = (float*)d_out;

    cudaFuncSetAttribute(gemm_qkv, cudaFuncAttributeMaxDynamicSharedMemorySize, QKV_SMEM);
    cudaFuncSetAttribute(gemm_out, cudaFuncAttributeMaxDynamicSharedMemorySize, OUT_SMEM);
    cudaFuncSetAttribute(attn_mma, cudaFuncAttributeMaxDynamicSharedMemorySize, ATTN_SMEM);

    split_all<<<(Mtot * Dd + 4 * Dd * Dd) / 1024, 256>>>(x, Wq, Wk, Wv, Wo);

    gemm_qkv<<<dim3(Dd / 128, Mtot / 128, 3), 256, QKV_SMEM>>>(bq, bk, bv);

    attn_mma<<<dim3(8, Bb * Hh), 256, ATTN_SMEM>>>();

    gemm_out<<<dim3(Dd / 128, Mtot / 128), 256, OUT_SMEM>>>(bo, out);
}

// round 12
// speedup vs baseline: 6.5716x; 1.0048x over previous
#include <cuda_runtime.h>
#include <cuda_fp16.h>
#include <cstdint>

#define Bb 2
#define Ss 2048
#define Dd 1024
#define Hh 16
#define HD 64
#define Mtot (Bb*Ss)   // 4096
#define QSCALE 0.1803368801111244f   // 0.125 * log2(e): softmax in exp2 domain

// ---------------- scratch (static device arrays; alloc APIs forbidden) -----
__device__ __align__(16) __half g_qh[Bb*Hh*Ss*HD];  // q split hi/lo (B,H,S,hd)
__device__ __align__(16) __half g_ql[Bb*Hh*Ss*HD];
__device__ __align__(16) __half g_kh[Bb*Hh*Ss*HD];  // k single fp16
__device__ __align__(16) __half g_vh[Bb*Hh*Ss*HD];  // v single fp16
__device__ __align__(16) __half g_xh[Mtot*Dd];      // x split hi/lo
__device__ __align__(16) __half g_xl[Mtot*Dd];
__device__ __align__(16) __half g_w [4u*Dd*Dd];     // Wq,Wk,Wv,Wo single fp16
__device__ __align__(16) __half g_c16[Mtot*Dd];     // ctx single fp16 (B,S,D)

// ---------------- PTX helpers (sm_80/75-era only) --------------------------
__device__ __forceinline__ uint32_t smem_to_u32(const void* p) {
    uint32_t a;
    asm("{ .reg .u64 t; cvta.to.shared.u64 t, %1; cvt.u32.u64 %0, t; }"
        : "=r"(a) : "l"(p));
    return a;
}
__device__ __forceinline__ void cp_async16(uint32_t dst, const void* src) {
    asm volatile("cp.async.cg.shared.global [%0], [%1], 16;"
                 :: "r"(dst), "l"(src) : "memory");
}
__device__ __forceinline__ void cp_commit() {
    asm volatile("cp.async.commit_group;" ::: "memory");
}
template<int N> __device__ __forceinline__ void cp_wait() {
    asm volatile("cp.async.wait_group %0;" :: "n"(N) : "memory");
}
__device__ __forceinline__ void ldsm_x4(uint32_t* r, uint32_t addr) {
    asm volatile("ldmatrix.sync.aligned.m8n8.x4.shared.b16 {%0,%1,%2,%3}, [%4];"
                 : "=r"(r[0]), "=r"(r[1]), "=r"(r[2]), "=r"(r[3]) : "r"(addr));
}
__device__ __forceinline__ void ldsm_x4_t(uint32_t* r, uint32_t addr) {
    asm volatile("ldmatrix.sync.aligned.m8n8.x4.trans.shared.b16 {%0,%1,%2,%3}, [%4];"
                 : "=r"(r[0]), "=r"(r[1]), "=r"(r[2]), "=r"(r[3]) : "r"(addr));
}
__device__ __forceinline__ void mma16816(float* c, const uint32_t* a, const uint32_t* b) {
    asm volatile("mma.sync.aligned.m16n8k16.row.col.f32.f16.f16.f32 "
                 "{%0,%1,%2,%3}, {%4,%5,%6,%7}, {%8,%9}, {%0,%1,%2,%3};"
                 : "+f"(c[0]), "+f"(c[1]), "+f"(c[2]), "+f"(c[3])
                 : "r"(a[0]), "r"(a[1]), "r"(a[2]), "r"(a[3]), "r"(b[0]), "r"(b[1]));
}
__device__ __forceinline__ float ex2(float x) {
    float y;
    asm("ex2.approx.ftz.f32 %0, %1;" : "=f"(y) : "f"(x));
    return y;
}

// ---------------- fp32 -> fp16 hi/lo split ---------------------------------
__device__ __forceinline__ void split2h(float v, __half& h, __half& l) {
    h = __float2half(v);
    l = __float2half(v - __half2float(h));
}
__device__ __forceinline__ uint32_t packh(float a, float b) {
    __half2 t = __floats2half2_rn(a, b);
    return *(uint32_t*)&t;
}

// One launch: split x (first 4M elems, hi/lo) + round all 4 weights (single).
__global__ __launch_bounds__(256)
void split_all(const float* __restrict__ x,  const float* __restrict__ Wq,
               const float* __restrict__ Wk, const float* __restrict__ Wv,
               const float* __restrict__ Wo)
{
    int i = (blockIdx.x * 256 + threadIdx.x) * 4;
    if (i < Mtot * Dd) {
        float4 v = *(const float4*)(x + i);
        __half h0, h1, h2, h3, l0, l1, l2, l3;
        split2h(v.x, h0, l0); split2h(v.y, h1, l1);
        split2h(v.z, h2, l2); split2h(v.w, h3, l3);
        *(__half2*)(g_xh + i)     = __half2(h0, h1);
        *(__half2*)(g_xh + i + 2) = __half2(h2, h3);
        *(__half2*)(g_xl + i)     = __half2(l0, l1);
        *(__half2*)(g_xl + i + 2) = __half2(l2, l3);
    } else {
        int j = i - Mtot * Dd;
        int w = j >> 20;                 // Dd*Dd = 2^20
        int r = j & (Dd * Dd - 1);
        const float* src = (w == 0 ? Wq : w == 1 ? Wk : w == 2 ? Wv : Wo) + r;
        float4 v = *(const float4*)src;
        *(__half2*)(g_w + j)     = __floats2half2_rn(v.x, v.y);
        *(__half2*)(g_w + j + 2) = __floats2half2_rn(v.z, v.w);
    }
}

// ---------------------------------------------------------------------------
// mma.sync GEMM cores. Block 128x128, 8 warps, 3-STAGE cp.async pipeline
// (two chunk loads always in flight -> 2 compute-periods of latency cover).
// qkv: Q = (xh+xl)@W (2 terms); K/V = xh@W (1 term). out: out = c16@Wo.
// ---------------------------------------------------------------------------
#define TILE_B   10240                 // 128 rows * 80 B
#define BUF3_B   (3 * TILE_B)          // qkv per-stage: xh, xl, W
#define QKV_SMEM (3 * BUF3_B + 512)    // 92672
#define BUF2_B   (2 * TILE_B)          // out per-stage: c16, W
#define OUT_SMEM (3 * BUF2_B + 512)    // 61952

// Fused QKV projection: gridDim.z selects Q(2-term)/K(1-term)/V(1-term).
__global__ __launch_bounds__(256)
void gemm_qkv(const float* __restrict__ bq, const float* __restrict__ bk,
              const float* __restrict__ bv)
{
    extern __shared__ char smem[];
    const uint32_t sb = smem_to_u32(smem);
    float* biasS = (float*)(smem + 3 * BUF3_B);

    const int tid = threadIdx.x, wid = tid >> 5, lid = tid & 31;
    const int wm = wid >> 2, wn = wid & 3;
    const int m0 = blockIdx.y * 128, n0 = blockIdx.x * 128;
    const int z = blockIdx.z;
    const bool doLo = (z == 0);

    const float* bias = (z == 0) ? bq : (z == 1) ? bk : bv;
    const __half* W16 = g_w + (size_t)z * Dd * Dd;

    if (tid < 128) biasS[tid] = bias[n0 + tid];

    float acc[4][4][4];
#pragma unroll
    for (int i = 0; i < 4; i++)
#pragma unroll
        for (int j = 0; j < 4; j++)
#pragma unroll
            for (int k = 0; k < 4; k++) acc[i][j][k] = 0.f;

    auto issue = [&](int kt, int st) {
        const int kc = kt * 32;
#pragma unroll
        for (int i = 0; i < 6; i++) {
            int idx = tid + i * 256;
            int tile = idx >> 9, w = idx & 511;
            if (tile == 1 && !doLo) continue;      // xl unused for K/V
            int r = w >> 2, seg = (w & 3) * 16;
            uint32_t dst = sb + st * BUF3_B + tile * TILE_B + r * 80 + seg;
            const char* src;
            if (tile == 0)      src = (const char*)(g_xh + (size_t)(m0 + r) * Dd + kc) + seg;
            else if (tile == 1) src = (const char*)(g_xl + (size_t)(m0 + r) * Dd + kc) + seg;
            else                src = (const char*)(W16 + (size_t)(n0 + r) * Dd + kc) + seg;
            cp_async16(dst, src);
        }
        cp_commit();
    };

    issue(0, 0);
    issue(1, 1);
    const int arow0 = wm * 64 + (lid & 15);
    const int abyte0 = (lid >> 4) * 16;
    const int brow0 = wn * 32 + ((lid >> 4) << 3) + (lid & 7);
    const int bbyte0 = ((lid >> 3) & 1) * 16;

    int stage = 0;
    for (int kt = 0; kt < 32; kt++) {
        if (kt + 1 < 32) cp_wait<1>(); else cp_wait<0>();
        __syncthreads();               // chunk kt ready + stage (kt-1)%3 reads done
        if (kt + 2 < 32) issue(kt + 2, (kt + 2) % 3);

        const uint32_t tAh = sb + stage * BUF3_B;
        const uint32_t tAl = tAh + TILE_B;
        const uint32_t tBh = tAh + 2 * TILE_B;

#pragma unroll
        for (int kk = 0; kk < 2; kk++) {
            const int ab = kk * 32 + abyte0;
            const int bb = kk * 32 + bbyte0;
            uint32_t aH[4][4], bH[4][2];
#pragma unroll
            for (int mf = 0; mf < 4; mf++)
                ldsm_x4(aH[mf], tAh + (arow0 + mf * 16) * 80 + ab);
#pragma unroll
            for (int nf2 = 0; nf2 < 2; nf2++) {
                uint32_t ro = (brow0 + nf2 * 16) * 80;
                uint32_t r4[4];
                ldsm_x4(r4, tBh + ro + bb);
                bH[nf2 * 2][0] = r4[0]; bH[nf2 * 2][1] = r4[1];
                bH[nf2 * 2 + 1][0] = r4[2]; bH[nf2 * 2 + 1][1] = r4[3];
            }
#pragma unroll
            for (int mf = 0; mf < 4; mf++)
#pragma unroll
                for (int nf = 0; nf < 4; nf++)
                    mma16816(acc[mf][nf], aH[mf], bH[nf]);
            if (doLo) {
                uint32_t aL[4][4];
#pragma unroll
                for (int mf = 0; mf < 4; mf++)
                    ldsm_x4(aL[mf], tAl + (arow0 + mf * 16) * 80 + ab);
#pragma unroll
                for (int mf = 0; mf < 4; mf++)
#pragma unroll
                    for (int nf = 0; nf < 4; nf++)
                        mma16816(acc[mf][nf], aL[mf], bH[nf]);
            }
        }
        stage = (stage == 2) ? 0 : stage + 1;
    }

#pragma unroll
    for (int mf = 0; mf < 4; mf++) {
#pragma unroll
        for (int nf = 0; nf < 4; nf++) {
            int nl = wn * 32 + nf * 8 + (lid & 3) * 2;
            int n = n0 + nl;
            float b0 = biasS[nl], b1 = biasS[nl + 1];
#pragma unroll
            for (int half = 0; half < 2; half++) {
                int m = m0 + wm * 64 + mf * 16 + (lid >> 2) + half * 8;
                float v0 = acc[mf][nf][half * 2 + 0] + b0;
                float v1 = acc[mf][nf][half * 2 + 1] + b1;
                int b = m >> 11, s = m & (Ss - 1);
                int hh = n >> 6, d = n & (HD - 1);
                size_t o = (((size_t)(b * Hh + hh)) * Ss + s) * HD + d;
                if (z == 0) {          // Q: pre-scale + split hi/lo
                    v0 *= QSCALE; v1 *= QSCALE;
                    __half h0, l0, h1, l1;
                    split2h(v0, h0, l0); split2h(v1, h1, l1);
                    *(__half2*)(g_qh + o) = __half2(h0, h1);
                    *(__half2*)(g_ql + o) = __half2(l0, l1);
                } else {               // K/V: single fp16
                    __half* dst = (z == 1) ? g_kh : g_vh;
                    *(__half2*)(dst + o) = __floats2half2_rn(v0, v1);
                }
            }
        }
    }
}

// Output GEMM: out = c16 @ Wo16^T + bo, fp32 result (1 term, 3-stage pipe).
__global__ __launch_bounds__(256)
void gemm_out(const float* __restrict__ bias, float* __restrict__ Cout)
{
    extern __shared__ char smem[];
    const uint32_t sb = smem_to_u32(smem);
    float* biasS = (float*)(smem + 3 * BUF2_B);

    const int tid = threadIdx.x, wid = tid >> 5, lid = tid & 31;
    const int wm = wid >> 2, wn = wid & 3;
    const int m0 = blockIdx.y * 128, n0 = blockIdx.x * 128;

    const __half* W16 = g_w + (size_t)3 * Dd * Dd;

    if (tid < 128) biasS[tid] = bias[n0 + tid];

    float acc[4][4][4];
#pragma unroll
    for (int i = 0; i < 4; i++)
#pragma unroll
        for (int j = 0; j < 4; j++)
#pragma unroll
            for (int k = 0; k < 4; k++) acc[i][j][k] = 0.f;

    auto issue = [&](int kt, int st) {
        const int kc = kt * 32;
#pragma unroll
        for (int i = 0; i < 4; i++) {
            int idx = tid + i * 256;
            int tile = idx >> 9, w = idx & 511;
            int r = w >> 2, seg = (w & 3) * 16;
            uint32_t dst = sb + st * BUF2_B + tile * TILE_B + r * 80 + seg;
            const char* src;
            if (tile == 0) src = (const char*)(g_c16 + (size_t)(m0 + r) * Dd + kc) + seg;
            else           src = (const char*)(W16 + (size_t)(n0 + r) * Dd + kc) + seg;
            cp_async16(dst, src);
        }
        cp_commit();
    };

    issue(0, 0);
    issue(1, 1);
    const int arow0 = wm * 64 + (lid & 15);
    const int abyte0 = (lid >> 4) * 16;
    const int brow0 = wn * 32 + ((lid >> 4) << 3) + (lid & 7);
    const int bbyte0 = ((lid >> 3) & 1) * 16;

    int stage = 0;
    for (int kt = 0; kt < 32; kt++) {
        if (kt + 1 < 32) cp_wait<1>(); else cp_wait<0>();
        __syncthreads();
        if (kt + 2 < 32) issue(kt + 2, (kt + 2) % 3);

        const uint32_t tA = sb + stage * BUF2_B;
        const uint32_t tB = tA + TILE_B;

#pragma unroll
        for (int kk = 0; kk < 2; kk++) {
            const int ab = kk * 32 + abyte0;
            const int bb = kk * 32 + bbyte0;
            uint32_t aH[4][4], bH[4][2];
#pragma unroll
            for (int mf = 0; mf < 4; mf++)
                ldsm_x4(aH[mf], tA + (arow0 + mf * 16) * 80 + ab);
#pragma unroll
            for (int nf2 = 0; nf2 < 2; nf2++) {
                uint32_t ro = (brow0 + nf2 * 16) * 80;
                uint32_t r4[4];
                ldsm_x4(r4, tB + ro + bb);
                bH[nf2 * 2][0] = r4[0]; bH[nf2 * 2][1] = r4[1];
                bH[nf2 * 2 + 1][0] = r4[2]; bH[nf2 * 2 + 1][1] = r4[3];
            }
#pragma unroll
            for (int mf = 0; mf < 4; mf++)
#pragma unroll
                for (int nf = 0; nf < 4; nf++)
                    mma16816(acc[mf][nf], aH[mf], bH[nf]);
        }
        stage = (stage == 2) ? 0 : stage + 1;
    }

#pragma unroll
    for (int mf = 0; mf < 4; mf++) {
#pragma unroll
        for (int nf = 0; nf < 4; nf++) {
            int nl = wn * 32 + nf * 8 + (lid & 3) * 2;
            int n = n0 + nl;
            float b0 = biasS[nl], b1 = biasS[nl + 1];
#pragma unroll
            for (int half = 0; half < 2; half++) {
                int m = m0 + wm * 64 + mf * 16 + (lid >> 2) + half * 8;
                *(float2*)(Cout + (size_t)m * Dd + n) =
                    make_float2(acc[mf][nf][half * 2 + 0] + b0,
                                acc[mf][nf][half * 2 + 1] + b1);
            }
        }
    }
}

// ---------------------------------------------------------------------------
// Tensor-core causal flash attention. S = (qh+ql)@k16 (2 terms);
// O += P16@v16 (1 term). KV ring is 3-stage (two tile loads in flight).
// q-tile 128 rows, 256 threads / 8 warps; paired (pr, 15-pr) -> uniform work.
// ---------------------------------------------------------------------------
#define AT_STRIDE 144
#define QT_B     (128 * AT_STRIDE)           // 18432
#define KV_TILE  (64 * AT_STRIDE)            // 9216
#define KV0      (2 * QT_B)                  // 36864
#define KV_STAGE (2 * KV_TILE)               // 18432 (k + v)
#define ATTN_SMEM (KV0 + 3 * KV_STAGE)       // 92160

__global__ __launch_bounds__(256, 2)
void attn_mma()
{
    extern __shared__ char smem[];
    const uint32_t sb = smem_to_u32(smem);
    const int pr = blockIdx.x;                 // pair index 0..7
    const int bh = blockIdx.y;
    const int b = bh >> 4, h = bh & 15;
    const int tid = threadIdx.x, wid = tid >> 5, lid = tid & 31;

    const __half* kbase = g_kh + (size_t)bh * Ss * HD;
    const __half* vbase = g_vh + (size_t)bh * Ss * HD;

    auto issue = [&](int kt, int st) {
#pragma unroll
        for (int i = 0; i < 4; i++) {
            int idx = tid + i * 256;
            int t = idx >> 9, w = idx & 511;
            int r = w >> 3, c = w & 7;
            const __half* src = (t ? vbase : kbase) + (size_t)(kt * 64 + r) * HD + c * 8;
            cp_async16(sb + KV0 + st * KV_STAGE + t * KV_TILE + r * AT_STRIDE + c * 16, src);
        }
        cp_commit();
    };

    const uint32_t qrowb = (wid * 16 + (lid & 15)) * AT_STRIDE + (lid >> 4) * 16;
    const uint32_t krowb = (((lid >> 4) << 3) + (lid & 7)) * AT_STRIDE + ((lid >> 3) & 1) * 16;
    const uint32_t vrowb = (lid & 15) * AT_STRIDE + ((lid >> 4) & 1) * 16;

    for (int half_t = 0; half_t < 2; half_t++) {
        const int qt = half_t ? (15 - pr) : pr;       // q-tile of 128 rows
        const __half* QH = g_qh + ((size_t)bh * Ss + qt * 128) * HD;
        const __half* QL = g_ql + ((size_t)bh * Ss + qt * 128) * HD;
        const int nk = 2 * qt + 2;

        // Q tile (qh, ql): 128 rows x 128B each (own commit group)
#pragma unroll
        for (int i = 0; i < 8; i++) {
            int idx = tid + i * 256;
            int s = idx >> 10, w = idx & 1023;
            int r = w >> 3, c = w & 7;
            cp_async16(sb + s * QT_B + r * AT_STRIDE + c * 16,
                       (s ? QL : QH) + (size_t)r * HD + c * 8);
        }
        cp_commit();
        issue(0, 0);
        if (nk > 1) issue(1, 1);

        float acc[8][4];
#pragma unroll
        for (int i = 0; i < 8; i++)
#pragma unroll
            for (int j = 0; j < 4; j++) acc[i][j] = 0.f;
        float mrow[2] = { -1e30f, -1e30f }, lrow[2] = { 0.f, 0.f };

        int stage = 0;
        for (int kt = 0; kt < nk; kt++) {
            if (kt + 1 < nk) cp_wait<1>(); else cp_wait<0>();
            __syncthreads();          // chunk kt (and Q) ready + old stage reads done
            if (kt + 2 < nk) issue(kt + 2, (kt + 2) % 3);

            const uint32_t kbt = sb + KV0 + stage * KV_STAGE;
            const uint32_t vbt = kbt + KV_TILE;

            // ---- S = (qh + ql) @ k16^T  (2 MMA terms) ----
            float sf[8][4];
#pragma unroll
            for (int i = 0; i < 8; i++)
#pragma unroll
                for (int j = 0; j < 4; j++) sf[i][j] = 0.f;

#pragma unroll
            for (int kk = 0; kk < 4; kk++) {
                uint32_t aH[4], aL[4];
                ldsm_x4(aH, sb + qrowb + kk * 32);
                ldsm_x4(aL, sb + QT_B + qrowb + kk * 32);
#pragma unroll
                for (int nf2 = 0; nf2 < 4; nf2++) {
                    uint32_t rH[4];
                    ldsm_x4(rH, kbt + nf2 * 16 * AT_STRIDE + krowb + kk * 32);
                    mma16816(sf[nf2 * 2],     aH, rH);
                    mma16816(sf[nf2 * 2 + 1], aH, rH + 2);
                    mma16816(sf[nf2 * 2],     aL, rH);
                    mma16816(sf[nf2 * 2 + 1], aL, rH + 2);
                }
            }

            if (kt >= 2 * qt) {     // diagonal region: causal mask
                int r0 = wid * 16 + (lid >> 2);
                int coff = kt * 64 - qt * 128;
#pragma unroll
                for (int nf = 0; nf < 8; nf++) {
                    int c0 = coff + nf * 8 + (lid & 3) * 2;
                    if (c0     > r0)     sf[nf][0] = -1e30f;
                    if (c0 + 1 > r0)     sf[nf][1] = -1e30f;
                    if (c0     > r0 + 8) sf[nf][2] = -1e30f;
                    if (c0 + 1 > r0 + 8) sf[nf][3] = -1e30f;
                }
            }

            // ---- online softmax in exp2 domain ----
#pragma unroll
            for (int hf = 0; hf < 2; hf++) {
                float mx = -1e30f;
#pragma unroll
                for (int nf = 0; nf < 8; nf++)
                    mx = fmaxf(mx, fmaxf(sf[nf][hf * 2], sf[nf][hf * 2 + 1]));
                mx = fmaxf(mx, __shfl_xor_sync(0xffffffffu, mx, 1));
                mx = fmaxf(mx, __shfl_xor_sync(0xffffffffu, mx, 2));
                float mnew = fmaxf(mrow[hf], mx);
                float alpha = ex2(mrow[hf] - mnew);
                mrow[hf] = mnew;
                float sum = 0.f;
#pragma unroll
                for (int nf = 0; nf < 8; nf++) {
                    sf[nf][hf * 2]     = ex2(sf[nf][hf * 2] - mnew);
                    sf[nf][hf * 2 + 1] = ex2(sf[nf][hf * 2 + 1] - mnew);
                    sum += sf[nf][hf * 2] + sf[nf][hf * 2 + 1];
                }
                sum += __shfl_xor_sync(0xffffffffu, sum, 1);
                sum += __shfl_xor_sync(0xffffffffu, sum, 2);
                lrow[hf] = lrow[hf] * alpha + sum;
#pragma unroll
                for (int nf = 0; nf < 8; nf++) {
                    acc[nf][hf * 2]     *= alpha;
                    acc[nf][hf * 2 + 1] *= alpha;
                }
            }

            // ---- O += P16 @ v16  (1 MMA term) ----
#pragma unroll
            for (int kk2 = 0; kk2 < 4; kk2++) {
                uint32_t aPh[4];
#pragma unroll
                for (int q = 0; q < 2; q++) {
                    const float* c = sf[kk2 * 2 + q];
                    aPh[q * 2]     = packh(c[0], c[1]);
                    aPh[q * 2 + 1] = packh(c[2], c[3]);
                }
#pragma unroll
                for (int nf2 = 0; nf2 < 4; nf2++) {
                    uint32_t vH[4];
                    ldsm_x4_t(vH, vbt + (kk2 * 16) * AT_STRIDE + vrowb + nf2 * 32);
                    mma16816(acc[nf2 * 2],     aPh, vH);
                    mma16816(acc[nf2 * 2 + 1], aPh, vH + 2);
                }
            }
            stage = (stage == 2) ? 0 : stage + 1;
        }

        // ---- epilogue: ctx -> single fp16 (B,S,D) ----
        float inv0 = 1.f / lrow[0], inv1 = 1.f / lrow[1];
        int r0 = qt * 128 + wid * 16 + (lid >> 2);
#pragma unroll
        for (int nf = 0; nf < 8; nf++) {
            int d0 = h * HD + nf * 8 + (lid & 3) * 2;
            size_t o0 = ((size_t)b * Ss + r0) * Dd + d0;
            size_t o1 = ((size_t)b * Ss + r0 + 8) * Dd + d0;
            *(__half2*)(g_c16 + o0) =
                __floats2half2_rn(acc[nf][0] * inv0, acc[nf][1] * inv0);
            *(__half2*)(g_c16 + o1) =
                __floats2half2_rn(acc[nf][2] * inv1, acc[nf][3] * inv1);
        }
        __syncthreads();    // all smem reads done before next half's loads
    }
}

// ---------------------------------------------------------------------------
extern "C" void kernel_launch(void* const* d_in, const int* in_sizes, int n_in,
                              void* d_out, int out_size)
{
    const float* x  = (const float*)d_in[0];
    const float* Wq = (const float*)d_in[1];
    const float* bq = (const float*)d_in[2];
    const float* Wk = (const float*)d_in[3];
    const float* bk = (const float*)d_in[4];
    const float* Wv = (const float*)d_in[5];
    const float* bv = (const float*)d_in[6];
    const float* Wo = (const float*)d_in[7];
    const float* bo = (const float*)d_in[8];
    float* out = (float*)d_out;

    cudaFuncSetAttribute(gemm_qkv, cudaFuncAttributeMaxDynamicSharedMemorySize, QKV_SMEM);
    cudaFuncSetAttribute(gemm_out, cudaFuncAttributeMaxDynamicSharedMemorySize, OUT_SMEM);
    cudaFuncSetAttribute(attn_mma, cudaFuncAttributeMaxDynamicSharedMemorySize, ATTN_SMEM);

    split_all<<<(Mtot * Dd + 4 * Dd * Dd) / 1024, 256>>>(x, Wq, Wk, Wv, Wo);

    gemm_qkv<<<dim3(Dd / 128, Mtot / 128, 3), 256, QKV_SMEM>>>(bq, bk, bv);

    attn_mma<<<dim3(8, Bb * Hh), 256, ATTN_SMEM>>>();

    gemm_out<<<dim3(Dd / 128, Mtot / 128), 256, OUT_SMEM>>>(bo, out);
}

// round 13
// speedup vs baseline: 6.7499x; 1.0271x over previous
#include <cuda_runtime.h>
#include <cuda_fp16.h>
#include <cstdint>

#define Bb 2
#define Ss 2048
#define Dd 1024
#define Hh 16
#define HD 64
#define Mtot (Bb*Ss)   // 4096
#define QSCALE 0.1803368801111244f   // 0.125 * log2(e): softmax in exp2 domain

// ---------------- scratch (static device arrays; alloc APIs forbidden) -----
__device__ __align__(16) __half g_qh[Bb*Hh*Ss*HD];  // q split hi/lo (B,H,S,hd)
__device__ __align__(16) __half g_ql[Bb*Hh*Ss*HD];
__device__ __align__(16) __half g_kh[Bb*Hh*Ss*HD];  // k single fp16
__device__ __align__(16) __half g_vh[Bb*Hh*Ss*HD];  // v single fp16
__device__ __align__(16) __half g_xh[Mtot*Dd];      // x split hi/lo
__device__ __align__(16) __half g_xl[Mtot*Dd];
__device__ __align__(16) __half g_w [4u*Dd*Dd];     // Wq,Wk,Wv,Wo single fp16
__device__ __align__(16) __half g_c16[Mtot*Dd];     // ctx single fp16 (B,S,D)

// ---------------- PTX helpers (sm_80/75-era only) --------------------------
__device__ __forceinline__ uint32_t smem_to_u32(const void* p) {
    uint32_t a;
    asm("{ .reg .u64 t; cvta.to.shared.u64 t, %1; cvt.u32.u64 %0, t; }"
        : "=r"(a) : "l"(p));
    return a;
}
__device__ __forceinline__ void cp_async16(uint32_t dst, const void* src) {
    asm volatile("cp.async.cg.shared.global [%0], [%1], 16;"
                 :: "r"(dst), "l"(src) : "memory");
}
__device__ __forceinline__ void cp_commit() {
    asm volatile("cp.async.commit_group;" ::: "memory");
}
template<int N> __device__ __forceinline__ void cp_wait() {
    asm volatile("cp.async.wait_group %0;" :: "n"(N) : "memory");
}
__device__ __forceinline__ void ldsm_x4(uint32_t* r, uint32_t addr) {
    asm volatile("ldmatrix.sync.aligned.m8n8.x4.shared.b16 {%0,%1,%2,%3}, [%4];"
                 : "=r"(r[0]), "=r"(r[1]), "=r"(r[2]), "=r"(r[3]) : "r"(addr));
}
__device__ __forceinline__ void ldsm_x4_t(uint32_t* r, uint32_t addr) {
    asm volatile("ldmatrix.sync.aligned.m8n8.x4.trans.shared.b16 {%0,%1,%2,%3}, [%4];"
                 : "=r"(r[0]), "=r"(r[1]), "=r"(r[2]), "=r"(r[3]) : "r"(addr));
}
__device__ __forceinline__ void mma16816(float* c, const uint32_t* a, const uint32_t* b) {
    asm volatile("mma.sync.aligned.m16n8k16.row.col.f32.f16.f16.f32 "
                 "{%0,%1,%2,%3}, {%4,%5,%6,%7}, {%8,%9}, {%0,%1,%2,%3};"
                 : "+f"(c[0]), "+f"(c[1]), "+f"(c[2]), "+f"(c[3])
                 : "r"(a[0]), "r"(a[1]), "r"(a[2]), "r"(a[3]), "r"(b[0]), "r"(b[1]));
}
__device__ __forceinline__ float ex2(float x) {
    float y;
    asm("ex2.approx.ftz.f32 %0, %1;" : "=f"(y) : "f"(x));
    return y;
}

// ---------------- fp32 -> fp16 hi/lo split ---------------------------------
__device__ __forceinline__ void split2h(float v, __half& h, __half& l) {
    h = __float2half(v);
    l = __float2half(v - __half2float(h));
}
__device__ __forceinline__ uint32_t packh(float a, float b) {
    __half2 t = __floats2half2_rn(a, b);
    return *(uint32_t*)&t;
}

// One launch: split x (first 4M elems, hi/lo) + round all 4 weights (single).
__global__ __launch_bounds__(256)
void split_all(const float* __restrict__ x,  const float* __restrict__ Wq,
               const float* __restrict__ Wk, const float* __restrict__ Wv,
               const float* __restrict__ Wo)
{
    int i = (blockIdx.x * 256 + threadIdx.x) * 4;
    if (i < Mtot * Dd) {
        float4 v = *(const float4*)(x + i);
        __half h0, h1, h2, h3, l0, l1, l2, l3;
        split2h(v.x, h0, l0); split2h(v.y, h1, l1);
        split2h(v.z, h2, l2); split2h(v.w, h3, l3);
        *(__half2*)(g_xh + i)     = __half2(h0, h1);
        *(__half2*)(g_xh + i + 2) = __half2(h2, h3);
        *(__half2*)(g_xl + i)     = __half2(l0, l1);
        *(__half2*)(g_xl + i + 2) = __half2(l2, l3);
    } else {
        int j = i - Mtot * Dd;
        int w = j >> 20;                 // Dd*Dd = 2^20
        int r = j & (Dd * Dd - 1);
        const float* src = (w == 0 ? Wq : w == 1 ? Wk : w == 2 ? Wv : Wo) + r;
        float4 v = *(const float4*)src;
        *(__half2*)(g_w + j)     = __floats2half2_rn(v.x, v.y);
        *(__half2*)(g_w + j + 2) = __floats2half2_rn(v.z, v.w);
    }
}

// ---------------------------------------------------------------------------
// mma.sync GEMM cores. Block 128x128, FOUR warps (2x2 grid of 64x64 warp
// tiles -> 0.125-0.25 LDSM per MMA), 2-stage cp.async double buffer.
// qkv: Q = (xh+xl)@W (2 terms); K/V = xh@W (1 term). out: out = c16@Wo.
// ---------------------------------------------------------------------------
#define TILE_B   10240                 // 128 rows * 80 B
#define BUF3_B   (3 * TILE_B)          // qkv stage: xh, xl, W
#define QKV_SMEM (2 * BUF3_B + 512)    // 61952
#define BUF2_B   (2 * TILE_B)          // out stage: c16, W
#define OUT_SMEM (2 * BUF2_B + 512)    // 41472

// Fused QKV projection: gridDim.z selects Q(2-term)/K(1-term)/V(1-term).
__global__ __launch_bounds__(128)
void gemm_qkv(const float* __restrict__ bq, const float* __restrict__ bk,
              const float* __restrict__ bv)
{
    extern __shared__ char smem[];
    const uint32_t sb = smem_to_u32(smem);
    float* biasS = (float*)(smem + 2 * BUF3_B);

    const int tid = threadIdx.x, wid = tid >> 5, lid = tid & 31;
    const int wm = wid >> 1, wn = wid & 1;
    const int m0 = blockIdx.y * 128, n0 = blockIdx.x * 128;
    const int z = blockIdx.z;
    const bool doLo = (z == 0);

    const float* bias = (z == 0) ? bq : (z == 1) ? bk : bv;
    const __half* W16 = g_w + (size_t)z * Dd * Dd;

    biasS[tid] = bias[n0 + tid];

    float acc[4][8][4];
#pragma unroll
    for (int i = 0; i < 4; i++)
#pragma unroll
        for (int j = 0; j < 8; j++)
#pragma unroll
            for (int k = 0; k < 4; k++) acc[i][j][k] = 0.f;

    auto issue = [&](int kt, int st) {
        const int kc = kt * 32;
#pragma unroll
        for (int i = 0; i < 12; i++) {
            int idx = tid + i * 128;
            int tile = idx >> 9, w = idx & 511;
            if (tile == 1 && !doLo) continue;      // xl unused for K/V
            int r = w >> 2, seg = (w & 3) * 16;
            uint32_t dst = sb + st * BUF3_B + tile * TILE_B + r * 80 + seg;
            const char* src;
            if (tile == 0)      src = (const char*)(g_xh + (size_t)(m0 + r) * Dd + kc) + seg;
            else if (tile == 1) src = (const char*)(g_xl + (size_t)(m0 + r) * Dd + kc) + seg;
            else                src = (const char*)(W16 + (size_t)(n0 + r) * Dd + kc) + seg;
            cp_async16(dst, src);
        }
        cp_commit();
    };

    issue(0, 0);
    const int arow0 = wm * 64 + (lid & 15);
    const int abyte0 = (lid >> 4) * 16;
    const int brow0 = wn * 64 + ((lid >> 4) << 3) + (lid & 7);
    const int bbyte0 = ((lid >> 3) & 1) * 16;

    int buf = 0;
    for (int kt = 0; kt < 32; kt++) {
        cp_wait<0>();
        __syncthreads();               // data ready + prior reads of buf^1 done
        if (kt + 1 < 32) issue(kt + 1, buf ^ 1);

        const uint32_t tAh = sb + buf * BUF3_B;
        const uint32_t tAl = tAh + TILE_B;
        const uint32_t tBh = tAh + 2 * TILE_B;

#pragma unroll
        for (int kk = 0; kk < 2; kk++) {
            const int ab = kk * 32 + abyte0;
            const int bb = kk * 32 + bbyte0;
            uint32_t aH[4][4], bH[8][2];
#pragma unroll
            for (int mf = 0; mf < 4; mf++)
                ldsm_x4(aH[mf], tAh + (arow0 + mf * 16) * 80 + ab);
#pragma unroll
            for (int nf2 = 0; nf2 < 4; nf2++) {
                uint32_t r4[4];
                ldsm_x4(r4, tBh + (brow0 + nf2 * 16) * 80 + bb);
                bH[nf2 * 2][0] = r4[0]; bH[nf2 * 2][1] = r4[1];
                bH[nf2 * 2 + 1][0] = r4[2]; bH[nf2 * 2 + 1][1] = r4[3];
            }
#pragma unroll
            for (int mf = 0; mf < 4; mf++)
#pragma unroll
                for (int nf = 0; nf < 8; nf++)
                    mma16816(acc[mf][nf], aH[mf], bH[nf]);
            if (doLo) {
                uint32_t aL[4][4];
#pragma unroll
                for (int mf = 0; mf < 4; mf++)
                    ldsm_x4(aL[mf], tAl + (arow0 + mf * 16) * 80 + ab);
#pragma unroll
                for (int mf = 0; mf < 4; mf++)
#pragma unroll
                    for (int nf = 0; nf < 8; nf++)
                        mma16816(acc[mf][nf], aL[mf], bH[nf]);
            }
        }
        buf ^= 1;
    }

#pragma unroll
    for (int mf = 0; mf < 4; mf++) {
#pragma unroll
        for (int nf = 0; nf < 8; nf++) {
            int nl = wn * 64 + nf * 8 + (lid & 3) * 2;
            int n = n0 + nl;
            float b0 = biasS[nl], b1 = biasS[nl + 1];
#pragma unroll
            for (int half = 0; half < 2; half++) {
                int m = m0 + wm * 64 + mf * 16 + (lid >> 2) + half * 8;
                float v0 = acc[mf][nf][half * 2 + 0] + b0;
                float v1 = acc[mf][nf][half * 2 + 1] + b1;
                int b = m >> 11, s = m & (Ss - 1);
                int hh = n >> 6, d = n & (HD - 1);
                size_t o = (((size_t)(b * Hh + hh)) * Ss + s) * HD + d;
                if (z == 0) {          // Q: pre-scale + split hi/lo
                    v0 *= QSCALE; v1 *= QSCALE;
                    __half h0, l0, h1, l1;
                    split2h(v0, h0, l0); split2h(v1, h1, l1);
                    *(__half2*)(g_qh + o) = __half2(h0, h1);
                    *(__half2*)(g_ql + o) = __half2(l0, l1);
                } else {               // K/V: single fp16
                    __half* dst = (z == 1) ? g_kh : g_vh;
                    *(__half2*)(dst + o) = __floats2half2_rn(v0, v1);
                }
            }
        }
    }
}

// Output GEMM: out = c16 @ Wo16^T + bo, fp32 result (1 term).
__global__ __launch_bounds__(128)
void gemm_out(const float* __restrict__ bias, float* __restrict__ Cout)
{
    extern __shared__ char smem[];
    const uint32_t sb = smem_to_u32(smem);
    float* biasS = (float*)(smem + 2 * BUF2_B);

    const int tid = threadIdx.x, wid = tid >> 5, lid = tid & 31;
    const int wm = wid >> 1, wn = wid & 1;
    const int m0 = blockIdx.y * 128, n0 = blockIdx.x * 128;

    const __half* W16 = g_w + (size_t)3 * Dd * Dd;

    biasS[tid] = bias[n0 + tid];

    float acc[4][8][4];
#pragma unroll
    for (int i = 0; i < 4; i++)
#pragma unroll
        for (int j = 0; j < 8; j++)
#pragma unroll
            for (int k = 0; k < 4; k++) acc[i][j][k] = 0.f;

    auto issue = [&](int kt, int st) {
        const int kc = kt * 32;
#pragma unroll
        for (int i = 0; i < 8; i++) {
            int idx = tid + i * 128;
            int tile = idx >> 9, w = idx & 511;
            int r = w >> 2, seg = (w & 3) * 16;
            uint32_t dst = sb + st * BUF2_B + tile * TILE_B + r * 80 + seg;
            const char* src;
            if (tile == 0) src = (const char*)(g_c16 + (size_t)(m0 + r) * Dd + kc) + seg;
            else           src = (const char*)(W16 + (size_t)(n0 + r) * Dd + kc) + seg;
            cp_async16(dst, src);
        }
        cp_commit();
    };

    issue(0, 0);
    const int arow0 = wm * 64 + (lid & 15);
    const int abyte0 = (lid >> 4) * 16;
    const int brow0 = wn * 64 + ((lid >> 4) << 3) + (lid & 7);
    const int bbyte0 = ((lid >> 3) & 1) * 16;

    int buf = 0;
    for (int kt = 0; kt < 32; kt++) {
        cp_wait<0>();
        __syncthreads();
        if (kt + 1 < 32) issue(kt + 1, buf ^ 1);

        const uint32_t tA = sb + buf * BUF2_B;
        const uint32_t tB = tA + TILE_B;

#pragma unroll
        for (int kk = 0; kk < 2; kk++) {
            const int ab = kk * 32 + abyte0;
            const int bb = kk * 32 + bbyte0;
            uint32_t aH[4][4], bH[8][2];
#pragma unroll
            for (int mf = 0; mf < 4; mf++)
                ldsm_x4(aH[mf], tA + (arow0 + mf * 16) * 80 + ab);
#pragma unroll
            for (int nf2 = 0; nf2 < 4; nf2++) {
                uint32_t r4[4];
                ldsm_x4(r4, tB + (brow0 + nf2 * 16) * 80 + bb);
                bH[nf2 * 2][0] = r4[0]; bH[nf2 * 2][1] = r4[1];
                bH[nf2 * 2 + 1][0] = r4[2]; bH[nf2 * 2 + 1][1] = r4[3];
            }
#pragma unroll
            for (int mf = 0; mf < 4; mf++)
#pragma unroll
                for (int nf = 0; nf < 8; nf++)
                    mma16816(acc[mf][nf], aH[mf], bH[nf]);
        }
        buf ^= 1;
    }

#pragma unroll
    for (int mf = 0; mf < 4; mf++) {
#pragma unroll
        for (int nf = 0; nf < 8; nf++) {
            int nl = wn * 64 + nf * 8 + (lid & 3) * 2;
            int n = n0 + nl;
            float b0 = biasS[nl], b1 = biasS[nl + 1];
#pragma unroll
            for (int half = 0; half < 2; half++) {
                int m = m0 + wm * 64 + mf * 16 + (lid >> 2) + half * 8;
                *(float2*)(Cout + (size_t)m * Dd + n) =
                    make_float2(acc[mf][nf][half * 2 + 0] + b0,
                                acc[mf][nf][half * 2 + 1] + b1);
            }
        }
    }
}

// ---------------------------------------------------------------------------
// Tensor-core causal flash attention. S = (qh+ql)@k16 (2 terms);
// O += P16@v16 (1 term). KV ring is 3-stage (two tile loads in flight).
// q-tile 128 rows, 256 threads / 8 warps; paired (pr, 15-pr) -> uniform work.
// ---------------------------------------------------------------------------
#define AT_STRIDE 144
#define QT_B     (128 * AT_STRIDE)           // 18432
#define KV_TILE  (64 * AT_STRIDE)            // 9216
#define KV0      (2 * QT_B)                  // 36864
#define KV_STAGE (2 * KV_TILE)               // 18432 (k + v)
#define ATTN_SMEM (KV0 + 3 * KV_STAGE)       // 92160

__global__ __launch_bounds__(256, 2)
void attn_mma()
{
    extern __shared__ char smem[];
    const uint32_t sb = smem_to_u32(smem);
    const int pr = blockIdx.x;                 // pair index 0..7
    const int bh = blockIdx.y;
    const int b = bh >> 4, h = bh & 15;
    const int tid = threadIdx.x, wid = tid >> 5, lid = tid & 31;

    const __half* kbase = g_kh + (size_t)bh * Ss * HD;
    const __half* vbase = g_vh + (size_t)bh * Ss * HD;

    auto issue = [&](int kt, int st) {
#pragma unroll
        for (int i = 0; i < 4; i++) {
            int idx = tid + i * 256;
            int t = idx >> 9, w = idx & 511;
            int r = w >> 3, c = w & 7;
            const __half* src = (t ? vbase : kbase) + (size_t)(kt * 64 + r) * HD + c * 8;
            cp_async16(sb + KV0 + st * KV_STAGE + t * KV_TILE + r * AT_STRIDE + c * 16, src);
        }
        cp_commit();
    };

    const uint32_t qrowb = (wid * 16 + (lid & 15)) * AT_STRIDE + (lid >> 4) * 16;
    const uint32_t krowb = (((lid >> 4) << 3) + (lid & 7)) * AT_STRIDE + ((lid >> 3) & 1) * 16;
    const uint32_t vrowb = (lid & 15) * AT_STRIDE + ((lid >> 4) & 1) * 16;

    for (int half_t = 0; half_t < 2; half_t++) {
        const int qt = half_t ? (15 - pr) : pr;       // q-tile of 128 rows
        const __half* QH = g_qh + ((size_t)bh * Ss + qt * 128) * HD;
        const __half* QL = g_ql + ((size_t)bh * Ss + qt * 128) * HD;
        const int nk = 2 * qt + 2;

        // Q tile (qh, ql): 128 rows x 128B each (own commit group)
#pragma unroll
        for (int i = 0; i < 8; i++) {
            int idx = tid + i * 256;
            int s = idx >> 10, w = idx & 1023;
            int r = w >> 3, c = w & 7;
            cp_async16(sb + s * QT_B + r * AT_STRIDE + c * 16,
                       (s ? QL : QH) + (size_t)r * HD + c * 8);
        }
        cp_commit();
        issue(0, 0);
        if (nk > 1) issue(1, 1);

        float acc[8][4];
#pragma unroll
        for (int i = 0; i < 8; i++)
#pragma unroll
            for (int j = 0; j < 4; j++) acc[i][j] = 0.f;
        float mrow[2] = { -1e30f, -1e30f }, lrow[2] = { 0.f, 0.f };

        int stage = 0;
        for (int kt = 0; kt < nk; kt++) {
            if (kt + 1 < nk) cp_wait<1>(); else cp_wait<0>();
            __syncthreads();          // chunk kt (and Q) ready + old stage reads done
            if (kt + 2 < nk) issue(kt + 2, (kt + 2) % 3);

            const uint32_t kbt = sb + KV0 + stage * KV_STAGE;
            const uint32_t vbt = kbt + KV_TILE;

            // ---- S = (qh + ql) @ k16^T  (2 MMA terms) ----
            float sf[8][4];
#pragma unroll
            for (int i = 0; i < 8; i++)
#pragma unroll
                for (int j = 0; j < 4; j++) sf[i][j] = 0.f;

#pragma unroll
            for (int kk = 0; kk < 4; kk++) {
                uint32_t aH[4], aL[4];
                ldsm_x4(aH, sb + qrowb + kk * 32);
                ldsm_x4(aL, sb + QT_B + qrowb + kk * 32);
#pragma unroll
                for (int nf2 = 0; nf2 < 4; nf2++) {
                    uint32_t rH[4];
                    ldsm_x4(rH, kbt + nf2 * 16 * AT_STRIDE + krowb + kk * 32);
                    mma16816(sf[nf2 * 2],     aH, rH);
                    mma16816(sf[nf2 * 2 + 1], aH, rH + 2);
                    mma16816(sf[nf2 * 2],     aL, rH);
                    mma16816(sf[nf2 * 2 + 1], aL, rH + 2);
                }
            }

            if (kt >= 2 * qt) {     // diagonal region: causal mask
                int r0 = wid * 16 + (lid >> 2);
                int coff = kt * 64 - qt * 128;
#pragma unroll
                for (int nf = 0; nf < 8; nf++) {
                    int c0 = coff + nf * 8 + (lid & 3) * 2;
                    if (c0     > r0)     sf[nf][0] = -1e30f;
                    if (c0 + 1 > r0)     sf[nf][1] = -1e30f;
                    if (c0     > r0 + 8) sf[nf][2] = -1e30f;
                    if (c0 + 1 > r0 + 8) sf[nf][3] = -1e30f;
                }
            }

            // ---- online softmax in exp2 domain ----
#pragma unroll
            for (int hf = 0; hf < 2; hf++) {
                float mx = -1e30f;
#pragma unroll
                for (int nf = 0; nf < 8; nf++)
                    mx = fmaxf(mx, fmaxf(sf[nf][hf * 2], sf[nf][hf * 2 + 1]));
                mx = fmaxf(mx, __shfl_xor_sync(0xffffffffu, mx, 1));
                mx = fmaxf(mx, __shfl_xor_sync(0xffffffffu, mx, 2));
                float mnew = fmaxf(mrow[hf], mx);
                float alpha = ex2(mrow[hf] - mnew);
                mrow[hf] = mnew;
                float sum = 0.f;
#pragma unroll
                for (int nf = 0; nf < 8; nf++) {
                    sf[nf][hf * 2]     = ex2(sf[nf][hf * 2] - mnew);
                    sf[nf][hf * 2 + 1] = ex2(sf[nf][hf * 2 + 1] - mnew);
                    sum += sf[nf][hf * 2] + sf[nf][hf * 2 + 1];
                }
                sum += __shfl_xor_sync(0xffffffffu, sum, 1);
                sum += __shfl_xor_sync(0xffffffffu, sum, 2);
                lrow[hf] = lrow[hf] * alpha + sum;
#pragma unroll
                for (int nf = 0; nf < 8; nf++) {
                    acc[nf][hf * 2]     *= alpha;
                    acc[nf][hf * 2 + 1] *= alpha;
                }
            }

            // ---- O += P16 @ v16  (1 MMA term) ----
#pragma unroll
            for (int kk2 = 0; kk2 < 4; kk2++) {
                uint32_t aPh[4];
#pragma unroll
                for (int q = 0; q < 2; q++) {
                    const float* c = sf[kk2 * 2 + q];
                    aPh[q * 2]     = packh(c[0], c[1]);
                    aPh[q * 2 + 1] = packh(c[2], c[3]);
                }
#pragma unroll
                for (int nf2 = 0; nf2 < 4; nf2++) {
                    uint32_t vH[4];
                    ldsm_x4_t(vH, vbt + (kk2 * 16) * AT_STRIDE + vrowb + nf2 * 32);
                    mma16816(acc[nf2 * 2],     aPh, vH);
                    mma16816(acc[nf2 * 2 + 1], aPh, vH + 2);
                }
            }
            stage = (stage == 2) ? 0 : stage + 1;
        }

        // ---- epilogue: ctx -> single fp16 (B,S,D) ----
        float inv0 = 1.f / lrow[0], inv1 = 1.f / lrow[1];
        int r0 = qt * 128 + wid * 16 + (lid >> 2);
#pragma unroll
        for (int nf = 0; nf < 8; nf++) {
            int d0 = h * HD + nf * 8 + (lid & 3) * 2;
            size_t o0 = ((size_t)b * Ss + r0) * Dd + d0;
            size_t o1 = ((size_t)b * Ss + r0 + 8) * Dd + d0;
            *(__half2*)(g_c16 + o0) =
                __floats2half2_rn(acc[nf][0] * inv0, acc[nf][1] * inv0);
            *(__half2*)(g_c16 + o1) =
                __floats2half2_rn(acc[nf][2] * inv1, acc[nf][3] * inv1);
        }
        __syncthreads();    // all smem reads done before next half's loads
    }
}

// ---------------------------------------------------------------------------
extern "C" void kernel_launch(void* const* d_in, const int* in_sizes, int n_in,
                              void* d_out, int out_size)
{
    const float* x  = (const float*)d_in[0];
    const float* Wq = (const float*)d_in[1];
    const float* bq = (const float*)d_in[2];
    const float* Wk = (const float*)d_in[3];
    const float* bk = (const float*)d_in[4];
    const float* Wv = (const float*)d_in[5];
    const float* bv = (const float*)d_in[6];
    const float* Wo = (const float*)d_in[7];
    const float* bo = (const float*)d_in[8];
    float* out = (float*)d_out;

    cudaFuncSetAttribute(gemm_qkv, cudaFuncAttributeMaxDynamicSharedMemorySize, QKV_SMEM);
    cudaFuncSetAttribute(gemm_out, cudaFuncAttributeMaxDynamicSharedMemorySize, OUT_SMEM);
    cudaFuncSetAttribute(attn_mma, cudaFuncAttributeMaxDynamicSharedMemorySize, ATTN_SMEM);

    split_all<<<(Mtot * Dd + 4 * Dd * Dd) / 1024, 256>>>(x, Wq, Wk, Wv, Wo);

    gemm_qkv<<<dim3(Dd / 128, Mtot / 128, 3), 128, QKV_SMEM>>>(bq, bk, bv);

    attn_mma<<<dim3(8, Bb * Hh), 256, ATTN_SMEM>>>();

    gemm_out<<<dim3(Dd / 128, Mtot / 128), 128, OUT_SMEM>>>(bo, out);
}